// round 6
// baseline (speedup 1.0000x reference)
#include <cuda_runtime.h>
#include <cstdint>

#define BB 2
#define SS 2048
#define HH 16
#define DK 64
#define DM 1024
#define ROWS (BB*SS)          // 4096

// ---------------- scratch -----------------------------------------------------
// packed Q/K: float4 per (bh, s, k8, tig): {hi(k8*8+tig), hi(+4), lo(tig), lo(+4)}
__device__ float4 g_Qpk[(size_t)BB*HH*SS*32];
__device__ float4 g_Kpk[(size_t)BB*HH*SS*32];
__device__ float g_Vp[(size_t)ROWS*DK];
__device__ float g_escore[(size_t)BB*HH*SS*SS];   // exp(s/8) (536 MB)
__device__ float g_lpart[(size_t)BB*HH*16*SS];    // per (bh, ktile, q) partial sumexp
__device__ float g_rinv[(size_t)BB*HH*SS];        // 1 / l
__device__ float g_ao[(size_t)ROWS*DK];           // attn_output
__device__ float g_avpart[(size_t)8*BB*SS*DK];    // split-K partials for avg@V

// ---------------- helpers -------------------------------------------------------
__device__ __forceinline__ float fast_exp(float x) {
    x = fmaxf(x, -87.0f);
    float t = fmaf(x, 1.4426950408889634f, 12582912.0f);
    float n = t - 12582912.0f;
    float f = fmaf(x, 1.4426950408889634f, -n);
    float p = 1.5403530394e-4f;
    p = fmaf(p, f, 1.3333558146e-3f);
    p = fmaf(p, f, 9.6178371906e-3f);
    p = fmaf(p, f, 5.5502813330e-2f);
    p = fmaf(p, f, 2.4022650695e-1f);
    p = fmaf(p, f, 6.9314718056e-1f);
    p = fmaf(p, f, 1.0f);
    return p * __int_as_float(((int)n + 127) << 23);
}

__device__ __forceinline__ unsigned long long pack2(float lo, float hi) {
    unsigned long long r;
    asm("mov.b64 %0, {%1, %2};" : "=l"(r) : "f"(lo), "f"(hi));
    return r;
}
__device__ __forceinline__ void unpack2(unsigned long long v, float& lo, float& hi) {
    asm("mov.b64 {%0, %1}, %2;" : "=f"(lo), "=f"(hi) : "l"(v));
}
__device__ __forceinline__ unsigned long long fma2(unsigned long long a,
                                                   unsigned long long b,
                                                   unsigned long long c) {
    unsigned long long d;
    asm("fma.rn.f32x2 %0, %1, %2, %3;" : "=l"(d) : "l"(a), "l"(b), "l"(c));
    return d;
}

__device__ __forceinline__ void mma8(float* c, const uint32_t* a, const uint32_t* b) {
    asm volatile("mma.sync.aligned.m16n8k8.row.col.f32.tf32.tf32.f32 "
        "{%0,%1,%2,%3}, {%4,%5,%6,%7}, {%8,%9}, {%0,%1,%2,%3};"
        : "+f"(c[0]), "+f"(c[1]), "+f"(c[2]), "+f"(c[3])
        : "r"(a[0]), "r"(a[1]), "r"(a[2]), "r"(a[3]), "r"(b[0]), "r"(b[1]));
}

__device__ __forceinline__ void split_tf32(float x, float& hi, float& lo) {
    uint32_t h, l;
    asm("cvt.rna.tf32.f32 %0, %1;" : "=r"(h) : "f"(x));
    float hf = __uint_as_float(h);
    asm("cvt.rna.tf32.f32 %0, %1;" : "=r"(l) : "f"(x - hf));
    hi = hf; lo = __uint_as_float(l);
}

// smem row stride for packed tiles: 8 k8 * 16 floats + 8 pad = 136 words
#define PKW 136

// ---------------- pass 1: MMA scores -> store exp + per-row sumexp ---------------
__global__ __launch_bounds__(512, 1)
void mma_pass1(const float4* __restrict__ Qpk, const float4* __restrict__ Kpk,
               float* __restrict__ Esc, float* __restrict__ lpart)
{
    extern __shared__ float smf[];
    float* Qs = smf;                       // [128][136]
    float* Ks = Qs + 128 * PKW;            // [128][136]
    float* rowsum = Ks + 128 * PKW;        // [128][4]

    const int tid = threadIdx.x;
    const int kt = blockIdx.x, qt = blockIdx.y, bh = blockIdx.z;
    const long long qbase = ((long long)bh * SS + qt * 128) * 32;   // float4 units
    const long long kbase = ((long long)bh * SS + kt * 128) * 32;

#pragma unroll
    for (int i = 0; i < 8; i++) {
        int idx = tid + i * 512;           // 0..4095
        int r = idx >> 5, f = idx & 31;
        *(float4*)&Qs[r * PKW + f * 4] = Qpk[qbase + r * 32 + f];
        *(float4*)&Ks[r * PKW + f * 4] = Kpk[kbase + r * 32 + f];
    }
    __syncthreads();

    const int wid = tid >> 5, lane = tid & 31;
    const int wm = wid >> 2, wn = wid & 3;
    const int gid = lane >> 2, tig = lane & 3;

    float acc[2][4][4];
#pragma unroll
    for (int mt = 0; mt < 2; mt++)
#pragma unroll
        for (int nt = 0; nt < 4; nt++)
#pragma unroll
            for (int c = 0; c < 4; c++) acc[mt][nt][c] = 0.f;

#pragma unroll
    for (int k8 = 0; k8 < 8; k8++) {
        const int fo = (k8 * 4 + tig) * 4;
        uint32_t bhf[4][2], blf[4][2];
#pragma unroll
        for (int nt = 0; nt < 4; nt++) {
            float4 kf = *(const float4*)&Ks[(wn * 32 + nt * 8 + gid) * PKW + fo];
            bhf[nt][0] = __float_as_uint(kf.x); bhf[nt][1] = __float_as_uint(kf.y);
            blf[nt][0] = __float_as_uint(kf.z); blf[nt][1] = __float_as_uint(kf.w);
        }
#pragma unroll
        for (int mt = 0; mt < 2; mt++) {
            float4 q0 = *(const float4*)&Qs[(wm * 32 + mt * 16 + gid) * PKW + fo];
            float4 q1 = *(const float4*)&Qs[(wm * 32 + mt * 16 + gid + 8) * PKW + fo];
            uint32_t ah[4], al[4];
            ah[0] = __float_as_uint(q0.x); ah[1] = __float_as_uint(q1.x);
            ah[2] = __float_as_uint(q0.y); ah[3] = __float_as_uint(q1.y);
            al[0] = __float_as_uint(q0.z); al[1] = __float_as_uint(q1.z);
            al[2] = __float_as_uint(q0.w); al[3] = __float_as_uint(q1.w);
#pragma unroll
            for (int nt = 0; nt < 4; nt++) {
                mma8(acc[mt][nt], ah, bhf[nt]);   // hi*hi
                mma8(acc[mt][nt], al, bhf[nt]);   // lo*hi
                mma8(acc[mt][nt], ah, blf[nt]);   // hi*lo
            }
        }
    }

    // scale -> exp -> store exp + per-row partial sumexp
    float* Cp = Esc + ((long long)bh * SS + qt * 128) * SS + kt * 128;
    float p[2][2];
    p[0][0] = p[0][1] = p[1][0] = p[1][1] = 0.f;
#pragma unroll
    for (int mt = 0; mt < 2; mt++)
#pragma unroll
        for (int nt = 0; nt < 4; nt++) {
            float e0 = fast_exp(acc[mt][nt][0] * 0.125f);
            float e1 = fast_exp(acc[mt][nt][1] * 0.125f);
            float e2 = fast_exp(acc[mt][nt][2] * 0.125f);
            float e3 = fast_exp(acc[mt][nt][3] * 0.125f);
            int r0 = wm * 32 + mt * 16 + gid;
            int col = wn * 32 + nt * 8 + tig * 2;
            float2 v0 = {e0, e1}, v1 = {e2, e3};
            *(float2*)&Cp[(long long)r0 * SS + col] = v0;
            *(float2*)&Cp[(long long)(r0 + 8) * SS + col] = v1;
            p[mt][0] += e0 + e1;
            p[mt][1] += e2 + e3;
        }
#pragma unroll
    for (int o = 1; o <= 2; o <<= 1)
#pragma unroll
        for (int mt = 0; mt < 2; mt++) {
            p[mt][0] += __shfl_xor_sync(0xffffffffu, p[mt][0], o);
            p[mt][1] += __shfl_xor_sync(0xffffffffu, p[mt][1], o);
        }
    if (tig == 0) {
#pragma unroll
        for (int mt = 0; mt < 2; mt++)
#pragma unroll
            for (int j = 0; j < 2; j++) {
                int r = wm * 32 + mt * 16 + j * 8 + gid;
                rowsum[r * 4 + wn] = p[mt][j];
            }
    }
    __syncthreads();
    if (tid < 128) {
        float l = rowsum[tid * 4] + rowsum[tid * 4 + 1]
                + rowsum[tid * 4 + 2] + rowsum[tid * 4 + 3];
        lpart[(long long)(bh * 16 + kt) * SS + qt * 128 + tid] = l;
    }
}

// ---------------- combine: rinv = 1 / sum of partials ----------------------------
__global__ __launch_bounds__(256)
void combine_kernel(const float* __restrict__ lpart, float* __restrict__ rinv)
{
    int rowg = blockIdx.x * 256 + threadIdx.x;     // bh*2048 + q
    int bh = rowg >> 11, q = rowg & (SS - 1);
    float l = 0.f;
#pragma unroll
    for (int t = 0; t < 16; t++)
        l += lpart[(long long)(bh * 16 + t) * SS + q];
    rinv[rowg] = 1.0f / l;
}

// ---------------- head-averaged attention (pure streaming MAC) -------------------
__global__ __launch_bounds__(256)
void avg_kernel(const float* __restrict__ Esc, const float* __restrict__ rinv,
                float* __restrict__ avg)
{
    const int q = blockIdx.x;
    const int b = blockIdx.y;
    const int tid = threadIdx.x;

    __shared__ float rw[HH];
    if (tid < HH) rw[tid] = rinv[((long long)(b * HH + tid) << 11) + q] * (1.0f / HH);
    __syncthreads();

    const float* base = Esc + ((long long)(b * HH) * SS + q) * SS;
    float* dst = avg + ((long long)b * SS + q) * SS;
    for (int k0 = tid * 4; k0 < SS; k0 += 1024) {
        float ax = 0.f, ay = 0.f, az = 0.f, aw = 0.f;
#pragma unroll
        for (int h = 0; h < HH; h++) {
            const float4 s = *(const float4*)(base + (long long)h * SS * SS + k0);
            float r = rw[h];
            ax = fmaf(s.x, r, ax); ay = fmaf(s.y, r, ay);
            az = fmaf(s.z, r, az); aw = fmaf(s.w, r, aw);
        }
        float4 o = {ax, ay, az, aw};
        *(float4*)&dst[k0] = o;
    }
}

// ---------------- projection GEMM (SIMT f32x2) ------------------------------------
#define PADW 132

// MODE: 0 = plain [M,N] output + bias; 1 = packed head-layout hi/lo float4 output
template<int MODE>
__global__ __launch_bounds__(256, 2)
void proj_gemm(const float* __restrict__ A, const float* __restrict__ B,
               const float* __restrict__ bias, float* __restrict__ C,
               float4* __restrict__ Cpk,
               int N, int K, int lda, int ldb, int ldc)
{
    __shared__ __align__(16) float As[16 * PADW];
    __shared__ __align__(16) float Bs[16 * PADW];

    const int rowbase = blockIdx.y * 128;
    const int colbase = blockIdx.x * 128;
    const int tid = threadIdx.x;
    const int tx = tid & 15, ty = tid >> 4;
    const int row0 = ty * 8, col0 = tx * 8;

    float regA[8], regB[8];
    unsigned long long acc[8][4];
#pragma unroll
    for (int i = 0; i < 8; i++)
#pragma unroll
        for (int j = 0; j < 4; j++) acc[i][j] = 0ull;

#pragma unroll
    for (int i = 0; i < 8; i++) {
        int idx = tid + i * 256; int r = idx >> 4, kk = idx & 15;
        regA[i] = A[(long long)(rowbase + r) * lda + kk];
    }
#pragma unroll
    for (int i = 0; i < 8; i++) {
        int idx = tid + i * 256; int kk = idx >> 7, c = idx & 127;
        int col = colbase + c;
        regB[i] = (col < N) ? B[(long long)kk * ldb + col] : 0.f;
    }
#pragma unroll
    for (int i = 0; i < 8; i++) {
        int idx = tid + i * 256; int r = idx >> 4, kk = idx & 15;
        As[kk * PADW + r] = regA[i];
    }
#pragma unroll
    for (int i = 0; i < 8; i++) {
        int idx = tid + i * 256; int kk = idx >> 7, c = idx & 127;
        Bs[kk * PADW + c] = regB[i];
    }
    __syncthreads();

    for (int k0 = 16; ; k0 += 16) {
        const bool more = (k0 < K);
        if (more) {
#pragma unroll
            for (int i = 0; i < 8; i++) {
                int idx = tid + i * 256; int r = idx >> 4, kk = idx & 15;
                regA[i] = A[(long long)(rowbase + r) * lda + k0 + kk];
            }
#pragma unroll
            for (int i = 0; i < 8; i++) {
                int idx = tid + i * 256; int kk = idx >> 7, c = idx & 127;
                int col = colbase + c;
                regB[i] = (col < N) ? B[(long long)(k0 + kk) * ldb + col] : 0.f;
            }
        }
#pragma unroll
        for (int kk = 0; kk < 16; kk++) {
            float4 a0 = *(const float4*)&As[kk * PADW + row0];
            float4 a1 = *(const float4*)&As[kk * PADW + row0 + 4];
            float4 b0 = *(const float4*)&Bs[kk * PADW + col0];
            float4 b1 = *(const float4*)&Bs[kk * PADW + col0 + 4];
            float a[8] = {a0.x, a0.y, a0.z, a0.w, a1.x, a1.y, a1.z, a1.w};
            unsigned long long bp[4];
            bp[0] = pack2(b0.x, b0.y); bp[1] = pack2(b0.z, b0.w);
            bp[2] = pack2(b1.x, b1.y); bp[3] = pack2(b1.z, b1.w);
#pragma unroll
            for (int i = 0; i < 8; i++) {
                unsigned long long ap = pack2(a[i], a[i]);
#pragma unroll
                for (int j = 0; j < 4; j++) acc[i][j] = fma2(ap, bp[j], acc[i][j]);
            }
        }
        if (!more) break;
        __syncthreads();
#pragma unroll
        for (int i = 0; i < 8; i++) {
            int idx = tid + i * 256; int r = idx >> 4, kk = idx & 15;
            As[kk * PADW + r] = regA[i];
        }
#pragma unroll
        for (int i = 0; i < 8; i++) {
            int idx = tid + i * 256; int kk = idx >> 7, c = idx & 127;
            Bs[kk * PADW + c] = regB[i];
        }
        __syncthreads();
    }

#pragma unroll
    for (int i = 0; i < 8; i++) {
        int gr = rowbase + row0 + i;
        if (MODE == 1) {
            // cols col0..col0+7 = exactly one k8 group of one head
            int gcol = colbase + col0;
            int b = gr >> 11, s = gr & (SS - 1);
            int h = gcol >> 6, k8 = (gcol & 63) >> 3;
            float v[8], hv[8], lv[8];
            unpack2(acc[i][0], v[0], v[1]); unpack2(acc[i][1], v[2], v[3]);
            unpack2(acc[i][2], v[4], v[5]); unpack2(acc[i][3], v[6], v[7]);
#pragma unroll
            for (int j = 0; j < 8; j++) {
                v[j] += bias[gcol + j];
                split_tf32(v[j], hv[j], lv[j]);
            }
            long long base4 = (((long long)(b * HH + h) * SS + s) * 8 + k8) * 4;
#pragma unroll
            for (int tg = 0; tg < 4; tg++) {
                float4 o = {hv[tg], hv[tg + 4], lv[tg], lv[tg + 4]};
                Cpk[base4 + tg] = o;
            }
        } else {
#pragma unroll
            for (int j2 = 0; j2 < 4; j2 += 2) {
                int col = colbase + col0 + j2 * 2;
                if (col < N) {
                    float4 v;
                    unpack2(acc[i][j2],     v.x, v.y);
                    unpack2(acc[i][j2 + 1], v.z, v.w);
                    const float4 bb = *(const float4*)&bias[col];
                    v.x += bb.x; v.y += bb.y; v.z += bb.z; v.w += bb.w;
                    *(float4*)&C[(long long)gr * ldc + col] = v;
                }
            }
        }
    }
}

// ---------------- avg @ V (split-K partials) ---------------------------------------
__global__ __launch_bounds__(256)
void av_gemm(const float* __restrict__ avg, const float* __restrict__ V,
             float* __restrict__ part)
{
    __shared__ float As[16 * PADW];
    __shared__ float Bs[16 * 68];
    const int b = blockIdx.z;
    const int rowbase = blockIdx.y * 128;
    const int k0base = blockIdx.x * 256;
    const float* Ap = avg + ((long long)b * SS + rowbase) * SS;
    const float* Vp = V + (long long)b * SS * DK;
    const int tid = threadIdx.x;
    const int tx = tid & 15, ty = tid >> 4;

    float acc[8][4];
#pragma unroll
    for (int i = 0; i < 8; i++)
#pragma unroll
        for (int j = 0; j < 4; j++) acc[i][j] = 0.f;

    for (int kc = 0; kc < 256; kc += 16) {
        const int k0 = k0base + kc;
#pragma unroll
        for (int i = 0; i < 8; i++) {
            int idx = tid + i * 256; int r = idx >> 4, kk = idx & 15;
            As[kk * PADW + r] = Ap[(long long)r * SS + k0 + kk];
        }
#pragma unroll
        for (int i = 0; i < 4; i++) {
            int idx = tid + i * 256; int kk = idx >> 6, cc = idx & 63;
            Bs[kk * 68 + cc] = Vp[(long long)(k0 + kk) * DK + cc];
        }
        __syncthreads();
#pragma unroll
        for (int kk = 0; kk < 16; kk++) {
            float a[8];
#pragma unroll
            for (int i = 0; i < 8; i++) a[i] = As[kk * PADW + ty * 8 + i];
            float4 bv = *(const float4*)&Bs[kk * 68 + tx * 4];
#pragma unroll
            for (int i = 0; i < 8; i++) {
                acc[i][0] = fmaf(a[i], bv.x, acc[i][0]);
                acc[i][1] = fmaf(a[i], bv.y, acc[i][1]);
                acc[i][2] = fmaf(a[i], bv.z, acc[i][2]);
                acc[i][3] = fmaf(a[i], bv.w, acc[i][3]);
            }
        }
        __syncthreads();
    }
    float* P = part + ((long long)(blockIdx.x * BB + b) * SS + rowbase) * DK;
#pragma unroll
    for (int i = 0; i < 8; i++) {
        float4 v = {acc[i][0], acc[i][1], acc[i][2], acc[i][3]};
        *(float4*)&P[(long long)(ty * 8 + i) * DK + tx * 4] = v;
    }
}

__global__ __launch_bounds__(256)
void av_reduce(const float* __restrict__ part, float* __restrict__ Ao)
{
    int i = blockIdx.x * 256 + threadIdx.x;
    float s = 0.f;
#pragma unroll
    for (int t = 0; t < 8; t++) s += part[(long long)t * (BB * SS * DK) + i];
    Ao[i] = s;
}

// ---------------- launch -------------------------------------------------------------
extern "C" void kernel_launch(void* const* d_in, const int* in_sizes, int n_in,
                              void* d_out, int out_size)
{
    const float* query = (const float*)d_in[0];
    const float* key_  = (const float*)d_in[1];
    const float* value = (const float*)d_in[2];
    const float* Wq    = (const float*)d_in[3];
    const float* bq    = (const float*)d_in[4];
    const float* Wk    = (const float*)d_in[5];
    const float* bk    = (const float*)d_in[6];
    const float* Wv    = (const float*)d_in[7];
    const float* bv    = (const float*)d_in[8];
    const float* Wo    = (const float*)d_in[9];
    const float* bo    = (const float*)d_in[10];

    float* out_main = (float*)d_out;                 // [B,S,DM]
    float* out_avg  = out_main + (size_t)ROWS * DM;  // [B,S,S]

    float4 *Qpk, *Kpk;
    float *Vp, *Esc, *Lp, *Rv, *Ao, *Av;
    cudaGetSymbolAddress((void**)&Qpk, g_Qpk);
    cudaGetSymbolAddress((void**)&Kpk, g_Kpk);
    cudaGetSymbolAddress((void**)&Vp, g_Vp);
    cudaGetSymbolAddress((void**)&Esc, g_escore);
    cudaGetSymbolAddress((void**)&Lp, g_lpart);
    cudaGetSymbolAddress((void**)&Rv, g_rinv);
    cudaGetSymbolAddress((void**)&Ao, g_ao);
    cudaGetSymbolAddress((void**)&Av, g_avpart);

    const int smem1 = (2 * 128 * PKW + 128 * 4) * 4;   // 2 packed tiles + rowsum
    cudaFuncSetAttribute(mma_pass1, cudaFuncAttributeMaxDynamicSharedMemorySize, smem1);

    dim3 blk(256);

    // 1-2) Q/K projections -> packed head-layout tf32 hi/lo
    proj_gemm<1><<<dim3(8, 32, 1), blk>>>(query, Wq, bq, nullptr, Qpk, DM, DM, DM, DM, 0);
    proj_gemm<1><<<dim3(8, 32, 1), blk>>>(key_, Wk, bk, nullptr, Kpk, DM, DM, DM, DM, 0);

    // 3) V projection
    proj_gemm<0><<<dim3(1, 32, 1), blk>>>(value, Wv, bv, Vp, nullptr, DK, DM, DM, DK, DK);

    // 4) pass1: tf32 mma.sync scores -> exp(scores) + sumexp partials
    mma_pass1<<<dim3(16, 16, BB * HH), 512, smem1>>>(Qpk, Kpk, Esc, Lp);

    // 5) combine partials -> 1/l
    combine_kernel<<<dim3(BB * HH * SS / 256, 1, 1), blk>>>(Lp, Rv);

    // 6) head-averaged attention (streaming MAC) -> second output
    avg_kernel<<<dim3(SS, BB, 1), blk>>>(Esc, Rv, out_avg);

    // 7) attn_output = avg @ V (split-K=8)
    av_gemm<<<dim3(8, 16, BB), blk>>>(out_avg, Vp, Av);
    av_reduce<<<dim3(BB * SS * DK / 256, 1, 1), blk>>>(Av, Ao);

    // 8) output = attn_output @ Wo + bo
    proj_gemm<0><<<dim3(8, 32, 1), blk>>>(Ao, Wo, bo, out_main, nullptr, DM, DK, DK, DM, DM);
}

// round 7
// speedup vs baseline: 1.0035x; 1.0035x over previous
#include <cuda_runtime.h>
#include <cstdint>

#define BB 2
#define SS 2048
#define HH 16
#define DK 64
#define DM 1024
#define ROWS (BB*SS)          // 4096

// ---------------- scratch -----------------------------------------------------
// packed Q/K: float4 per (bh, s, f): f = k8*4+tig -> {hi(k8*8+tig), hi(+4), lo(tig), lo(+4)}
__device__ float4 g_Qpk[(size_t)BB*HH*SS*32];
__device__ float4 g_Kpk[(size_t)BB*HH*SS*32];
__device__ float g_Vp[(size_t)ROWS*DK];
__device__ float g_escore[(size_t)BB*HH*SS*SS];   // exp(s/8) (536 MB)
__device__ float g_lpart[(size_t)BB*HH*16*SS];    // per (bh, ktile, q) partial sumexp
__device__ float g_rinv[(size_t)BB*HH*SS];        // 1 / l
__device__ float g_ao[(size_t)ROWS*DK];           // attn_output
__device__ float g_avpart[(size_t)8*BB*SS*DK];    // split-K partials for avg@V

// ---------------- helpers -------------------------------------------------------
__device__ __forceinline__ float fast_exp(float x) {
    x = fmaxf(x, -87.0f);
    float t = fmaf(x, 1.4426950408889634f, 12582912.0f);
    float n = t - 12582912.0f;
    float f = fmaf(x, 1.4426950408889634f, -n);
    float p = 1.5403530394e-4f;
    p = fmaf(p, f, 1.3333558146e-3f);
    p = fmaf(p, f, 9.6178371906e-3f);
    p = fmaf(p, f, 5.5502813330e-2f);
    p = fmaf(p, f, 2.4022650695e-1f);
    p = fmaf(p, f, 6.9314718056e-1f);
    p = fmaf(p, f, 1.0f);
    return p * __int_as_float(((int)n + 127) << 23);
}

__device__ __forceinline__ unsigned long long pack2(float lo, float hi) {
    unsigned long long r;
    asm("mov.b64 %0, {%1, %2};" : "=l"(r) : "f"(lo), "f"(hi));
    return r;
}
__device__ __forceinline__ void unpack2(unsigned long long v, float& lo, float& hi) {
    asm("mov.b64 {%0, %1}, %2;" : "=f"(lo), "=f"(hi) : "l"(v));
}
__device__ __forceinline__ unsigned long long fma2(unsigned long long a,
                                                   unsigned long long b,
                                                   unsigned long long c) {
    unsigned long long d;
    asm("fma.rn.f32x2 %0, %1, %2, %3;" : "=l"(d) : "l"(a), "l"(b), "l"(c));
    return d;
}

__device__ __forceinline__ void mma8(float* c, const uint32_t* a, const uint32_t* b) {
    asm volatile("mma.sync.aligned.m16n8k8.row.col.f32.tf32.tf32.f32 "
        "{%0,%1,%2,%3}, {%4,%5,%6,%7}, {%8,%9}, {%0,%1,%2,%3};"
        : "+f"(c[0]), "+f"(c[1]), "+f"(c[2]), "+f"(c[3])
        : "r"(a[0]), "r"(a[1]), "r"(a[2]), "r"(a[3]), "r"(b[0]), "r"(b[1]));
}

__device__ __forceinline__ void split_tf32(float x, float& hi, float& lo) {
    uint32_t h, l;
    asm("cvt.rna.tf32.f32 %0, %1;" : "=r"(h) : "f"(x));
    float hf = __uint_as_float(h);
    asm("cvt.rna.tf32.f32 %0, %1;" : "=r"(l) : "f"(x - hf));
    hi = hf; lo = __uint_as_float(l);
}

// smem tile: 128 rows x 32 float4, stride 32 float4 (no pad), XOR swizzle on f:
//   f_smem = f ^ ((row & 1) << 2)
// -> every 8-lane LDS.128 phase covers 8 distinct 16B bank-quads (conflict-free).
#define FSWZ(r, f) ((f) ^ (((r) & 1) << 2))

// ---------------- pass 1: MMA scores -> store exp + per-row sumexp ---------------
__global__ __launch_bounds__(512, 1)
void mma_pass1(const float4* __restrict__ Qpk, const float4* __restrict__ Kpk,
               float* __restrict__ Esc, float* __restrict__ lpart)
{
    extern __shared__ float4 smq[];
    float4* Qs = smq;                       // [128][32]
    float4* Ks = Qs + 128 * 32;             // [128][32]
    float* rowsum = (float*)(Ks + 128 * 32);  // [128][4]

    const int tid = threadIdx.x;
    const int kt = blockIdx.x, qt = blockIdx.y, bh = blockIdx.z;
    const long long qbase = ((long long)bh * SS + qt * 128) * 32;   // float4 units
    const long long kbase = ((long long)bh * SS + kt * 128) * 32;

#pragma unroll
    for (int i = 0; i < 8; i++) {
        int idx = tid + i * 512;           // 0..4095
        int r = idx >> 5, f = idx & 31;
        int fs = FSWZ(r, f);
        Qs[r * 32 + fs] = Qpk[qbase + r * 32 + f];
        Ks[r * 32 + fs] = Kpk[kbase + r * 32 + f];
    }
    __syncthreads();

    const int wid = tid >> 5, lane = tid & 31;
    const int wm = wid >> 2, wn = wid & 3;
    const int gid = lane >> 2, tig = lane & 3;

    float acc[2][4][4];
#pragma unroll
    for (int mt = 0; mt < 2; mt++)
#pragma unroll
        for (int nt = 0; nt < 4; nt++)
#pragma unroll
            for (int c = 0; c < 4; c++) acc[mt][nt][c] = 0.f;

#pragma unroll
    for (int k8 = 0; k8 < 8; k8++) {
        const int f = k8 * 4 + tig;
        uint32_t bhf[4][2], blf[4][2];
#pragma unroll
        for (int nt = 0; nt < 4; nt++) {
            int row = wn * 32 + nt * 8 + gid;
            float4 kf = Ks[row * 32 + FSWZ(row, f)];
            bhf[nt][0] = __float_as_uint(kf.x); bhf[nt][1] = __float_as_uint(kf.y);
            blf[nt][0] = __float_as_uint(kf.z); blf[nt][1] = __float_as_uint(kf.w);
        }
#pragma unroll
        for (int mt = 0; mt < 2; mt++) {
            int row0 = wm * 32 + mt * 16 + gid;
            int row1 = row0 + 8;
            float4 q0 = Qs[row0 * 32 + FSWZ(row0, f)];
            float4 q1 = Qs[row1 * 32 + FSWZ(row1, f)];
            uint32_t ah[4], al[4];
            ah[0] = __float_as_uint(q0.x); ah[1] = __float_as_uint(q1.x);
            ah[2] = __float_as_uint(q0.y); ah[3] = __float_as_uint(q1.y);
            al[0] = __float_as_uint(q0.z); al[1] = __float_as_uint(q1.z);
            al[2] = __float_as_uint(q0.w); al[3] = __float_as_uint(q1.w);
#pragma unroll
            for (int nt = 0; nt < 4; nt++) {
                mma8(acc[mt][nt], ah, bhf[nt]);   // hi*hi
                mma8(acc[mt][nt], al, bhf[nt]);   // lo*hi
                mma8(acc[mt][nt], ah, blf[nt]);   // hi*lo
            }
        }
    }

    // scale -> exp -> store exp + per-row partial sumexp
    float* Cp = Esc + ((long long)bh * SS + qt * 128) * SS + kt * 128;
    float p[2][2];
    p[0][0] = p[0][1] = p[1][0] = p[1][1] = 0.f;
#pragma unroll
    for (int mt = 0; mt < 2; mt++)
#pragma unroll
        for (int nt = 0; nt < 4; nt++) {
            float e0 = fast_exp(acc[mt][nt][0] * 0.125f);
            float e1 = fast_exp(acc[mt][nt][1] * 0.125f);
            float e2 = fast_exp(acc[mt][nt][2] * 0.125f);
            float e3 = fast_exp(acc[mt][nt][3] * 0.125f);
            int r0 = wm * 32 + mt * 16 + gid;
            int col = wn * 32 + nt * 8 + tig * 2;
            float2 v0 = {e0, e1}, v1 = {e2, e3};
            *(float2*)&Cp[(long long)r0 * SS + col] = v0;
            *(float2*)&Cp[(long long)(r0 + 8) * SS + col] = v1;
            p[mt][0] += e0 + e1;
            p[mt][1] += e2 + e3;
        }
#pragma unroll
    for (int o = 1; o <= 2; o <<= 1)
#pragma unroll
        for (int mt = 0; mt < 2; mt++) {
            p[mt][0] += __shfl_xor_sync(0xffffffffu, p[mt][0], o);
            p[mt][1] += __shfl_xor_sync(0xffffffffu, p[mt][1], o);
        }
    if (tig == 0) {
#pragma unroll
        for (int mt = 0; mt < 2; mt++)
#pragma unroll
            for (int j = 0; j < 2; j++) {
                int r = wm * 32 + mt * 16 + j * 8 + gid;
                rowsum[r * 4 + wn] = p[mt][j];
            }
    }
    __syncthreads();
    if (tid < 128) {
        float l = rowsum[tid * 4] + rowsum[tid * 4 + 1]
                + rowsum[tid * 4 + 2] + rowsum[tid * 4 + 3];
        lpart[(long long)(bh * 16 + kt) * SS + qt * 128 + tid] = l;
    }
}

// ---------------- combine: rinv = 1 / sum of partials ----------------------------
__global__ __launch_bounds__(256)
void combine_kernel(const float* __restrict__ lpart, float* __restrict__ rinv)
{
    int rowg = blockIdx.x * 256 + threadIdx.x;     // bh*2048 + q
    int bh = rowg >> 11, q = rowg & (SS - 1);
    float l = 0.f;
#pragma unroll
    for (int t = 0; t < 16; t++)
        l += lpart[(long long)(bh * 16 + t) * SS + q];
    rinv[rowg] = 1.0f / l;
}

// ---------------- head-averaged attention (pure streaming MAC) -------------------
__global__ __launch_bounds__(256)
void avg_kernel(const float* __restrict__ Esc, const float* __restrict__ rinv,
                float* __restrict__ avg)
{
    const int q = blockIdx.x;
    const int b = blockIdx.y;
    const int tid = threadIdx.x;

    __shared__ float rw[HH];
    if (tid < HH) rw[tid] = rinv[((long long)(b * HH + tid) << 11) + q] * (1.0f / HH);
    __syncthreads();

    const float* base = Esc + ((long long)(b * HH) * SS + q) * SS;
    float* dst = avg + ((long long)b * SS + q) * SS;
    for (int k0 = tid * 4; k0 < SS; k0 += 1024) {
        float ax = 0.f, ay = 0.f, az = 0.f, aw = 0.f;
#pragma unroll
        for (int h = 0; h < HH; h++) {
            const float4 s = *(const float4*)(base + (long long)h * SS * SS + k0);
            float r = rw[h];
            ax = fmaf(s.x, r, ax); ay = fmaf(s.y, r, ay);
            az = fmaf(s.z, r, az); aw = fmaf(s.w, r, aw);
        }
        float4 o = {ax, ay, az, aw};
        *(float4*)&dst[k0] = o;
    }
}

// ---------------- projection GEMM (SIMT f32x2) ------------------------------------
#define PADW 132

// MODE: 0 = plain [M,N] output + bias; 1 = packed head-layout hi/lo float4 output
template<int MODE>
__global__ __launch_bounds__(256, 2)
void proj_gemm(const float* __restrict__ A, const float* __restrict__ B,
               const float* __restrict__ bias, float* __restrict__ C,
               float4* __restrict__ Cpk,
               int N, int K, int lda, int ldb, int ldc)
{
    __shared__ __align__(16) float As[16 * PADW];
    __shared__ __align__(16) float Bs[16 * PADW];

    const int rowbase = blockIdx.y * 128;
    const int colbase = blockIdx.x * 128;
    const int tid = threadIdx.x;
    const int tx = tid & 15, ty = tid >> 4;
    const int row0 = ty * 8, col0 = tx * 8;

    float regA[8], regB[8];
    unsigned long long acc[8][4];
#pragma unroll
    for (int i = 0; i < 8; i++)
#pragma unroll
        for (int j = 0; j < 4; j++) acc[i][j] = 0ull;

#pragma unroll
    for (int i = 0; i < 8; i++) {
        int idx = tid + i * 256; int r = idx >> 4, kk = idx & 15;
        regA[i] = A[(long long)(rowbase + r) * lda + kk];
    }
#pragma unroll
    for (int i = 0; i < 8; i++) {
        int idx = tid + i * 256; int kk = idx >> 7, c = idx & 127;
        int col = colbase + c;
        regB[i] = (col < N) ? B[(long long)kk * ldb + col] : 0.f;
    }
#pragma unroll
    for (int i = 0; i < 8; i++) {
        int idx = tid + i * 256; int r = idx >> 4, kk = idx & 15;
        As[kk * PADW + r] = regA[i];
    }
#pragma unroll
    for (int i = 0; i < 8; i++) {
        int idx = tid + i * 256; int kk = idx >> 7, c = idx & 127;
        Bs[kk * PADW + c] = regB[i];
    }
    __syncthreads();

    for (int k0 = 16; ; k0 += 16) {
        const bool more = (k0 < K);
        if (more) {
#pragma unroll
            for (int i = 0; i < 8; i++) {
                int idx = tid + i * 256; int r = idx >> 4, kk = idx & 15;
                regA[i] = A[(long long)(rowbase + r) * lda + k0 + kk];
            }
#pragma unroll
            for (int i = 0; i < 8; i++) {
                int idx = tid + i * 256; int kk = idx >> 7, c = idx & 127;
                int col = colbase + c;
                regB[i] = (col < N) ? B[(long long)(k0 + kk) * ldb + col] : 0.f;
            }
        }
#pragma unroll
        for (int kk = 0; kk < 16; kk++) {
            float4 a0 = *(const float4*)&As[kk * PADW + row0];
            float4 a1 = *(const float4*)&As[kk * PADW + row0 + 4];
            float4 b0 = *(const float4*)&Bs[kk * PADW + col0];
            float4 b1 = *(const float4*)&Bs[kk * PADW + col0 + 4];
            float a[8] = {a0.x, a0.y, a0.z, a0.w, a1.x, a1.y, a1.z, a1.w};
            unsigned long long bp[4];
            bp[0] = pack2(b0.x, b0.y); bp[1] = pack2(b0.z, b0.w);
            bp[2] = pack2(b1.x, b1.y); bp[3] = pack2(b1.z, b1.w);
#pragma unroll
            for (int i = 0; i < 8; i++) {
                unsigned long long ap = pack2(a[i], a[i]);
#pragma unroll
                for (int j = 0; j < 4; j++) acc[i][j] = fma2(ap, bp[j], acc[i][j]);
            }
        }
        if (!more) break;
        __syncthreads();
#pragma unroll
        for (int i = 0; i < 8; i++) {
            int idx = tid + i * 256; int r = idx >> 4, kk = idx & 15;
            As[kk * PADW + r] = regA[i];
        }
#pragma unroll
        for (int i = 0; i < 8; i++) {
            int idx = tid + i * 256; int kk = idx >> 7, c = idx & 127;
            Bs[kk * PADW + c] = regB[i];
        }
        __syncthreads();
    }

#pragma unroll
    for (int i = 0; i < 8; i++) {
        int gr = rowbase + row0 + i;
        if (MODE == 1) {
            // cols col0..col0+7 = exactly one k8 group of one head
            int gcol = colbase + col0;
            int b = gr >> 11, s = gr & (SS - 1);
            int h = gcol >> 6, k8 = (gcol & 63) >> 3;
            float v[8], hv[8], lv[8];
            unpack2(acc[i][0], v[0], v[1]); unpack2(acc[i][1], v[2], v[3]);
            unpack2(acc[i][2], v[4], v[5]); unpack2(acc[i][3], v[6], v[7]);
#pragma unroll
            for (int j = 0; j < 8; j++) {
                v[j] += bias[gcol + j];
                split_tf32(v[j], hv[j], lv[j]);
            }
            long long base4 = (((long long)(b * HH + h) * SS + s) * 8 + k8) * 4;
#pragma unroll
            for (int tg = 0; tg < 4; tg++) {
                float4 o = {hv[tg], hv[tg + 4], lv[tg], lv[tg + 4]};
                Cpk[base4 + tg] = o;
            }
        } else {
#pragma unroll
            for (int j2 = 0; j2 < 4; j2 += 2) {
                int col = colbase + col0 + j2 * 2;
                if (col < N) {
                    float4 v;
                    unpack2(acc[i][j2],     v.x, v.y);
                    unpack2(acc[i][j2 + 1], v.z, v.w);
                    const float4 bb = *(const float4*)&bias[col];
                    v.x += bb.x; v.y += bb.y; v.z += bb.z; v.w += bb.w;
                    *(float4*)&C[(long long)gr * ldc + col] = v;
                }
            }
        }
    }
}

// ---------------- avg @ V (split-K partials) ---------------------------------------
__global__ __launch_bounds__(256)
void av_gemm(const float* __restrict__ avg, const float* __restrict__ V,
             float* __restrict__ part)
{
    __shared__ float As[16 * PADW];
    __shared__ float Bs[16 * 68];
    const int b = blockIdx.z;
    const int rowbase = blockIdx.y * 128;
    const int k0base = blockIdx.x * 256;
    const float* Ap = avg + ((long long)b * SS + rowbase) * SS;
    const float* Vp = V + (long long)b * SS * DK;
    const int tid = threadIdx.x;
    const int tx = tid & 15, ty = tid >> 4;

    float acc[8][4];
#pragma unroll
    for (int i = 0; i < 8; i++)
#pragma unroll
        for (int j = 0; j < 4; j++) acc[i][j] = 0.f;

    for (int kc = 0; kc < 256; kc += 16) {
        const int k0 = k0base + kc;
#pragma unroll
        for (int i = 0; i < 8; i++) {
            int idx = tid + i * 256; int r = idx >> 4, kk = idx & 15;
            As[kk * PADW + r] = Ap[(long long)r * SS + k0 + kk];
        }
#pragma unroll
        for (int i = 0; i < 4; i++) {
            int idx = tid + i * 256; int kk = idx >> 6, cc = idx & 63;
            Bs[kk * 68 + cc] = Vp[(long long)(k0 + kk) * DK + cc];
        }
        __syncthreads();
#pragma unroll
        for (int kk = 0; kk < 16; kk++) {
            float a[8];
#pragma unroll
            for (int i = 0; i < 8; i++) a[i] = As[kk * PADW + ty * 8 + i];
            float4 bv = *(const float4*)&Bs[kk * 68 + tx * 4];
#pragma unroll
            for (int i = 0; i < 8; i++) {
                acc[i][0] = fmaf(a[i], bv.x, acc[i][0]);
                acc[i][1] = fmaf(a[i], bv.y, acc[i][1]);
                acc[i][2] = fmaf(a[i], bv.z, acc[i][2]);
                acc[i][3] = fmaf(a[i], bv.w, acc[i][3]);
            }
        }
        __syncthreads();
    }
    float* P = part + ((long long)(blockIdx.x * BB + b) * SS + rowbase) * DK;
#pragma unroll
    for (int i = 0; i < 8; i++) {
        float4 v = {acc[i][0], acc[i][1], acc[i][2], acc[i][3]};
        *(float4*)&P[(long long)(ty * 8 + i) * DK + tx * 4] = v;
    }
}

__global__ __launch_bounds__(256)
void av_reduce(const float* __restrict__ part, float* __restrict__ Ao)
{
    int i = blockIdx.x * 256 + threadIdx.x;
    float s = 0.f;
#pragma unroll
    for (int t = 0; t < 8; t++) s += part[(long long)t * (BB * SS * DK) + i];
    Ao[i] = s;
}

// ---------------- launch -------------------------------------------------------------
extern "C" void kernel_launch(void* const* d_in, const int* in_sizes, int n_in,
                              void* d_out, int out_size)
{
    const float* query = (const float*)d_in[0];
    const float* key_  = (const float*)d_in[1];
    const float* value = (const float*)d_in[2];
    const float* Wq    = (const float*)d_in[3];
    const float* bq    = (const float*)d_in[4];
    const float* Wk    = (const float*)d_in[5];
    const float* bk    = (const float*)d_in[6];
    const float* Wv    = (const float*)d_in[7];
    const float* bv    = (const float*)d_in[8];
    const float* Wo    = (const float*)d_in[9];
    const float* bo    = (const float*)d_in[10];

    float* out_main = (float*)d_out;                 // [B,S,DM]
    float* out_avg  = out_main + (size_t)ROWS * DM;  // [B,S,S]

    float4 *Qpk, *Kpk;
    float *Vp, *Esc, *Lp, *Rv, *Ao, *Av;
    cudaGetSymbolAddress((void**)&Qpk, g_Qpk);
    cudaGetSymbolAddress((void**)&Kpk, g_Kpk);
    cudaGetSymbolAddress((void**)&Vp, g_Vp);
    cudaGetSymbolAddress((void**)&Esc, g_escore);
    cudaGetSymbolAddress((void**)&Lp, g_lpart);
    cudaGetSymbolAddress((void**)&Rv, g_rinv);
    cudaGetSymbolAddress((void**)&Ao, g_ao);
    cudaGetSymbolAddress((void**)&Av, g_avpart);

    const int smem1 = 2 * 128 * 32 * 16 + 128 * 4 * 4;   // 2 tiles (128KB) + rowsum
    cudaFuncSetAttribute(mma_pass1, cudaFuncAttributeMaxDynamicSharedMemorySize, smem1);

    dim3 blk(256);

    // 1-2) Q/K projections -> packed head-layout tf32 hi/lo
    proj_gemm<1><<<dim3(8, 32, 1), blk>>>(query, Wq, bq, nullptr, Qpk, DM, DM, DM, DM, 0);
    proj_gemm<1><<<dim3(8, 32, 1), blk>>>(key_, Wk, bk, nullptr, Kpk, DM, DM, DM, DM, 0);

    // 3) V projection
    proj_gemm<0><<<dim3(1, 32, 1), blk>>>(value, Wv, bv, Vp, nullptr, DK, DM, DM, DK, DK);

    // 4) pass1: tf32 mma.sync scores -> exp(scores) + sumexp partials
    mma_pass1<<<dim3(16, 16, BB * HH), 512, smem1>>>(Qpk, Kpk, Esc, Lp);

    // 5) combine partials -> 1/l
    combine_kernel<<<dim3(BB * HH * SS / 256, 1, 1), blk>>>(Lp, Rv);

    // 6) head-averaged attention (streaming MAC) -> second output
    avg_kernel<<<dim3(SS, BB, 1), blk>>>(Esc, Rv, out_avg);

    // 7) attn_output = avg @ V (split-K=8)
    av_gemm<<<dim3(8, 16, BB), blk>>>(out_avg, Vp, Av);
    av_reduce<<<dim3(BB * SS * DK / 256, 1, 1), blk>>>(Av, Ao);

    // 8) output = attn_output @ Wo + bo
    proj_gemm<0><<<dim3(8, 32, 1), blk>>>(Ao, Wo, bo, out_main, nullptr, DM, DK, DK, DM, DM);
}

// round 8
// speedup vs baseline: 1.1033x; 1.0995x over previous
#include <cuda_runtime.h>
#include <cuda_fp16.h>
#include <cstdint>

#define BB 2
#define SS 2048
#define HH 16
#define DK 64
#define DM 1024
#define ROWS (BB*SS)          // 4096

// ---------------- scratch -----------------------------------------------------
// packed Q/K: float4 per (bh, s, f): f = k8*4+tig -> {hi(k8*8+tig), hi(+4), lo(tig), lo(+4)}
__device__ float4 g_Qpk[(size_t)BB*HH*SS*32];
__device__ float4 g_Kpk[(size_t)BB*HH*SS*32];
__device__ float g_Vp[(size_t)ROWS*DK];
__device__ __half g_escore[(size_t)BB*HH*SS*SS];  // exp(s/8) fp16 (268 MB)
__device__ float g_lpart[(size_t)BB*HH*16*SS];    // per (bh, ktile, q) partial sumexp
__device__ float g_rinv[(size_t)BB*HH*SS];        // 1 / l
__device__ float g_ao[(size_t)ROWS*DK];           // attn_output
__device__ float g_avpart[(size_t)8*BB*SS*DK];    // split-K partials for avg@V

// ---------------- helpers -------------------------------------------------------
__device__ __forceinline__ float fast_exp(float x) {
    x = fmaxf(x, -87.0f);
    float t = fmaf(x, 1.4426950408889634f, 12582912.0f);
    float n = t - 12582912.0f;
    float f = fmaf(x, 1.4426950408889634f, -n);
    float p = 1.5403530394e-4f;
    p = fmaf(p, f, 1.3333558146e-3f);
    p = fmaf(p, f, 9.6178371906e-3f);
    p = fmaf(p, f, 5.5502813330e-2f);
    p = fmaf(p, f, 2.4022650695e-1f);
    p = fmaf(p, f, 6.9314718056e-1f);
    p = fmaf(p, f, 1.0f);
    return p * __int_as_float(((int)n + 127) << 23);
}

__device__ __forceinline__ unsigned long long pack2(float lo, float hi) {
    unsigned long long r;
    asm("mov.b64 %0, {%1, %2};" : "=l"(r) : "f"(lo), "f"(hi));
    return r;
}
__device__ __forceinline__ void unpack2(unsigned long long v, float& lo, float& hi) {
    asm("mov.b64 {%0, %1}, %2;" : "=f"(lo), "=f"(hi) : "l"(v));
}
__device__ __forceinline__ unsigned long long fma2(unsigned long long a,
                                                   unsigned long long b,
                                                   unsigned long long c) {
    unsigned long long d;
    asm("fma.rn.f32x2 %0, %1, %2, %3;" : "=l"(d) : "l"(a), "l"(b), "l"(c));
    return d;
}

__device__ __forceinline__ void mma8(float* c, const uint32_t* a, const uint32_t* b) {
    asm volatile("mma.sync.aligned.m16n8k8.row.col.f32.tf32.tf32.f32 "
        "{%0,%1,%2,%3}, {%4,%5,%6,%7}, {%8,%9}, {%0,%1,%2,%3};"
        : "+f"(c[0]), "+f"(c[1]), "+f"(c[2]), "+f"(c[3])
        : "r"(a[0]), "r"(a[1]), "r"(a[2]), "r"(a[3]), "r"(b[0]), "r"(b[1]));
}

__device__ __forceinline__ void split_tf32(float x, float& hi, float& lo) {
    uint32_t h, l;
    asm("cvt.rna.tf32.f32 %0, %1;" : "=r"(h) : "f"(x));
    float hf = __uint_as_float(h);
    asm("cvt.rna.tf32.f32 %0, %1;" : "=r"(l) : "f"(x - hf));
    hi = hf; lo = __uint_as_float(l);
}

// XOR swizzle on float4 index (row parity) -> conflict-free LDS.128/STS.128
#define FSWZ(r, f) ((f) ^ (((r) & 1) << 2))

// ---------------- pass 1: 256x128 tile, MMA -> fp16 exp + per-row sumexp ---------
__global__ __launch_bounds__(512, 1)
void mma_pass1(const float4* __restrict__ Qpk, const float4* __restrict__ Kpk,
               __half* __restrict__ Esc, float* __restrict__ lpart)
{
    extern __shared__ float4 smq[];
    float4* Qs = smq;                        // [256][32]
    float4* Ks = Qs + 256 * 32;              // [128][32]
    float* rowsum = (float*)(Ks + 128 * 32); // [256][4]

    const int tid = threadIdx.x;
    const int kt = blockIdx.x, qt = blockIdx.y, bh = blockIdx.z;
    const long long qbase = ((long long)bh * SS + qt * 256) * 32;   // float4 units
    const long long kbase = ((long long)bh * SS + kt * 128) * 32;

#pragma unroll
    for (int i = 0; i < 16; i++) {
        int idx = tid + i * 512;             // 0..8191
        int r = idx >> 5, f = idx & 31;
        Qs[r * 32 + FSWZ(r, f)] = Qpk[qbase + r * 32 + f];
    }
#pragma unroll
    for (int i = 0; i < 8; i++) {
        int idx = tid + i * 512;             // 0..4095
        int r = idx >> 5, f = idx & 31;
        Ks[r * 32 + FSWZ(r, f)] = Kpk[kbase + r * 32 + f];
    }
    __syncthreads();

    const int wid = tid >> 5, lane = tid & 31;
    const int wm = wid >> 2, wn = wid & 3;        // 4x4 warp grid
    const int gid = lane >> 2, tig = lane & 3;

    float acc[4][4][4];
#pragma unroll
    for (int mt = 0; mt < 4; mt++)
#pragma unroll
        for (int nt = 0; nt < 4; nt++)
#pragma unroll
            for (int c = 0; c < 4; c++) acc[mt][nt][c] = 0.f;

#pragma unroll
    for (int k8 = 0; k8 < 8; k8++) {
        const int f = k8 * 4 + tig;
        uint32_t bhf[4][2], blf[4][2];
#pragma unroll
        for (int nt = 0; nt < 4; nt++) {
            int row = wn * 32 + nt * 8 + gid;
            float4 kf = Ks[row * 32 + FSWZ(row, f)];
            bhf[nt][0] = __float_as_uint(kf.x); bhf[nt][1] = __float_as_uint(kf.y);
            blf[nt][0] = __float_as_uint(kf.z); blf[nt][1] = __float_as_uint(kf.w);
        }
#pragma unroll
        for (int mt = 0; mt < 4; mt++) {
            int row0 = wm * 64 + mt * 16 + gid;
            int row1 = row0 + 8;
            float4 q0 = Qs[row0 * 32 + FSWZ(row0, f)];
            float4 q1 = Qs[row1 * 32 + FSWZ(row1, f)];
            uint32_t ah[4], al[4];
            ah[0] = __float_as_uint(q0.x); ah[1] = __float_as_uint(q1.x);
            ah[2] = __float_as_uint(q0.y); ah[3] = __float_as_uint(q1.y);
            al[0] = __float_as_uint(q0.z); al[1] = __float_as_uint(q1.z);
            al[2] = __float_as_uint(q0.w); al[3] = __float_as_uint(q1.w);
#pragma unroll
            for (int nt = 0; nt < 4; nt++) {
                mma8(acc[mt][nt], ah, bhf[nt]);   // hi*hi
                mma8(acc[mt][nt], al, bhf[nt]);   // lo*hi
                mma8(acc[mt][nt], ah, blf[nt]);   // hi*lo
            }
        }
    }

    // scale -> exp -> store fp16 + per-row fp32 partial sumexp
    __half* Cp = Esc + ((long long)bh * SS + qt * 256) * SS + kt * 128;
    float p[4][2];
#pragma unroll
    for (int mt = 0; mt < 4; mt++) { p[mt][0] = 0.f; p[mt][1] = 0.f; }
#pragma unroll
    for (int mt = 0; mt < 4; mt++)
#pragma unroll
        for (int nt = 0; nt < 4; nt++) {
            float e0 = fast_exp(acc[mt][nt][0] * 0.125f);
            float e1 = fast_exp(acc[mt][nt][1] * 0.125f);
            float e2 = fast_exp(acc[mt][nt][2] * 0.125f);
            float e3 = fast_exp(acc[mt][nt][3] * 0.125f);
            int r0 = wm * 64 + mt * 16 + gid;
            int col = wn * 32 + nt * 8 + tig * 2;
            *(__half2*)&Cp[(long long)r0 * SS + col] = __floats2half2_rn(e0, e1);
            *(__half2*)&Cp[(long long)(r0 + 8) * SS + col] = __floats2half2_rn(e2, e3);
            p[mt][0] += e0 + e1;
            p[mt][1] += e2 + e3;
        }
#pragma unroll
    for (int o = 1; o <= 2; o <<= 1)
#pragma unroll
        for (int mt = 0; mt < 4; mt++) {
            p[mt][0] += __shfl_xor_sync(0xffffffffu, p[mt][0], o);
            p[mt][1] += __shfl_xor_sync(0xffffffffu, p[mt][1], o);
        }
    if (tig == 0) {
#pragma unroll
        for (int mt = 0; mt < 4; mt++)
#pragma unroll
            for (int j = 0; j < 2; j++) {
                int r = wm * 64 + mt * 16 + j * 8 + gid;
                rowsum[r * 4 + wn] = p[mt][j];
            }
    }
    __syncthreads();
    if (tid < 256) {
        float l = rowsum[tid * 4] + rowsum[tid * 4 + 1]
                + rowsum[tid * 4 + 2] + rowsum[tid * 4 + 3];
        lpart[(long long)(bh * 16 + kt) * SS + qt * 256 + tid] = l;
    }
}

// ---------------- combine: rinv = 1 / sum of partials ----------------------------
__global__ __launch_bounds__(256)
void combine_kernel(const float* __restrict__ lpart, float* __restrict__ rinv)
{
    int rowg = blockIdx.x * 256 + threadIdx.x;     // bh*2048 + q
    int bh = rowg >> 11, q = rowg & (SS - 1);
    float l = 0.f;
#pragma unroll
    for (int t = 0; t < 16; t++)
        l += lpart[(long long)(bh * 16 + t) * SS + q];
    rinv[rowg] = 1.0f / l;
}

// ---------------- head-averaged attention (fp16 stream MAC) ----------------------
__global__ __launch_bounds__(256)
void avg_kernel(const __half* __restrict__ Esc, const float* __restrict__ rinv,
                float* __restrict__ avg)
{
    const int q = blockIdx.x;
    const int b = blockIdx.y;
    const int tid = threadIdx.x;

    __shared__ float rw[HH];
    if (tid < HH) rw[tid] = rinv[((long long)(b * HH + tid) << 11) + q] * (1.0f / HH);
    __syncthreads();

    const __half* base = Esc + ((long long)(b * HH) * SS + q) * SS;
    const int k0 = tid * 8;                       // 256 thr * 8 = 2048
    float a0 = 0.f, a1 = 0.f, a2 = 0.f, a3 = 0.f;
    float a4 = 0.f, a5 = 0.f, a6 = 0.f, a7 = 0.f;
#pragma unroll
    for (int h = 0; h < HH; h++) {
        uint4 raw = *(const uint4*)(base + (long long)h * SS * SS + k0);
        float2 f0 = __half22float2(*(__half2*)&raw.x);
        float2 f1 = __half22float2(*(__half2*)&raw.y);
        float2 f2 = __half22float2(*(__half2*)&raw.z);
        float2 f3 = __half22float2(*(__half2*)&raw.w);
        float r = rw[h];
        a0 = fmaf(f0.x, r, a0); a1 = fmaf(f0.y, r, a1);
        a2 = fmaf(f1.x, r, a2); a3 = fmaf(f1.y, r, a3);
        a4 = fmaf(f2.x, r, a4); a5 = fmaf(f2.y, r, a5);
        a6 = fmaf(f3.x, r, a6); a7 = fmaf(f3.y, r, a7);
    }
    float* dst = avg + ((long long)b * SS + q) * SS + k0;
    float4 o0 = {a0, a1, a2, a3};
    float4 o1 = {a4, a5, a6, a7};
    *(float4*)&dst[0] = o0;
    *(float4*)&dst[4] = o1;
}

// ---------------- projection GEMM (SIMT f32x2) ------------------------------------
#define PADW 132

// MODE: 0 = plain [M,N] output + bias; 1 = packed head-layout hi/lo float4 output
template<int MODE>
__global__ __launch_bounds__(256, 2)
void proj_gemm(const float* __restrict__ A, const float* __restrict__ B,
               const float* __restrict__ bias, float* __restrict__ C,
               float4* __restrict__ Cpk,
               int N, int K, int lda, int ldb, int ldc)
{
    __shared__ __align__(16) float As[16 * PADW];
    __shared__ __align__(16) float Bs[16 * PADW];

    const int rowbase = blockIdx.y * 128;
    const int colbase = blockIdx.x * 128;
    const int tid = threadIdx.x;
    const int tx = tid & 15, ty = tid >> 4;
    const int row0 = ty * 8, col0 = tx * 8;

    float regA[8], regB[8];
    unsigned long long acc[8][4];
#pragma unroll
    for (int i = 0; i < 8; i++)
#pragma unroll
        for (int j = 0; j < 4; j++) acc[i][j] = 0ull;

#pragma unroll
    for (int i = 0; i < 8; i++) {
        int idx = tid + i * 256; int r = idx >> 4, kk = idx & 15;
        regA[i] = A[(long long)(rowbase + r) * lda + kk];
    }
#pragma unroll
    for (int i = 0; i < 8; i++) {
        int idx = tid + i * 256; int kk = idx >> 7, c = idx & 127;
        int col = colbase + c;
        regB[i] = (col < N) ? B[(long long)kk * ldb + col] : 0.f;
    }
#pragma unroll
    for (int i = 0; i < 8; i++) {
        int idx = tid + i * 256; int r = idx >> 4, kk = idx & 15;
        As[kk * PADW + r] = regA[i];
    }
#pragma unroll
    for (int i = 0; i < 8; i++) {
        int idx = tid + i * 256; int kk = idx >> 7, c = idx & 127;
        Bs[kk * PADW + c] = regB[i];
    }
    __syncthreads();

    for (int k0 = 16; ; k0 += 16) {
        const bool more = (k0 < K);
        if (more) {
#pragma unroll
            for (int i = 0; i < 8; i++) {
                int idx = tid + i * 256; int r = idx >> 4, kk = idx & 15;
                regA[i] = A[(long long)(rowbase + r) * lda + k0 + kk];
            }
#pragma unroll
            for (int i = 0; i < 8; i++) {
                int idx = tid + i * 256; int kk = idx >> 7, c = idx & 127;
                int col = colbase + c;
                regB[i] = (col < N) ? B[(long long)(k0 + kk) * ldb + col] : 0.f;
            }
        }
#pragma unroll
        for (int kk = 0; kk < 16; kk++) {
            float4 a0 = *(const float4*)&As[kk * PADW + row0];
            float4 a1 = *(const float4*)&As[kk * PADW + row0 + 4];
            float4 b0 = *(const float4*)&Bs[kk * PADW + col0];
            float4 b1 = *(const float4*)&Bs[kk * PADW + col0 + 4];
            float a[8] = {a0.x, a0.y, a0.z, a0.w, a1.x, a1.y, a1.z, a1.w};
            unsigned long long bp[4];
            bp[0] = pack2(b0.x, b0.y); bp[1] = pack2(b0.z, b0.w);
            bp[2] = pack2(b1.x, b1.y); bp[3] = pack2(b1.z, b1.w);
#pragma unroll
            for (int i = 0; i < 8; i++) {
                unsigned long long ap = pack2(a[i], a[i]);
#pragma unroll
                for (int j = 0; j < 4; j++) acc[i][j] = fma2(ap, bp[j], acc[i][j]);
            }
        }
        if (!more) break;
        __syncthreads();
#pragma unroll
        for (int i = 0; i < 8; i++) {
            int idx = tid + i * 256; int r = idx >> 4, kk = idx & 15;
            As[kk * PADW + r] = regA[i];
        }
#pragma unroll
        for (int i = 0; i < 8; i++) {
            int idx = tid + i * 256; int kk = idx >> 7, c = idx & 127;
            Bs[kk * PADW + c] = regB[i];
        }
        __syncthreads();
    }

#pragma unroll
    for (int i = 0; i < 8; i++) {
        int gr = rowbase + row0 + i;
        if (MODE == 1) {
            // cols col0..col0+7 = exactly one k8 group of one head
            int gcol = colbase + col0;
            int b = gr >> 11, s = gr & (SS - 1);
            int h = gcol >> 6, k8 = (gcol & 63) >> 3;
            float v[8], hv[8], lv[8];
            unpack2(acc[i][0], v[0], v[1]); unpack2(acc[i][1], v[2], v[3]);
            unpack2(acc[i][2], v[4], v[5]); unpack2(acc[i][3], v[6], v[7]);
#pragma unroll
            for (int j = 0; j < 8; j++) {
                v[j] += bias[gcol + j];
                split_tf32(v[j], hv[j], lv[j]);
            }
            long long base4 = (((long long)(b * HH + h) * SS + s) * 8 + k8) * 4;
#pragma unroll
            for (int tg = 0; tg < 4; tg++) {
                float4 o = {hv[tg], hv[tg + 4], lv[tg], lv[tg + 4]};
                Cpk[base4 + tg] = o;
            }
        } else {
#pragma unroll
            for (int j2 = 0; j2 < 4; j2 += 2) {
                int col = colbase + col0 + j2 * 2;
                if (col < N) {
                    float4 v;
                    unpack2(acc[i][j2],     v.x, v.y);
                    unpack2(acc[i][j2 + 1], v.z, v.w);
                    const float4 bb = *(const float4*)&bias[col];
                    v.x += bb.x; v.y += bb.y; v.z += bb.z; v.w += bb.w;
                    *(float4*)&C[(long long)gr * ldc + col] = v;
                }
            }
        }
    }
}

// ---------------- avg @ V (split-K partials) ---------------------------------------
__global__ __launch_bounds__(256)
void av_gemm(const float* __restrict__ avg, const float* __restrict__ V,
             float* __restrict__ part)
{
    __shared__ float As[16 * PADW];
    __shared__ float Bs[16 * 68];
    const int b = blockIdx.z;
    const int rowbase = blockIdx.y * 128;
    const int k0base = blockIdx.x * 256;
    const float* Ap = avg + ((long long)b * SS + rowbase) * SS;
    const float* Vp = V + (long long)b * SS * DK;
    const int tid = threadIdx.x;
    const int tx = tid & 15, ty = tid >> 4;

    float acc[8][4];
#pragma unroll
    for (int i = 0; i < 8; i++)
#pragma unroll
        for (int j = 0; j < 4; j++) acc[i][j] = 0.f;

    for (int kc = 0; kc < 256; kc += 16) {
        const int k0 = k0base + kc;
#pragma unroll
        for (int i = 0; i < 8; i++) {
            int idx = tid + i * 256; int r = idx >> 4, kk = idx & 15;
            As[kk * PADW + r] = Ap[(long long)r * SS + k0 + kk];
        }
#pragma unroll
        for (int i = 0; i < 4; i++) {
            int idx = tid + i * 256; int kk = idx >> 6, cc = idx & 63;
            Bs[kk * 68 + cc] = Vp[(long long)(k0 + kk) * DK + cc];
        }
        __syncthreads();
#pragma unroll
        for (int kk = 0; kk < 16; kk++) {
            float a[8];
#pragma unroll
            for (int i = 0; i < 8; i++) a[i] = As[kk * PADW + ty * 8 + i];
            float4 bv = *(const float4*)&Bs[kk * 68 + tx * 4];
#pragma unroll
            for (int i = 0; i < 8; i++) {
                acc[i][0] = fmaf(a[i], bv.x, acc[i][0]);
                acc[i][1] = fmaf(a[i], bv.y, acc[i][1]);
                acc[i][2] = fmaf(a[i], bv.z, acc[i][2]);
                acc[i][3] = fmaf(a[i], bv.w, acc[i][3]);
            }
        }
        __syncthreads();
    }
    float* P = part + ((long long)(blockIdx.x * BB + b) * SS + rowbase) * DK;
#pragma unroll
    for (int i = 0; i < 8; i++) {
        float4 v = {acc[i][0], acc[i][1], acc[i][2], acc[i][3]};
        *(float4*)&P[(long long)(ty * 8 + i) * DK + tx * 4] = v;
    }
}

__global__ __launch_bounds__(256)
void av_reduce(const float* __restrict__ part, float* __restrict__ Ao)
{
    int i = blockIdx.x * 256 + threadIdx.x;
    float s = 0.f;
#pragma unroll
    for (int t = 0; t < 8; t++) s += part[(long long)t * (BB * SS * DK) + i];
    Ao[i] = s;
}

// ---------------- launch -------------------------------------------------------------
extern "C" void kernel_launch(void* const* d_in, const int* in_sizes, int n_in,
                              void* d_out, int out_size)
{
    const float* query = (const float*)d_in[0];
    const float* key_  = (const float*)d_in[1];
    const float* value = (const float*)d_in[2];
    const float* Wq    = (const float*)d_in[3];
    const float* bq    = (const float*)d_in[4];
    const float* Wk    = (const float*)d_in[5];
    const float* bk    = (const float*)d_in[6];
    const float* Wv    = (const float*)d_in[7];
    const float* bv    = (const float*)d_in[8];
    const float* Wo    = (const float*)d_in[9];
    const float* bo    = (const float*)d_in[10];

    float* out_main = (float*)d_out;                 // [B,S,DM]
    float* out_avg  = out_main + (size_t)ROWS * DM;  // [B,S,S]

    float4 *Qpk, *Kpk;
    __half* Esc;
    float *Vp, *Lp, *Rv, *Ao, *Av;
    cudaGetSymbolAddress((void**)&Qpk, g_Qpk);
    cudaGetSymbolAddress((void**)&Kpk, g_Kpk);
    cudaGetSymbolAddress((void**)&Vp, g_Vp);
    cudaGetSymbolAddress((void**)&Esc, g_escore);
    cudaGetSymbolAddress((void**)&Lp, g_lpart);
    cudaGetSymbolAddress((void**)&Rv, g_rinv);
    cudaGetSymbolAddress((void**)&Ao, g_ao);
    cudaGetSymbolAddress((void**)&Av, g_avpart);

    // Q tile 256x32 f4 + K tile 128x32 f4 + rowsum 256x4 f32
    const int smem1 = (256 + 128) * 32 * 16 + 256 * 4 * 4;   // 200704 B
    cudaFuncSetAttribute(mma_pass1, cudaFuncAttributeMaxDynamicSharedMemorySize, smem1);

    dim3 blk(256);

    // 1-2) Q/K projections -> packed head-layout tf32 hi/lo
    proj_gemm<1><<<dim3(8, 32, 1), blk>>>(query, Wq, bq, nullptr, Qpk, DM, DM, DM, DM, 0);
    proj_gemm<1><<<dim3(8, 32, 1), blk>>>(key_, Wk, bk, nullptr, Kpk, DM, DM, DM, DM, 0);

    // 3) V projection
    proj_gemm<0><<<dim3(1, 32, 1), blk>>>(value, Wv, bv, Vp, nullptr, DK, DM, DM, DK, DK);

    // 4) pass1: tf32 mma.sync scores (256x128 tiles) -> fp16 exp + sumexp partials
    mma_pass1<<<dim3(16, 8, BB * HH), 512, smem1>>>(Qpk, Kpk, Esc, Lp);

    // 5) combine partials -> 1/l
    combine_kernel<<<dim3(BB * HH * SS / 256, 1, 1), blk>>>(Lp, Rv);

    // 6) head-averaged attention (fp16 streaming MAC) -> second output
    avg_kernel<<<dim3(SS, BB, 1), blk>>>(Esc, Rv, out_avg);

    // 7) attn_output = avg @ V (split-K=8)
    av_gemm<<<dim3(8, 16, BB), blk>>>(out_avg, Vp, Av);
    av_reduce<<<dim3(BB * SS * DK / 256, 1, 1), blk>>>(Av, Ao);

    // 8) output = attn_output @ Wo + bo
    proj_gemm<0><<<dim3(8, 32, 1), blk>>>(Ao, Wo, bo, out_main, nullptr, DM, DK, DK, DM, DM);
}

// round 9
// speedup vs baseline: 1.1049x; 1.0014x over previous
#include <cuda_runtime.h>
#include <cuda_fp16.h>
#include <cstdint>

#define BB 2
#define SS 2048
#define HH 16
#define DK 64
#define DM 1024
#define ROWS (BB*SS)          // 4096

// ---------------- scratch -----------------------------------------------------
// packed Q/K: float4 per (bh, s, f): f = k8*4+tig -> {hi(k8*8+tig), hi(+4), lo(tig), lo(+4)}
__device__ float4 g_Qpk[(size_t)BB*HH*SS*32];
__device__ float4 g_Kpk[(size_t)BB*HH*SS*32];
__device__ float g_Vp[(size_t)ROWS*DK];
__device__ __half g_escore[(size_t)BB*HH*SS*SS];  // exp(s/8) fp16 (268 MB)
__device__ float g_lpart[(size_t)BB*HH*16*SS];    // per (bh, ktile, q) partial sumexp
__device__ float g_rinv[(size_t)BB*HH*SS];        // 1 / l
__device__ float g_ao[(size_t)ROWS*DK];           // attn_output
__device__ float g_avpart[(size_t)8*BB*SS*DK];    // split-K partials for avg@V

// ---------------- helpers -------------------------------------------------------
__device__ __forceinline__ float fast_exp(float x) {
    x = fmaxf(x, -87.0f);
    float t = fmaf(x, 1.4426950408889634f, 12582912.0f);
    float n = t - 12582912.0f;
    float f = fmaf(x, 1.4426950408889634f, -n);
    float p = 1.5403530394e-4f;
    p = fmaf(p, f, 1.3333558146e-3f);
    p = fmaf(p, f, 9.6178371906e-3f);
    p = fmaf(p, f, 5.5502813330e-2f);
    p = fmaf(p, f, 2.4022650695e-1f);
    p = fmaf(p, f, 6.9314718056e-1f);
    p = fmaf(p, f, 1.0f);
    return p * __int_as_float(((int)n + 127) << 23);
}

__device__ __forceinline__ unsigned long long pack2(float lo, float hi) {
    unsigned long long r;
    asm("mov.b64 %0, {%1, %2};" : "=l"(r) : "f"(lo), "f"(hi));
    return r;
}
__device__ __forceinline__ void unpack2(unsigned long long v, float& lo, float& hi) {
    asm("mov.b64 {%0, %1}, %2;" : "=f"(lo), "=f"(hi) : "l"(v));
}
__device__ __forceinline__ unsigned long long fma2(unsigned long long a,
                                                   unsigned long long b,
                                                   unsigned long long c) {
    unsigned long long d;
    asm("fma.rn.f32x2 %0, %1, %2, %3;" : "=l"(d) : "l"(a), "l"(b), "l"(c));
    return d;
}

__device__ __forceinline__ void mma8(float* c, const uint32_t* a, const uint32_t* b) {
    asm volatile("mma.sync.aligned.m16n8k8.row.col.f32.tf32.tf32.f32 "
        "{%0,%1,%2,%3}, {%4,%5,%6,%7}, {%8,%9}, {%0,%1,%2,%3};"
        : "+f"(c[0]), "+f"(c[1]), "+f"(c[2]), "+f"(c[3])
        : "r"(a[0]), "r"(a[1]), "r"(a[2]), "r"(a[3]), "r"(b[0]), "r"(b[1]));
}

__device__ __forceinline__ void split_tf32(float x, float& hi, float& lo) {
    uint32_t h, l;
    asm("cvt.rna.tf32.f32 %0, %1;" : "=r"(h) : "f"(x));
    float hf = __uint_as_float(h);
    asm("cvt.rna.tf32.f32 %0, %1;" : "=r"(l) : "f"(x - hf));
    hi = hf; lo = __uint_as_float(l);
}

// XOR swizzle on float4 index (row parity) -> conflict-free LDS.128/STS.128
#define FSWZ(r, f) ((f) ^ (((r) & 1) << 2))

// ---------------- pass 1: 256x128 tile, MMA -> fp16 exp + per-row sumexp ---------
__global__ __launch_bounds__(512, 1)
void mma_pass1(const float4* __restrict__ Qpk, const float4* __restrict__ Kpk,
               __half* __restrict__ Esc, float* __restrict__ lpart)
{
    extern __shared__ float4 smq[];
    float4* Qs = smq;                        // [256][32]
    float4* Ks = Qs + 256 * 32;              // [128][32]
    float* rowsum = (float*)(Ks + 128 * 32); // [256][4]

    const int tid = threadIdx.x;
    const int kt = blockIdx.x, qt = blockIdx.y, bh = blockIdx.z;
    const long long qbase = ((long long)bh * SS + qt * 256) * 32;   // float4 units
    const long long kbase = ((long long)bh * SS + kt * 128) * 32;

#pragma unroll
    for (int i = 0; i < 16; i++) {
        int idx = tid + i * 512;             // 0..8191
        int r = idx >> 5, f = idx & 31;
        Qs[r * 32 + FSWZ(r, f)] = Qpk[qbase + r * 32 + f];
    }
#pragma unroll
    for (int i = 0; i < 8; i++) {
        int idx = tid + i * 512;             // 0..4095
        int r = idx >> 5, f = idx & 31;
        Ks[r * 32 + FSWZ(r, f)] = Kpk[kbase + r * 32 + f];
    }
    __syncthreads();

    const int wid = tid >> 5, lane = tid & 31;
    const int wm = wid >> 2, wn = wid & 3;        // 4x4 warp grid
    const int gid = lane >> 2, tig = lane & 3;

    float acc[4][4][4];
#pragma unroll
    for (int mt = 0; mt < 4; mt++)
#pragma unroll
        for (int nt = 0; nt < 4; nt++)
#pragma unroll
            for (int c = 0; c < 4; c++) acc[mt][nt][c] = 0.f;

#pragma unroll
    for (int k8 = 0; k8 < 8; k8++) {
        const int f = k8 * 4 + tig;
        uint32_t bhf[4][2], blf[4][2];
#pragma unroll
        for (int nt = 0; nt < 4; nt++) {
            int row = wn * 32 + nt * 8 + gid;
            float4 kf = Ks[row * 32 + FSWZ(row, f)];
            bhf[nt][0] = __float_as_uint(kf.x); bhf[nt][1] = __float_as_uint(kf.y);
            blf[nt][0] = __float_as_uint(kf.z); blf[nt][1] = __float_as_uint(kf.w);
        }
#pragma unroll
        for (int mt = 0; mt < 4; mt++) {
            int row0 = wm * 64 + mt * 16 + gid;
            int row1 = row0 + 8;
            float4 q0 = Qs[row0 * 32 + FSWZ(row0, f)];
            float4 q1 = Qs[row1 * 32 + FSWZ(row1, f)];
            uint32_t ah[4], al[4];
            ah[0] = __float_as_uint(q0.x); ah[1] = __float_as_uint(q1.x);
            ah[2] = __float_as_uint(q0.y); ah[3] = __float_as_uint(q1.y);
            al[0] = __float_as_uint(q0.z); al[1] = __float_as_uint(q1.z);
            al[2] = __float_as_uint(q0.w); al[3] = __float_as_uint(q1.w);
#pragma unroll
            for (int nt = 0; nt < 4; nt++) {
                mma8(acc[mt][nt], ah, bhf[nt]);   // hi*hi
                mma8(acc[mt][nt], al, bhf[nt]);   // lo*hi
                mma8(acc[mt][nt], ah, blf[nt]);   // hi*lo
            }
        }
    }

    // scale -> exp -> store fp16 + per-row fp32 partial sumexp
    __half* Cp = Esc + ((long long)bh * SS + qt * 256) * SS + kt * 128;
    float p[4][2];
#pragma unroll
    for (int mt = 0; mt < 4; mt++) { p[mt][0] = 0.f; p[mt][1] = 0.f; }
#pragma unroll
    for (int mt = 0; mt < 4; mt++)
#pragma unroll
        for (int nt = 0; nt < 4; nt++) {
            float e0 = fast_exp(acc[mt][nt][0] * 0.125f);
            float e1 = fast_exp(acc[mt][nt][1] * 0.125f);
            float e2 = fast_exp(acc[mt][nt][2] * 0.125f);
            float e3 = fast_exp(acc[mt][nt][3] * 0.125f);
            int r0 = wm * 64 + mt * 16 + gid;
            int col = wn * 32 + nt * 8 + tig * 2;
            *(__half2*)&Cp[(long long)r0 * SS + col] = __floats2half2_rn(e0, e1);
            *(__half2*)&Cp[(long long)(r0 + 8) * SS + col] = __floats2half2_rn(e2, e3);
            p[mt][0] += e0 + e1;
            p[mt][1] += e2 + e3;
        }
#pragma unroll
    for (int o = 1; o <= 2; o <<= 1)
#pragma unroll
        for (int mt = 0; mt < 4; mt++) {
            p[mt][0] += __shfl_xor_sync(0xffffffffu, p[mt][0], o);
            p[mt][1] += __shfl_xor_sync(0xffffffffu, p[mt][1], o);
        }
    if (tig == 0) {
#pragma unroll
        for (int mt = 0; mt < 4; mt++)
#pragma unroll
            for (int j = 0; j < 2; j++) {
                int r = wm * 64 + mt * 16 + j * 8 + gid;
                rowsum[r * 4 + wn] = p[mt][j];
            }
    }
    __syncthreads();
    if (tid < 256) {
        float l = rowsum[tid * 4] + rowsum[tid * 4 + 1]
                + rowsum[tid * 4 + 2] + rowsum[tid * 4 + 3];
        lpart[(long long)(bh * 16 + kt) * SS + qt * 256 + tid] = l;
    }
}

// ---------------- combine: rinv = 1 / sum of partials ----------------------------
__global__ __launch_bounds__(256)
void combine_kernel(const float* __restrict__ lpart, float* __restrict__ rinv)
{
    int rowg = blockIdx.x * 256 + threadIdx.x;     // bh*2048 + q
    int bh = rowg >> 11, q = rowg & (SS - 1);
    float l = 0.f;
#pragma unroll
    for (int t = 0; t < 16; t++)
        l += lpart[(long long)(bh * 16 + t) * SS + q];
    rinv[rowg] = 1.0f / l;
}

// ---------------- head-averaged attention (fp16 stream MAC) ----------------------
__global__ __launch_bounds__(256)
void avg_kernel(const __half* __restrict__ Esc, const float* __restrict__ rinv,
                float* __restrict__ avg)
{
    const int q = blockIdx.x;
    const int b = blockIdx.y;
    const int tid = threadIdx.x;

    __shared__ float rw[HH];
    if (tid < HH) rw[tid] = rinv[((long long)(b * HH + tid) << 11) + q] * (1.0f / HH);
    __syncthreads();

    const __half* base = Esc + ((long long)(b * HH) * SS + q) * SS;
    const int k0 = tid * 8;                       // 256 thr * 8 = 2048
    float a0 = 0.f, a1 = 0.f, a2 = 0.f, a3 = 0.f;
    float a4 = 0.f, a5 = 0.f, a6 = 0.f, a7 = 0.f;
#pragma unroll
    for (int h = 0; h < HH; h++) {
        uint4 raw = *(const uint4*)(base + (long long)h * SS * SS + k0);
        float2 f0 = __half22float2(*(__half2*)&raw.x);
        float2 f1 = __half22float2(*(__half2*)&raw.y);
        float2 f2 = __half22float2(*(__half2*)&raw.z);
        float2 f3 = __half22float2(*(__half2*)&raw.w);
        float r = rw[h];
        a0 = fmaf(f0.x, r, a0); a1 = fmaf(f0.y, r, a1);
        a2 = fmaf(f1.x, r, a2); a3 = fmaf(f1.y, r, a3);
        a4 = fmaf(f2.x, r, a4); a5 = fmaf(f2.y, r, a5);
        a6 = fmaf(f3.x, r, a6); a7 = fmaf(f3.y, r, a7);
    }
    float* dst = avg + ((long long)b * SS + q) * SS + k0;
    float4 o0 = {a0, a1, a2, a3};
    float4 o1 = {a4, a5, a6, a7};
    *(float4*)&dst[0] = o0;
    *(float4*)&dst[4] = o1;
}

// ---------------- projection GEMM (SIMT f32x2) ------------------------------------
#define PADW 132

// MODE: 0 = plain [M,N] output + bias; 1 = packed head-layout hi/lo float4 output
template<int MODE>
__global__ __launch_bounds__(256, 2)
void proj_gemm(const float* __restrict__ A, const float* __restrict__ B,
               const float* __restrict__ bias, float* __restrict__ C,
               float4* __restrict__ Cpk,
               int N, int K, int lda, int ldb, int ldc)
{
    __shared__ __align__(16) float As[16 * PADW];
    __shared__ __align__(16) float Bs[16 * PADW];

    const int rowbase = blockIdx.y * 128;
    const int colbase = blockIdx.x * 128;
    const int tid = threadIdx.x;
    const int tx = tid & 15, ty = tid >> 4;
    const int row0 = ty * 8, col0 = tx * 8;

    float regA[8], regB[8];
    unsigned long long acc[8][4];
#pragma unroll
    for (int i = 0; i < 8; i++)
#pragma unroll
        for (int j = 0; j < 4; j++) acc[i][j] = 0ull;

#pragma unroll
    for (int i = 0; i < 8; i++) {
        int idx = tid + i * 256; int r = idx >> 4, kk = idx & 15;
        regA[i] = A[(long long)(rowbase + r) * lda + kk];
    }
#pragma unroll
    for (int i = 0; i < 8; i++) {
        int idx = tid + i * 256; int kk = idx >> 7, c = idx & 127;
        int col = colbase + c;
        regB[i] = (col < N) ? B[(long long)kk * ldb + col] : 0.f;
    }
#pragma unroll
    for (int i = 0; i < 8; i++) {
        int idx = tid + i * 256; int r = idx >> 4, kk = idx & 15;
        As[kk * PADW + r] = regA[i];
    }
#pragma unroll
    for (int i = 0; i < 8; i++) {
        int idx = tid + i * 256; int kk = idx >> 7, c = idx & 127;
        Bs[kk * PADW + c] = regB[i];
    }
    __syncthreads();

    for (int k0 = 16; ; k0 += 16) {
        const bool more = (k0 < K);
        if (more) {
#pragma unroll
            for (int i = 0; i < 8; i++) {
                int idx = tid + i * 256; int r = idx >> 4, kk = idx & 15;
                regA[i] = A[(long long)(rowbase + r) * lda + k0 + kk];
            }
#pragma unroll
            for (int i = 0; i < 8; i++) {
                int idx = tid + i * 256; int kk = idx >> 7, c = idx & 127;
                int col = colbase + c;
                regB[i] = (col < N) ? B[(long long)(k0 + kk) * ldb + col] : 0.f;
            }
        }
#pragma unroll
        for (int kk = 0; kk < 16; kk++) {
            float4 a0 = *(const float4*)&As[kk * PADW + row0];
            float4 a1 = *(const float4*)&As[kk * PADW + row0 + 4];
            float4 b0 = *(const float4*)&Bs[kk * PADW + col0];
            float4 b1 = *(const float4*)&Bs[kk * PADW + col0 + 4];
            float a[8] = {a0.x, a0.y, a0.z, a0.w, a1.x, a1.y, a1.z, a1.w};
            unsigned long long bp[4];
            bp[0] = pack2(b0.x, b0.y); bp[1] = pack2(b0.z, b0.w);
            bp[2] = pack2(b1.x, b1.y); bp[3] = pack2(b1.z, b1.w);
#pragma unroll
            for (int i = 0; i < 8; i++) {
                unsigned long long ap = pack2(a[i], a[i]);
#pragma unroll
                for (int j = 0; j < 4; j++) acc[i][j] = fma2(ap, bp[j], acc[i][j]);
            }
        }
        if (!more) break;
        __syncthreads();
#pragma unroll
        for (int i = 0; i < 8; i++) {
            int idx = tid + i * 256; int r = idx >> 4, kk = idx & 15;
            As[kk * PADW + r] = regA[i];
        }
#pragma unroll
        for (int i = 0; i < 8; i++) {
            int idx = tid + i * 256; int kk = idx >> 7, c = idx & 127;
            Bs[kk * PADW + c] = regB[i];
        }
        __syncthreads();
    }

#pragma unroll
    for (int i = 0; i < 8; i++) {
        int gr = rowbase + row0 + i;
        if (MODE == 1) {
            // cols col0..col0+7 = exactly one k8 group of one head
            int gcol = colbase + col0;
            int b = gr >> 11, s = gr & (SS - 1);
            int h = gcol >> 6, k8 = (gcol & 63) >> 3;
            float v[8], hv[8], lv[8];
            unpack2(acc[i][0], v[0], v[1]); unpack2(acc[i][1], v[2], v[3]);
            unpack2(acc[i][2], v[4], v[5]); unpack2(acc[i][3], v[6], v[7]);
#pragma unroll
            for (int j = 0; j < 8; j++) {
                v[j] += bias[gcol + j];
                split_tf32(v[j], hv[j], lv[j]);
            }
            long long base4 = (((long long)(b * HH + h) * SS + s) * 8 + k8) * 4;
#pragma unroll
            for (int tg = 0; tg < 4; tg++) {
                float4 o = {hv[tg], hv[tg + 4], lv[tg], lv[tg + 4]};
                Cpk[base4 + tg] = o;
            }
        } else {
#pragma unroll
            for (int j2 = 0; j2 < 4; j2 += 2) {
                int col = colbase + col0 + j2 * 2;
                if (col < N) {
                    float4 v;
                    unpack2(acc[i][j2],     v.x, v.y);
                    unpack2(acc[i][j2 + 1], v.z, v.w);
                    const float4 bb = *(const float4*)&bias[col];
                    v.x += bb.x; v.y += bb.y; v.z += bb.z; v.w += bb.w;
                    *(float4*)&C[(long long)gr * ldc + col] = v;
                }
            }
        }
    }
}

// ---------------- avg @ V (split-K partials) ---------------------------------------
__global__ __launch_bounds__(256)
void av_gemm(const float* __restrict__ avg, const float* __restrict__ V,
             float* __restrict__ part)
{
    __shared__ float As[16 * PADW];
    __shared__ float Bs[16 * 68];
    const int b = blockIdx.z;
    const int rowbase = blockIdx.y * 128;
    const int k0base = blockIdx.x * 256;
    const float* Ap = avg + ((long long)b * SS + rowbase) * SS;
    const float* Vp = V + (long long)b * SS * DK;
    const int tid = threadIdx.x;
    const int tx = tid & 15, ty = tid >> 4;

    float acc[8][4];
#pragma unroll
    for (int i = 0; i < 8; i++)
#pragma unroll
        for (int j = 0; j < 4; j++) acc[i][j] = 0.f;

    for (int kc = 0; kc < 256; kc += 16) {
        const int k0 = k0base + kc;
#pragma unroll
        for (int i = 0; i < 8; i++) {
            int idx = tid + i * 256; int r = idx >> 4, kk = idx & 15;
            As[kk * PADW + r] = Ap[(long long)r * SS + k0 + kk];
        }
#pragma unroll
        for (int i = 0; i < 4; i++) {
            int idx = tid + i * 256; int kk = idx >> 6, cc = idx & 63;
            Bs[kk * 68 + cc] = Vp[(long long)(k0 + kk) * DK + cc];
        }
        __syncthreads();
#pragma unroll
        for (int kk = 0; kk < 16; kk++) {
            float a[8];
#pragma unroll
            for (int i = 0; i < 8; i++) a[i] = As[kk * PADW + ty * 8 + i];
            float4 bv = *(const float4*)&Bs[kk * 68 + tx * 4];
#pragma unroll
            for (int i = 0; i < 8; i++) {
                acc[i][0] = fmaf(a[i], bv.x, acc[i][0]);
                acc[i][1] = fmaf(a[i], bv.y, acc[i][1]);
                acc[i][2] = fmaf(a[i], bv.z, acc[i][2]);
                acc[i][3] = fmaf(a[i], bv.w, acc[i][3]);
            }
        }
        __syncthreads();
    }
    float* P = part + ((long long)(blockIdx.x * BB + b) * SS + rowbase) * DK;
#pragma unroll
    for (int i = 0; i < 8; i++) {
        float4 v = {acc[i][0], acc[i][1], acc[i][2], acc[i][3]};
        *(float4*)&P[(long long)(ty * 8 + i) * DK + tx * 4] = v;
    }
}

__global__ __launch_bounds__(256)
void av_reduce(const float* __restrict__ part, float* __restrict__ Ao)
{
    int i = blockIdx.x * 256 + threadIdx.x;
    float s = 0.f;
#pragma unroll
    for (int t = 0; t < 8; t++) s += part[(long long)t * (BB * SS * DK) + i];
    Ao[i] = s;
}

// ---------------- launch -------------------------------------------------------------
extern "C" void kernel_launch(void* const* d_in, const int* in_sizes, int n_in,
                              void* d_out, int out_size)
{
    const float* query = (const float*)d_in[0];
    const float* key_  = (const float*)d_in[1];
    const float* value = (const float*)d_in[2];
    const float* Wq    = (const float*)d_in[3];
    const float* bq    = (const float*)d_in[4];
    const float* Wk    = (const float*)d_in[5];
    const float* bk    = (const float*)d_in[6];
    const float* Wv    = (const float*)d_in[7];
    const float* bv    = (const float*)d_in[8];
    const float* Wo    = (const float*)d_in[9];
    const float* bo    = (const float*)d_in[10];

    float* out_main = (float*)d_out;                 // [B,S,DM]
    float* out_avg  = out_main + (size_t)ROWS * DM;  // [B,S,S]

    float4 *Qpk, *Kpk;
    __half* Esc;
    float *Vp, *Lp, *Rv, *Ao, *Av;
    cudaGetSymbolAddress((void**)&Qpk, g_Qpk);
    cudaGetSymbolAddress((void**)&Kpk, g_Kpk);
    cudaGetSymbolAddress((void**)&Vp, g_Vp);
    cudaGetSymbolAddress((void**)&Esc, g_escore);
    cudaGetSymbolAddress((void**)&Lp, g_lpart);
    cudaGetSymbolAddress((void**)&Rv, g_rinv);
    cudaGetSymbolAddress((void**)&Ao, g_ao);
    cudaGetSymbolAddress((void**)&Av, g_avpart);

    // Q tile 256x32 f4 + K tile 128x32 f4 + rowsum 256x4 f32
    const int smem1 = (256 + 128) * 32 * 16 + 256 * 4 * 4;   // 200704 B
    cudaFuncSetAttribute(mma_pass1, cudaFuncAttributeMaxDynamicSharedMemorySize, smem1);

    dim3 blk(256);

    // 1-2) Q/K projections -> packed head-layout tf32 hi/lo
    proj_gemm<1><<<dim3(8, 32, 1), blk>>>(query, Wq, bq, nullptr, Qpk, DM, DM, DM, DM, 0);
    proj_gemm<1><<<dim3(8, 32, 1), blk>>>(key_, Wk, bk, nullptr, Kpk, DM, DM, DM, DM, 0);

    // 3) V projection
    proj_gemm<0><<<dim3(1, 32, 1), blk>>>(value, Wv, bv, Vp, nullptr, DK, DM, DM, DK, DK);

    // 4) pass1: tf32 mma.sync scores (256x128 tiles) -> fp16 exp + sumexp partials
    mma_pass1<<<dim3(16, 8, BB * HH), 512, smem1>>>(Qpk, Kpk, Esc, Lp);

    // 5) combine partials -> 1/l
    combine_kernel<<<dim3(BB * HH * SS / 256, 1, 1), blk>>>(Lp, Rv);

    // 6) head-averaged attention (fp16 streaming MAC) -> second output
    avg_kernel<<<dim3(SS, BB, 1), blk>>>(Esc, Rv, out_avg);

    // 7) attn_output = avg @ V (split-K=8)
    av_gemm<<<dim3(8, 16, BB), blk>>>(out_avg, Vp, Av);
    av_reduce<<<dim3(BB * SS * DK / 256, 1, 1), blk>>>(Av, Ao);

    // 8) output = attn_output @ Wo + bo
    proj_gemm<0><<<dim3(8, 32, 1), blk>>>(Ao, Wo, bo, out_main, nullptr, DM, DK, DK, DM, DM);
}

// round 10
// speedup vs baseline: 1.2684x; 1.1479x over previous
#include <cuda_runtime.h>
#include <cuda_fp16.h>
#include <cstdint>

#define BB 2
#define SS 2048
#define HH 16
#define DK 64
#define DM 1024
#define ROWS (BB*SS)          // 4096

// ---------------- scratch -----------------------------------------------------
// packed Q/K: uint4 per (bh, s, k16, tig) = {hi(2t,2t+1), mid(2t,2t+1), hi(2t+8,2t+9), mid(2t+8,2t+9)}
// (bf16 pairs; 16 uint4 per row)
__device__ uint4 g_Qpk[(size_t)BB*HH*SS*16];
__device__ uint4 g_Kpk[(size_t)BB*HH*SS*16];
__device__ float g_Vp[(size_t)ROWS*DK];
__device__ __half g_escore[(size_t)BB*HH*SS*SS];  // exp(s/8) fp16 (268 MB)
__device__ float g_lpart[(size_t)BB*HH*16*SS];    // per (bh, ktile, q) partial sumexp
__device__ float g_rinv[(size_t)BB*HH*SS];        // 1 / l
__device__ float g_ao[(size_t)ROWS*DK];           // attn_output
__device__ float g_avpart[(size_t)8*BB*SS*DK];    // split-K partials for avg@V

// ---------------- helpers -------------------------------------------------------
__device__ __forceinline__ float fast_exp(float x) {
    x = fmaxf(x, -87.0f);
    float t = fmaf(x, 1.4426950408889634f, 12582912.0f);
    float n = t - 12582912.0f;
    float f = fmaf(x, 1.4426950408889634f, -n);
    float p = 1.5403530394e-4f;
    p = fmaf(p, f, 1.3333558146e-3f);
    p = fmaf(p, f, 9.6178371906e-3f);
    p = fmaf(p, f, 5.5502813330e-2f);
    p = fmaf(p, f, 2.4022650695e-1f);
    p = fmaf(p, f, 6.9314718056e-1f);
    p = fmaf(p, f, 1.0f);
    return p * __int_as_float(((int)n + 127) << 23);
}

__device__ __forceinline__ unsigned long long pack2(float lo, float hi) {
    unsigned long long r;
    asm("mov.b64 %0, {%1, %2};" : "=l"(r) : "f"(lo), "f"(hi));
    return r;
}
__device__ __forceinline__ void unpack2(unsigned long long v, float& lo, float& hi) {
    asm("mov.b64 {%0, %1}, %2;" : "=f"(lo), "=f"(hi) : "l"(v));
}
__device__ __forceinline__ unsigned long long fma2(unsigned long long a,
                                                   unsigned long long b,
                                                   unsigned long long c) {
    unsigned long long d;
    asm("fma.rn.f32x2 %0, %1, %2, %3;" : "=l"(d) : "l"(a), "l"(b), "l"(c));
    return d;
}

// bf16x2 pack: result = {lo half = lo, hi half = hi}
__device__ __forceinline__ uint32_t bf16pack(float lo, float hi) {
    uint32_t r;
    asm("cvt.rn.bf16x2.f32 %0, %1, %2;" : "=r"(r) : "f"(hi), "f"(lo));
    return r;
}

__device__ __forceinline__ void mma16(float* c, const uint32_t* a, const uint32_t* b) {
    asm volatile("mma.sync.aligned.m16n8k16.row.col.f32.bf16.bf16.f32 "
        "{%0,%1,%2,%3}, {%4,%5,%6,%7}, {%8,%9}, {%0,%1,%2,%3};"
        : "+f"(c[0]), "+f"(c[1]), "+f"(c[2]), "+f"(c[3])
        : "r"(a[0]), "r"(a[1]), "r"(a[2]), "r"(a[3]), "r"(b[0]), "r"(b[1]));
}

// XOR swizzle on uint4 index (row parity) -> conflict-free LDS.128/STS.128
#define FSWZ(r, f) ((f) ^ (((r) & 1) << 2))

// ---------------- pass 1: 256x128 tile, bf16x2-split MMA -> fp16 exp + sumexp ----
__global__ __launch_bounds__(512, 1)
void mma_pass1(const uint4* __restrict__ Qpk, const uint4* __restrict__ Kpk,
               __half* __restrict__ Esc, float* __restrict__ lpart)
{
    extern __shared__ uint4 smq[];
    uint4* Qs = smq;                         // [256][16]
    uint4* Ks = Qs + 256 * 16;               // [128][16]
    float* rowsum = (float*)(Ks + 128 * 16); // [256][4]

    const int tid = threadIdx.x;
    const int kt = blockIdx.x, qt = blockIdx.y, bh = blockIdx.z;
    const long long qbase = ((long long)bh * SS + qt * 256) * 16;   // uint4 units
    const long long kbase = ((long long)bh * SS + kt * 128) * 16;

#pragma unroll
    for (int i = 0; i < 8; i++) {
        int idx = tid + i * 512;             // 0..4095
        int r = idx >> 4, f = idx & 15;
        Qs[r * 16 + FSWZ(r, f)] = Qpk[qbase + r * 16 + f];
    }
#pragma unroll
    for (int i = 0; i < 4; i++) {
        int idx = tid + i * 512;             // 0..2047
        int r = idx >> 4, f = idx & 15;
        Ks[r * 16 + FSWZ(r, f)] = Kpk[kbase + r * 16 + f];
    }
    __syncthreads();

    const int wid = tid >> 5, lane = tid & 31;
    const int wm = wid >> 2, wn = wid & 3;        // 4x4 warp grid
    const int gid = lane >> 2, tig = lane & 3;

    float acc[4][4][4];
#pragma unroll
    for (int mt = 0; mt < 4; mt++)
#pragma unroll
        for (int nt = 0; nt < 4; nt++)
#pragma unroll
            for (int c = 0; c < 4; c++) acc[mt][nt][c] = 0.f;

#pragma unroll
    for (int k16 = 0; k16 < 4; k16++) {
        const int f = k16 * 4 + tig;
        uint32_t bhf[4][2], bmf[4][2];
#pragma unroll
        for (int nt = 0; nt < 4; nt++) {
            int row = wn * 32 + nt * 8 + gid;
            uint4 kv = Ks[row * 16 + FSWZ(row, f)];
            bhf[nt][0] = kv.x; bhf[nt][1] = kv.z;
            bmf[nt][0] = kv.y; bmf[nt][1] = kv.w;
        }
#pragma unroll
        for (int mt = 0; mt < 4; mt++) {
            int r0 = wm * 64 + mt * 16 + gid;
            int r1 = r0 + 8;
            uint4 qa = Qs[r0 * 16 + FSWZ(r0, f)];
            uint4 qb = Qs[r1 * 16 + FSWZ(r1, f)];
            uint32_t ah[4], am[4];
            ah[0] = qa.x; ah[1] = qb.x; ah[2] = qa.z; ah[3] = qb.z;
            am[0] = qa.y; am[1] = qb.y; am[2] = qa.w; am[3] = qb.w;
#pragma unroll
            for (int nt = 0; nt < 4; nt++) {
                mma16(acc[mt][nt], ah, bhf[nt]);   // hi*hi
                mma16(acc[mt][nt], ah, bmf[nt]);   // hi*mid
                mma16(acc[mt][nt], am, bhf[nt]);   // mid*hi
            }
        }
    }

    // scale -> exp -> store fp16 + per-row fp32 partial sumexp
    __half* Cp = Esc + ((long long)bh * SS + qt * 256) * SS + kt * 128;
    float p[4][2];
#pragma unroll
    for (int mt = 0; mt < 4; mt++) { p[mt][0] = 0.f; p[mt][1] = 0.f; }
#pragma unroll
    for (int mt = 0; mt < 4; mt++)
#pragma unroll
        for (int nt = 0; nt < 4; nt++) {
            float e0 = fast_exp(acc[mt][nt][0] * 0.125f);
            float e1 = fast_exp(acc[mt][nt][1] * 0.125f);
            float e2 = fast_exp(acc[mt][nt][2] * 0.125f);
            float e3 = fast_exp(acc[mt][nt][3] * 0.125f);
            int r0 = wm * 64 + mt * 16 + gid;
            int col = wn * 32 + nt * 8 + tig * 2;
            *(__half2*)&Cp[(long long)r0 * SS + col] = __floats2half2_rn(e0, e1);
            *(__half2*)&Cp[(long long)(r0 + 8) * SS + col] = __floats2half2_rn(e2, e3);
            p[mt][0] += e0 + e1;
            p[mt][1] += e2 + e3;
        }
#pragma unroll
    for (int o = 1; o <= 2; o <<= 1)
#pragma unroll
        for (int mt = 0; mt < 4; mt++) {
            p[mt][0] += __shfl_xor_sync(0xffffffffu, p[mt][0], o);
            p[mt][1] += __shfl_xor_sync(0xffffffffu, p[mt][1], o);
        }
    if (tig == 0) {
#pragma unroll
        for (int mt = 0; mt < 4; mt++)
#pragma unroll
            for (int j = 0; j < 2; j++) {
                int r = wm * 64 + mt * 16 + j * 8 + gid;
                rowsum[r * 4 + wn] = p[mt][j];
            }
    }
    __syncthreads();
    if (tid < 256) {
        float l = rowsum[tid * 4] + rowsum[tid * 4 + 1]
                + rowsum[tid * 4 + 2] + rowsum[tid * 4 + 3];
        lpart[(long long)(bh * 16 + kt) * SS + qt * 256 + tid] = l;
    }
}

// ---------------- combine: rinv = 1 / sum of partials ----------------------------
__global__ __launch_bounds__(256)
void combine_kernel(const float* __restrict__ lpart, float* __restrict__ rinv)
{
    int rowg = blockIdx.x * 256 + threadIdx.x;     // bh*2048 + q
    int bh = rowg >> 11, q = rowg & (SS - 1);
    float l = 0.f;
#pragma unroll
    for (int t = 0; t < 16; t++)
        l += lpart[(long long)(bh * 16 + t) * SS + q];
    rinv[rowg] = 1.0f / l;
}

// ---------------- head-averaged attention (fp16 stream MAC) ----------------------
__global__ __launch_bounds__(256)
void avg_kernel(const __half* __restrict__ Esc, const float* __restrict__ rinv,
                float* __restrict__ avg)
{
    const int q = blockIdx.x;
    const int b = blockIdx.y;
    const int tid = threadIdx.x;

    __shared__ float rw[HH];
    if (tid < HH) rw[tid] = rinv[((long long)(b * HH + tid) << 11) + q] * (1.0f / HH);
    __syncthreads();

    const __half* base = Esc + ((long long)(b * HH) * SS + q) * SS;
    const int k0 = tid * 8;                       // 256 thr * 8 = 2048
    float a0 = 0.f, a1 = 0.f, a2 = 0.f, a3 = 0.f;
    float a4 = 0.f, a5 = 0.f, a6 = 0.f, a7 = 0.f;
#pragma unroll
    for (int h = 0; h < HH; h++) {
        uint4 raw = *(const uint4*)(base + (long long)h * SS * SS + k0);
        float2 f0 = __half22float2(*(__half2*)&raw.x);
        float2 f1 = __half22float2(*(__half2*)&raw.y);
        float2 f2 = __half22float2(*(__half2*)&raw.z);
        float2 f3 = __half22float2(*(__half2*)&raw.w);
        float r = rw[h];
        a0 = fmaf(f0.x, r, a0); a1 = fmaf(f0.y, r, a1);
        a2 = fmaf(f1.x, r, a2); a3 = fmaf(f1.y, r, a3);
        a4 = fmaf(f2.x, r, a4); a5 = fmaf(f2.y, r, a5);
        a6 = fmaf(f3.x, r, a6); a7 = fmaf(f3.y, r, a7);
    }
    float* dst = avg + ((long long)b * SS + q) * SS + k0;
    float4 o0 = {a0, a1, a2, a3};
    float4 o1 = {a4, a5, a6, a7};
    *(float4*)&dst[0] = o0;
    *(float4*)&dst[4] = o1;
}

// ---------------- projection GEMM (SIMT f32x2) ------------------------------------
#define PADW 132

// MODE: 0 = plain [M,N] output + bias; 1 = packed head-layout bf16 hi/mid output
template<int MODE>
__global__ __launch_bounds__(256, 2)
void proj_gemm(const float* __restrict__ A, const float* __restrict__ B,
               const float* __restrict__ bias, float* __restrict__ C,
               uint4* __restrict__ Cpk,
               int N, int K, int lda, int ldb, int ldc)
{
    __shared__ __align__(16) float As[16 * PADW];
    __shared__ __align__(16) float Bs[16 * PADW];

    const int rowbase = blockIdx.y * 128;
    const int colbase = blockIdx.x * 128;
    const int tid = threadIdx.x;
    const int tx = tid & 15, ty = tid >> 4;
    const int row0 = ty * 8, col0 = tx * 8;

    float regA[8], regB[8];
    unsigned long long acc[8][4];
#pragma unroll
    for (int i = 0; i < 8; i++)
#pragma unroll
        for (int j = 0; j < 4; j++) acc[i][j] = 0ull;

#pragma unroll
    for (int i = 0; i < 8; i++) {
        int idx = tid + i * 256; int r = idx >> 4, kk = idx & 15;
        regA[i] = A[(long long)(rowbase + r) * lda + kk];
    }
#pragma unroll
    for (int i = 0; i < 8; i++) {
        int idx = tid + i * 256; int kk = idx >> 7, c = idx & 127;
        int col = colbase + c;
        regB[i] = (col < N) ? B[(long long)kk * ldb + col] : 0.f;
    }
#pragma unroll
    for (int i = 0; i < 8; i++) {
        int idx = tid + i * 256; int r = idx >> 4, kk = idx & 15;
        As[kk * PADW + r] = regA[i];
    }
#pragma unroll
    for (int i = 0; i < 8; i++) {
        int idx = tid + i * 256; int kk = idx >> 7, c = idx & 127;
        Bs[kk * PADW + c] = regB[i];
    }
    __syncthreads();

    for (int k0 = 16; ; k0 += 16) {
        const bool more = (k0 < K);
        if (more) {
#pragma unroll
            for (int i = 0; i < 8; i++) {
                int idx = tid + i * 256; int r = idx >> 4, kk = idx & 15;
                regA[i] = A[(long long)(rowbase + r) * lda + k0 + kk];
            }
#pragma unroll
            for (int i = 0; i < 8; i++) {
                int idx = tid + i * 256; int kk = idx >> 7, c = idx & 127;
                int col = colbase + c;
                regB[i] = (col < N) ? B[(long long)(k0 + kk) * ldb + col] : 0.f;
            }
        }
#pragma unroll
        for (int kk = 0; kk < 16; kk++) {
            float4 a0 = *(const float4*)&As[kk * PADW + row0];
            float4 a1 = *(const float4*)&As[kk * PADW + row0 + 4];
            float4 b0 = *(const float4*)&Bs[kk * PADW + col0];
            float4 b1 = *(const float4*)&Bs[kk * PADW + col0 + 4];
            float a[8] = {a0.x, a0.y, a0.z, a0.w, a1.x, a1.y, a1.z, a1.w};
            unsigned long long bp[4];
            bp[0] = pack2(b0.x, b0.y); bp[1] = pack2(b0.z, b0.w);
            bp[2] = pack2(b1.x, b1.y); bp[3] = pack2(b1.z, b1.w);
#pragma unroll
            for (int i = 0; i < 8; i++) {
                unsigned long long ap = pack2(a[i], a[i]);
#pragma unroll
                for (int j = 0; j < 4; j++) acc[i][j] = fma2(ap, bp[j], acc[i][j]);
            }
        }
        if (!more) break;
        __syncthreads();
#pragma unroll
        for (int i = 0; i < 8; i++) {
            int idx = tid + i * 256; int r = idx >> 4, kk = idx & 15;
            As[kk * PADW + r] = regA[i];
        }
#pragma unroll
        for (int i = 0; i < 8; i++) {
            int idx = tid + i * 256; int kk = idx >> 7, c = idx & 127;
            Bs[kk * PADW + c] = regB[i];
        }
        __syncthreads();
    }

#pragma unroll
    for (int i = 0; i < 8; i++) {
        int gr = rowbase + row0 + i;
        if (MODE == 1) {
            // cols gcol..gcol+7 = one k8 half-group of one head
            int gcol = colbase + col0;
            int b = gr >> 11, s = gr & (SS - 1);
            int h = gcol >> 6;
            int hc = gcol & 63;
            int k16 = hc >> 4;
            int half = (hc >> 3) & 1;
            float v[8];
            unpack2(acc[i][0], v[0], v[1]); unpack2(acc[i][1], v[2], v[3]);
            unpack2(acc[i][2], v[4], v[5]); unpack2(acc[i][3], v[6], v[7]);
#pragma unroll
            for (int j = 0; j < 8; j++) v[j] += bias[gcol + j];

            long long rowbase4 = ((long long)(b * HH + h) * SS + s) * 16;
            uint2* dst = (uint2*)(Cpk + rowbase4 + k16 * 4);
#pragma unroll
            for (int p = 0; p < 4; p++) {
                uint32_t hp = bf16pack(v[2 * p], v[2 * p + 1]);
                float hf0 = __uint_as_float(hp << 16);
                float hf1 = __uint_as_float(hp & 0xffff0000u);
                uint32_t mp = bf16pack(v[2 * p] - hf0, v[2 * p + 1] - hf1);
                uint2 o = {hp, mp};
                dst[p * 2 + half] = o;
            }
        } else {
#pragma unroll
            for (int j2 = 0; j2 < 4; j2 += 2) {
                int col = colbase + col0 + j2 * 2;
                if (col < N) {
                    float4 v;
                    unpack2(acc[i][j2],     v.x, v.y);
                    unpack2(acc[i][j2 + 1], v.z, v.w);
                    const float4 bb = *(const float4*)&bias[col];
                    v.x += bb.x; v.y += bb.y; v.z += bb.z; v.w += bb.w;
                    *(float4*)&C[(long long)gr * ldc + col] = v;
                }
            }
        }
    }
}

// ---------------- avg @ V (split-K partials) ---------------------------------------
__global__ __launch_bounds__(256)
void av_gemm(const float* __restrict__ avg, const float* __restrict__ V,
             float* __restrict__ part)
{
    __shared__ float As[16 * PADW];
    __shared__ float Bs[16 * 68];
    const int b = blockIdx.z;
    const int rowbase = blockIdx.y * 128;
    const int k0base = blockIdx.x * 256;
    const float* Ap = avg + ((long long)b * SS + rowbase) * SS;
    const float* Vp = V + (long long)b * SS * DK;
    const int tid = threadIdx.x;
    const int tx = tid & 15, ty = tid >> 4;

    float acc[8][4];
#pragma unroll
    for (int i = 0; i < 8; i++)
#pragma unroll
        for (int j = 0; j < 4; j++) acc[i][j] = 0.f;

    for (int kc = 0; kc < 256; kc += 16) {
        const int k0 = k0base + kc;
#pragma unroll
        for (int i = 0; i < 8; i++) {
            int idx = tid + i * 256; int r = idx >> 4, kk = idx & 15;
            As[kk * PADW + r] = Ap[(long long)r * SS + k0 + kk];
        }
#pragma unroll
        for (int i = 0; i < 4; i++) {
            int idx = tid + i * 256; int kk = idx >> 6, cc = idx & 63;
            Bs[kk * 68 + cc] = Vp[(long long)(k0 + kk) * DK + cc];
        }
        __syncthreads();
#pragma unroll
        for (int kk = 0; kk < 16; kk++) {
            float a[8];
#pragma unroll
            for (int i = 0; i < 8; i++) a[i] = As[kk * PADW + ty * 8 + i];
            float4 bv = *(const float4*)&Bs[kk * 68 + tx * 4];
#pragma unroll
            for (int i = 0; i < 8; i++) {
                acc[i][0] = fmaf(a[i], bv.x, acc[i][0]);
                acc[i][1] = fmaf(a[i], bv.y, acc[i][1]);
                acc[i][2] = fmaf(a[i], bv.z, acc[i][2]);
                acc[i][3] = fmaf(a[i], bv.w, acc[i][3]);
            }
        }
        __syncthreads();
    }
    float* P = part + ((long long)(blockIdx.x * BB + b) * SS + rowbase) * DK;
#pragma unroll
    for (int i = 0; i < 8; i++) {
        float4 v = {acc[i][0], acc[i][1], acc[i][2], acc[i][3]};
        *(float4*)&P[(long long)(ty * 8 + i) * DK + tx * 4] = v;
    }
}

__global__ __launch_bounds__(256)
void av_reduce(const float* __restrict__ part, float* __restrict__ Ao)
{
    int i = blockIdx.x * 256 + threadIdx.x;
    float s = 0.f;
#pragma unroll
    for (int t = 0; t < 8; t++) s += part[(long long)t * (BB * SS * DK) + i];
    Ao[i] = s;
}

// ---------------- launch -------------------------------------------------------------
extern "C" void kernel_launch(void* const* d_in, const int* in_sizes, int n_in,
                              void* d_out, int out_size)
{
    const float* query = (const float*)d_in[0];
    const float* key_  = (const float*)d_in[1];
    const float* value = (const float*)d_in[2];
    const float* Wq    = (const float*)d_in[3];
    const float* bq    = (const float*)d_in[4];
    const float* Wk    = (const float*)d_in[5];
    const float* bk    = (const float*)d_in[6];
    const float* Wv    = (const float*)d_in[7];
    const float* bv    = (const float*)d_in[8];
    const float* Wo    = (const float*)d_in[9];
    const float* bo    = (const float*)d_in[10];

    float* out_main = (float*)d_out;                 // [B,S,DM]
    float* out_avg  = out_main + (size_t)ROWS * DM;  // [B,S,S]

    uint4 *Qpk, *Kpk;
    __half* Esc;
    float *Vp, *Lp, *Rv, *Ao, *Av;
    cudaGetSymbolAddress((void**)&Qpk, g_Qpk);
    cudaGetSymbolAddress((void**)&Kpk, g_Kpk);
    cudaGetSymbolAddress((void**)&Vp, g_Vp);
    cudaGetSymbolAddress((void**)&Esc, g_escore);
    cudaGetSymbolAddress((void**)&Lp, g_lpart);
    cudaGetSymbolAddress((void**)&Rv, g_rinv);
    cudaGetSymbolAddress((void**)&Ao, g_ao);
    cudaGetSymbolAddress((void**)&Av, g_avpart);

    // Q tile 256x16 u4 + K tile 128x16 u4 + rowsum 256x4 f32
    const int smem1 = (256 + 128) * 16 * 16 + 256 * 4 * 4;   // 102400 B
    cudaFuncSetAttribute(mma_pass1, cudaFuncAttributeMaxDynamicSharedMemorySize, smem1);

    dim3 blk(256);

    // 1-2) Q/K projections -> packed head-layout bf16 hi/mid
    proj_gemm<1><<<dim3(8, 32, 1), blk>>>(query, Wq, bq, nullptr, Qpk, DM, DM, DM, DM, 0);
    proj_gemm<1><<<dim3(8, 32, 1), blk>>>(key_, Wk, bk, nullptr, Kpk, DM, DM, DM, DM, 0);

    // 3) V projection
    proj_gemm<0><<<dim3(1, 32, 1), blk>>>(value, Wv, bv, Vp, nullptr, DK, DM, DM, DK, DK);

    // 4) pass1: bf16x2-split mma.sync scores (256x128 tiles) -> fp16 exp + partials
    mma_pass1<<<dim3(16, 8, BB * HH), 512, smem1>>>(Qpk, Kpk, Esc, Lp);

    // 5) combine partials -> 1/l
    combine_kernel<<<dim3(BB * HH * SS / 256, 1, 1), blk>>>(Lp, Rv);

    // 6) head-averaged attention (fp16 streaming MAC) -> second output
    avg_kernel<<<dim3(SS, BB, 1), blk>>>(Esc, Rv, out_avg);

    // 7) attn_output = avg @ V (split-K=8)
    av_gemm<<<dim3(8, 16, BB), blk>>>(out_avg, Vp, Av);
    av_reduce<<<dim3(BB * SS * DK / 256, 1, 1), blk>>>(Av, Ao);

    // 8) output = attn_output @ Wo + bo
    proj_gemm<0><<<dim3(8, 32, 1), blk>>>(Ao, Wo, bo, out_main, nullptr, DM, DK, DK, DM, DM);
}

// round 11
// speedup vs baseline: 1.6177x; 1.2754x over previous
#include <cuda_runtime.h>
#include <cuda_fp16.h>
#include <cstdint>

#define BB 2
#define SS 2048
#define HH 16
#define DK 64
#define DM 1024
#define ROWS (BB*SS)          // 4096

// ---------------- scratch -----------------------------------------------------
// packed bf16 hi/mid: uint4 per (row, k16, tig) = {hi(2t,2t+1), mid(2t,2t+1), hi(+8,+9), mid(+8,+9)}
__device__ uint4 g_Xq[(size_t)ROWS*256];          // split query  [4096][256]
__device__ uint4 g_Xk[(size_t)ROWS*256];          // split key
__device__ uint4 g_Wtq[(size_t)DM*256];           // split Wq^T   [1024][256]
__device__ uint4 g_Wtk[(size_t)DM*256];
__device__ uint4 g_Qpk[(size_t)BB*HH*SS*16];      // head-layout packed Q
__device__ uint4 g_Kpk[(size_t)BB*HH*SS*16];
__device__ float g_Vp[(size_t)ROWS*DK];
__device__ __half g_escore[(size_t)BB*HH*SS*SS];  // exp(s/8) fp16 (268 MB)
__device__ float g_lpart[(size_t)BB*HH*16*SS];
__device__ float g_rinv[(size_t)BB*HH*SS];
__device__ float g_ao[(size_t)ROWS*DK];
__device__ float g_avpart[(size_t)8*BB*SS*DK];

// ---------------- helpers -------------------------------------------------------
__device__ __forceinline__ float fast_exp(float x) {
    x = fmaxf(x, -87.0f);
    float t = fmaf(x, 1.4426950408889634f, 12582912.0f);
    float n = t - 12582912.0f;
    float f = fmaf(x, 1.4426950408889634f, -n);
    float p = 1.3333558146e-3f;
    p = fmaf(p, f, 9.6178371906e-3f);
    p = fmaf(p, f, 5.5502813330e-2f);
    p = fmaf(p, f, 2.4022650695e-1f);
    p = fmaf(p, f, 6.9314718056e-1f);
    p = fmaf(p, f, 1.0f);
    return p * __int_as_float(((int)n + 127) << 23);
}

__device__ __forceinline__ unsigned long long pack2(float lo, float hi) {
    unsigned long long r;
    asm("mov.b64 %0, {%1, %2};" : "=l"(r) : "f"(lo), "f"(hi));
    return r;
}
__device__ __forceinline__ void unpack2(unsigned long long v, float& lo, float& hi) {
    asm("mov.b64 {%0, %1}, %2;" : "=f"(lo), "=f"(hi) : "l"(v));
}
__device__ __forceinline__ unsigned long long fma2(unsigned long long a,
                                                   unsigned long long b,
                                                   unsigned long long c) {
    unsigned long long d;
    asm("fma.rn.f32x2 %0, %1, %2, %3;" : "=l"(d) : "l"(a), "l"(b), "l"(c));
    return d;
}

// pack two floats to bf16x2 (first arg -> low half)
__device__ __forceinline__ uint32_t bf16pack(float lo, float hi) {
    uint32_t r;
    asm("cvt.rn.bf16x2.f32 %0, %1, %2;" : "=r"(r) : "f"(hi), "f"(lo));
    return r;
}

// hi/mid split of a float pair -> {hi-pair, mid-pair}
__device__ __forceinline__ uint2 himid(float v0, float v1) {
    uint32_t hp = bf16pack(v0, v1);
    uint32_t mp = bf16pack(v0 - __uint_as_float(hp << 16),
                           v1 - __uint_as_float(hp & 0xffff0000u));
    uint2 o = {hp, mp};
    return o;
}

__device__ __forceinline__ void mma16(float* c, const uint32_t* a, const uint32_t* b) {
    asm volatile("mma.sync.aligned.m16n8k16.row.col.f32.bf16.bf16.f32 "
        "{%0,%1,%2,%3}, {%4,%5,%6,%7}, {%8,%9}, {%0,%1,%2,%3};"
        : "+f"(c[0]), "+f"(c[1]), "+f"(c[2]), "+f"(c[3])
        : "r"(a[0]), "r"(a[1]), "r"(a[2]), "r"(a[3]), "r"(b[0]), "r"(b[1]));
}

#define FSWZ(r, f) ((f) ^ (((r) & 1) << 2))

// ---------------- input split kernels ---------------------------------------------
__global__ __launch_bounds__(256)
void split_x(const float* __restrict__ X, uint4* __restrict__ out)
{
    int g = blockIdx.x * 256 + threadIdx.x;        // 0..ROWS*256-1
    int r = g >> 8, f = g & 255;
    int k = (f >> 2) * 16 + (f & 3) * 2;
    const float* xp = X + (long long)r * DM + k;
    uint2 a = himid(xp[0], xp[1]);
    uint2 b = himid(xp[8], xp[9]);
    uint4 o = {a.x, a.y, b.x, b.y};
    out[g] = o;
}

__global__ __launch_bounds__(256)
void split_w(const float* __restrict__ W, uint4* __restrict__ out)
{
    __shared__ float ws[64][65];
    const int tid = threadIdx.x;
    const int kb = blockIdx.y * 64, nb = blockIdx.x * 64;
#pragma unroll
    for (int i = 0; i < 16; i++) {
        int idx = tid + i * 256; int kk = idx >> 6, nn = idx & 63;
        ws[kk][nn] = W[(long long)(kb + kk) * DM + nb + nn];
    }
    __syncthreads();
#pragma unroll
    for (int i = 0; i < 4; i++) {
        int idx = tid + i * 256; int nn = idx >> 4, f = idx & 15;
        int kk = (f >> 2) * 16 + (f & 3) * 2;
        uint2 a = himid(ws[kk][nn], ws[kk + 1][nn]);
        uint2 b = himid(ws[kk + 8][nn], ws[kk + 9][nn]);
        uint4 o = {a.x, a.y, b.x, b.y};
        out[(long long)(nb + nn) * 256 + (kb >> 2) + f] = o;
    }
}

// ---------------- Q/K projection via bf16-split MMA --------------------------------
// C[4096,1024] = X @ W + bias, output re-split into packed head layout.
__global__ __launch_bounds__(512, 1)
void proj_mma(const uint4* __restrict__ Xpk, const uint4* __restrict__ Wt,
              const float* __restrict__ bias, uint4* __restrict__ Cpk)
{
    extern __shared__ uint4 smq[];
    uint4* Xs = smq;                 // [256][16]
    uint4* Ws = Xs + 256 * 16;       // [128][16]

    const int tid = threadIdx.x;
    const int colbase = blockIdx.x * 128;
    const int rowbase = blockIdx.y * 256;
    const int wid = tid >> 5, lane = tid & 31;
    const int wm = wid >> 2, wn = wid & 3;
    const int gid = lane >> 2, tig = lane & 3;

    float acc[4][4][4];
#pragma unroll
    for (int mt = 0; mt < 4; mt++)
#pragma unroll
        for (int nt = 0; nt < 4; nt++)
#pragma unroll
            for (int c = 0; c < 4; c++) acc[mt][nt][c] = 0.f;

    for (int kc = 0; kc < 16; kc++) {
#pragma unroll
        for (int i = 0; i < 8; i++) {
            int idx = tid + i * 512; int r = idx >> 4, f = idx & 15;
            Xs[r * 16 + FSWZ(r, f)] = Xpk[(long long)(rowbase + r) * 256 + kc * 16 + f];
        }
#pragma unroll
        for (int i = 0; i < 4; i++) {
            int idx = tid + i * 512; int r = idx >> 4, f = idx & 15;
            Ws[r * 16 + FSWZ(r, f)] = Wt[(long long)(colbase + r) * 256 + kc * 16 + f];
        }
        __syncthreads();
#pragma unroll
        for (int k16 = 0; k16 < 4; k16++) {
            const int f = k16 * 4 + tig;
            uint32_t bhf[4][2], bmf[4][2];
#pragma unroll
            for (int nt = 0; nt < 4; nt++) {
                int row = wn * 32 + nt * 8 + gid;
                uint4 kv = Ws[row * 16 + FSWZ(row, f)];
                bhf[nt][0] = kv.x; bhf[nt][1] = kv.z;
                bmf[nt][0] = kv.y; bmf[nt][1] = kv.w;
            }
#pragma unroll
            for (int mt = 0; mt < 4; mt++) {
                int r0 = wm * 64 + mt * 16 + gid;
                int r1 = r0 + 8;
                uint4 qa = Xs[r0 * 16 + FSWZ(r0, f)];
                uint4 qb = Xs[r1 * 16 + FSWZ(r1, f)];
                uint32_t ah[4], am[4];
                ah[0] = qa.x; ah[1] = qb.x; ah[2] = qa.z; ah[3] = qb.z;
                am[0] = qa.y; am[1] = qb.y; am[2] = qa.w; am[3] = qb.w;
#pragma unroll
                for (int nt = 0; nt < 4; nt++) {
                    mma16(acc[mt][nt], ah, bhf[nt]);
                    mma16(acc[mt][nt], ah, bmf[nt]);
                    mma16(acc[mt][nt], am, bhf[nt]);
                }
            }
        }
        __syncthreads();
    }

    // epilogue: + bias, hi/mid split, packed head layout
    const int nb = colbase + wn * 32;
    const int h = nb >> 6;
    const int db = nb & 63;          // 0 or 32
#pragma unroll
    for (int ntp = 0; ntp < 2; ntp++) {
        int cb = nb + ntp * 16 + tig * 2;
        float b0 = bias[cb],     b1 = bias[cb + 1];
        float b2 = bias[cb + 8], b3 = bias[cb + 9];
        int k16o = (db >> 4) + ntp;
#pragma unroll
        for (int mt = 0; mt < 4; mt++) {
#pragma unroll
            for (int rr = 0; rr < 2; rr++) {
                int gr = rowbase + wm * 64 + mt * 16 + rr * 8 + gid;
                int b = gr >> 11, s = gr & (SS - 1);
                uint2 lo = himid(acc[mt][2 * ntp][rr * 2] + b0,
                                 acc[mt][2 * ntp][rr * 2 + 1] + b1);
                uint2 hi = himid(acc[mt][2 * ntp + 1][rr * 2] + b2,
                                 acc[mt][2 * ntp + 1][rr * 2 + 1] + b3);
                uint4 o = {lo.x, lo.y, hi.x, hi.y};
                Cpk[((long long)((b * HH + h) * SS + s)) * 16 + k16o * 4 + tig] = o;
            }
        }
    }
}

// ---------------- pass 1: 256x128 tile, bf16-split MMA -> fp16 exp + sumexp --------
__global__ __launch_bounds__(512, 1)
void mma_pass1(const uint4* __restrict__ Qpk, const uint4* __restrict__ Kpk,
               __half* __restrict__ Esc, float* __restrict__ lpart)
{
    extern __shared__ uint4 smq[];
    uint4* Qs = smq;                          // [256][16]
    uint4* Ks = Qs + 256 * 16;                // [128][16]
    float* rowsum = (float*)(smq + 384 * 16); // [256][4] at 98304 B
    __half* smh = (__half*)smq;               // epilogue staging, pitch 136 halves

    const int tid = threadIdx.x;
    const int kt = blockIdx.x, qt = blockIdx.y, bh = blockIdx.z;
    const long long qbase = ((long long)bh * SS + qt * 256) * 16;
    const long long kbase = ((long long)bh * SS + kt * 128) * 16;

#pragma unroll
    for (int i = 0; i < 8; i++) {
        int idx = tid + i * 512;
        int r = idx >> 4, f = idx & 15;
        Qs[r * 16 + FSWZ(r, f)] = Qpk[qbase + r * 16 + f];
    }
#pragma unroll
    for (int i = 0; i < 4; i++) {
        int idx = tid + i * 512;
        int r = idx >> 4, f = idx & 15;
        Ks[r * 16 + FSWZ(r, f)] = Kpk[kbase + r * 16 + f];
    }
    __syncthreads();

    const int wid = tid >> 5, lane = tid & 31;
    const int wm = wid >> 2, wn = wid & 3;
    const int gid = lane >> 2, tig = lane & 3;

    float acc[4][4][4];
#pragma unroll
    for (int mt = 0; mt < 4; mt++)
#pragma unroll
        for (int nt = 0; nt < 4; nt++)
#pragma unroll
            for (int c = 0; c < 4; c++) acc[mt][nt][c] = 0.f;

#pragma unroll
    for (int k16 = 0; k16 < 4; k16++) {
        const int f = k16 * 4 + tig;
        uint32_t bhf[4][2], bmf[4][2];
#pragma unroll
        for (int nt = 0; nt < 4; nt++) {
            int row = wn * 32 + nt * 8 + gid;
            uint4 kv = Ks[row * 16 + FSWZ(row, f)];
            bhf[nt][0] = kv.x; bhf[nt][1] = kv.z;
            bmf[nt][0] = kv.y; bmf[nt][1] = kv.w;
        }
#pragma unroll
        for (int mt = 0; mt < 4; mt++) {
            int r0 = wm * 64 + mt * 16 + gid;
            int r1 = r0 + 8;
            uint4 qa = Qs[r0 * 16 + FSWZ(r0, f)];
            uint4 qb = Qs[r1 * 16 + FSWZ(r1, f)];
            uint32_t ah[4], am[4];
            ah[0] = qa.x; ah[1] = qb.x; ah[2] = qa.z; ah[3] = qb.z;
            am[0] = qa.y; am[1] = qb.y; am[2] = qa.w; am[3] = qb.w;
#pragma unroll
            for (int nt = 0; nt < 4; nt++) {
                mma16(acc[mt][nt], ah, bhf[nt]);
                mma16(acc[mt][nt], ah, bmf[nt]);
                mma16(acc[mt][nt], am, bhf[nt]);
            }
        }
    }

    // exp in place + per-row partial sums
    float p[4][2];
#pragma unroll
    for (int mt = 0; mt < 4; mt++) { p[mt][0] = 0.f; p[mt][1] = 0.f; }
#pragma unroll
    for (int mt = 0; mt < 4; mt++)
#pragma unroll
        for (int nt = 0; nt < 4; nt++) {
            acc[mt][nt][0] = fast_exp(acc[mt][nt][0] * 0.125f);
            acc[mt][nt][1] = fast_exp(acc[mt][nt][1] * 0.125f);
            acc[mt][nt][2] = fast_exp(acc[mt][nt][2] * 0.125f);
            acc[mt][nt][3] = fast_exp(acc[mt][nt][3] * 0.125f);
            p[mt][0] += acc[mt][nt][0] + acc[mt][nt][1];
            p[mt][1] += acc[mt][nt][2] + acc[mt][nt][3];
        }
#pragma unroll
    for (int o = 1; o <= 2; o <<= 1)
#pragma unroll
        for (int mt = 0; mt < 4; mt++) {
            p[mt][0] += __shfl_xor_sync(0xffffffffu, p[mt][0], o);
            p[mt][1] += __shfl_xor_sync(0xffffffffu, p[mt][1], o);
        }
    if (tig == 0) {
#pragma unroll
        for (int mt = 0; mt < 4; mt++)
#pragma unroll
            for (int j = 0; j < 2; j++) {
                int r = wm * 64 + mt * 16 + j * 8 + gid;
                rowsum[r * 4 + wn] = p[mt][j];
            }
    }
    __syncthreads();   // mainloop smem reads done; rowsum visible

    if (tid < 256) {
        float l = rowsum[tid * 4] + rowsum[tid * 4 + 1]
                + rowsum[tid * 4 + 2] + rowsum[tid * 4 + 3];
        lpart[(long long)(bh * 16 + kt) * SS + qt * 256 + tid] = l;
    }

    // stage fp16 tile in smem (pitch 136 halves, conflict-free), then coalesced copy
#pragma unroll
    for (int mt = 0; mt < 4; mt++) {
        int r0 = wm * 64 + mt * 16 + gid;
#pragma unroll
        for (int nt = 0; nt < 4; nt++) {
            int col = wn * 32 + nt * 8 + tig * 2;
            *(__half2*)&smh[r0 * 136 + col] =
                __floats2half2_rn(acc[mt][nt][0], acc[mt][nt][1]);
            *(__half2*)&smh[(r0 + 8) * 136 + col] =
                __floats2half2_rn(acc[mt][nt][2], acc[mt][nt][3]);
        }
    }
    __syncthreads();

    __half* Cp = Esc + ((long long)bh * SS + qt * 256) * SS + kt * 128;
    const int u = tid & 15;
    const int rbase = tid >> 4;              // 0..31
#pragma unroll
    for (int i = 0; i < 8; i++) {
        int row = i * 32 + rbase;
        uint4 v = *(uint4*)&smh[row * 136 + u * 8];
        *(uint4*)&Cp[(long long)row * SS + u * 8] = v;
    }
}

// ---------------- combine: rinv = 1 / sum of partials ----------------------------
__global__ __launch_bounds__(256)
void combine_kernel(const float* __restrict__ lpart, float* __restrict__ rinv)
{
    int rowg = blockIdx.x * 256 + threadIdx.x;
    int bh = rowg >> 11, q = rowg & (SS - 1);
    float l = 0.f;
#pragma unroll
    for (int t = 0; t < 16; t++)
        l += lpart[(long long)(bh * 16 + t) * SS + q];
    rinv[rowg] = 1.0f / l;
}

// ---------------- head-averaged attention (fp16 stream MAC) ----------------------
__global__ __launch_bounds__(256)
void avg_kernel(const __half* __restrict__ Esc, const float* __restrict__ rinv,
                float* __restrict__ avg)
{
    const int q = blockIdx.x;
    const int b = blockIdx.y;
    const int tid = threadIdx.x;

    __shared__ float rw[HH];
    if (tid < HH) rw[tid] = rinv[((long long)(b * HH + tid) << 11) + q] * (1.0f / HH);
    __syncthreads();

    const __half* base = Esc + ((long long)(b * HH) * SS + q) * SS;
    const int k0 = tid * 8;
    float a0 = 0.f, a1 = 0.f, a2 = 0.f, a3 = 0.f;
    float a4 = 0.f, a5 = 0.f, a6 = 0.f, a7 = 0.f;
#pragma unroll
    for (int h = 0; h < HH; h++) {
        uint4 raw = *(const uint4*)(base + (long long)h * SS * SS + k0);
        float2 f0 = __half22float2(*(__half2*)&raw.x);
        float2 f1 = __half22float2(*(__half2*)&raw.y);
        float2 f2 = __half22float2(*(__half2*)&raw.z);
        float2 f3 = __half22float2(*(__half2*)&raw.w);
        float r = rw[h];
        a0 = fmaf(f0.x, r, a0); a1 = fmaf(f0.y, r, a1);
        a2 = fmaf(f1.x, r, a2); a3 = fmaf(f1.y, r, a3);
        a4 = fmaf(f2.x, r, a4); a5 = fmaf(f2.y, r, a5);
        a6 = fmaf(f3.x, r, a6); a7 = fmaf(f3.y, r, a7);
    }
    float* dst = avg + ((long long)b * SS + q) * SS + k0;
    float4 o0 = {a0, a1, a2, a3};
    float4 o1 = {a4, a5, a6, a7};
    *(float4*)&dst[0] = o0;
    *(float4*)&dst[4] = o1;
}

// ---------------- SIMT projection GEMM (V projection + final) ----------------------
#define PADW 132

__global__ __launch_bounds__(256, 2)
void proj_gemm(const float* __restrict__ A, const float* __restrict__ B,
               const float* __restrict__ bias, float* __restrict__ C,
               int N, int K, int lda, int ldb, int ldc)
{
    __shared__ __align__(16) float As[16 * PADW];
    __shared__ __align__(16) float Bs[16 * PADW];

    const int rowbase = blockIdx.y * 128;
    const int colbase = blockIdx.x * 128;
    const int tid = threadIdx.x;
    const int tx = tid & 15, ty = tid >> 4;
    const int row0 = ty * 8, col0 = tx * 8;

    float regA[8], regB[8];
    unsigned long long acc[8][4];
#pragma unroll
    for (int i = 0; i < 8; i++)
#pragma unroll
        for (int j = 0; j < 4; j++) acc[i][j] = 0ull;

#pragma unroll
    for (int i = 0; i < 8; i++) {
        int idx = tid + i * 256; int r = idx >> 4, kk = idx & 15;
        regA[i] = A[(long long)(rowbase + r) * lda + kk];
    }
#pragma unroll
    for (int i = 0; i < 8; i++) {
        int idx = tid + i * 256; int kk = idx >> 7, c = idx & 127;
        int col = colbase + c;
        regB[i] = (col < N) ? B[(long long)kk * ldb + col] : 0.f;
    }
#pragma unroll
    for (int i = 0; i < 8; i++) {
        int idx = tid + i * 256; int r = idx >> 4, kk = idx & 15;
        As[kk * PADW + r] = regA[i];
    }
#pragma unroll
    for (int i = 0; i < 8; i++) {
        int idx = tid + i * 256; int kk = idx >> 7, c = idx & 127;
        Bs[kk * PADW + c] = regB[i];
    }
    __syncthreads();

    for (int k0 = 16; ; k0 += 16) {
        const bool more = (k0 < K);
        if (more) {
#pragma unroll
            for (int i = 0; i < 8; i++) {
                int idx = tid + i * 256; int r = idx >> 4, kk = idx & 15;
                regA[i] = A[(long long)(rowbase + r) * lda + k0 + kk];
            }
#pragma unroll
            for (int i = 0; i < 8; i++) {
                int idx = tid + i * 256; int kk = idx >> 7, c = idx & 127;
                int col = colbase + c;
                regB[i] = (col < N) ? B[(long long)(k0 + kk) * ldb + col] : 0.f;
            }
        }
#pragma unroll
        for (int kk = 0; kk < 16; kk++) {
            float4 a0 = *(const float4*)&As[kk * PADW + row0];
            float4 a1 = *(const float4*)&As[kk * PADW + row0 + 4];
            float4 b0 = *(const float4*)&Bs[kk * PADW + col0];
            float4 b1 = *(const float4*)&Bs[kk * PADW + col0 + 4];
            float a[8] = {a0.x, a0.y, a0.z, a0.w, a1.x, a1.y, a1.z, a1.w};
            unsigned long long bp[4];
            bp[0] = pack2(b0.x, b0.y); bp[1] = pack2(b0.z, b0.w);
            bp[2] = pack2(b1.x, b1.y); bp[3] = pack2(b1.z, b1.w);
#pragma unroll
            for (int i = 0; i < 8; i++) {
                unsigned long long ap = pack2(a[i], a[i]);
#pragma unroll
                for (int j = 0; j < 4; j++) acc[i][j] = fma2(ap, bp[j], acc[i][j]);
            }
        }
        if (!more) break;
        __syncthreads();
#pragma unroll
        for (int i = 0; i < 8; i++) {
            int idx = tid + i * 256; int r = idx >> 4, kk = idx & 15;
            As[kk * PADW + r] = regA[i];
        }
#pragma unroll
        for (int i = 0; i < 8; i++) {
            int idx = tid + i * 256; int kk = idx >> 7, c = idx & 127;
            Bs[kk * PADW + c] = regB[i];
        }
        __syncthreads();
    }

#pragma unroll
    for (int i = 0; i < 8; i++) {
        int gr = rowbase + row0 + i;
#pragma unroll
        for (int j2 = 0; j2 < 4; j2 += 2) {
            int col = colbase + col0 + j2 * 2;
            if (col < N) {
                float4 v;
                unpack2(acc[i][j2],     v.x, v.y);
                unpack2(acc[i][j2 + 1], v.z, v.w);
                const float4 bb = *(const float4*)&bias[col];
                v.x += bb.x; v.y += bb.y; v.z += bb.z; v.w += bb.w;
                *(float4*)&C[(long long)gr * ldc + col] = v;
            }
        }
    }
}

// ---------------- avg @ V (split-K partials) ---------------------------------------
__global__ __launch_bounds__(256)
void av_gemm(const float* __restrict__ avg, const float* __restrict__ V,
             float* __restrict__ part)
{
    __shared__ float As[16 * PADW];
    __shared__ float Bs[16 * 68];
    const int b = blockIdx.z;
    const int rowbase = blockIdx.y * 128;
    const int k0base = blockIdx.x * 256;
    const float* Ap = avg + ((long long)b * SS + rowbase) * SS;
    const float* Vp = V + (long long)b * SS * DK;
    const int tid = threadIdx.x;
    const int tx = tid & 15, ty = tid >> 4;

    float acc[8][4];
#pragma unroll
    for (int i = 0; i < 8; i++)
#pragma unroll
        for (int j = 0; j < 4; j++) acc[i][j] = 0.f;

    for (int kc = 0; kc < 256; kc += 16) {
        const int k0 = k0base + kc;
#pragma unroll
        for (int i = 0; i < 8; i++) {
            int idx = tid + i * 256; int r = idx >> 4, kk = idx & 15;
            As[kk * PADW + r] = Ap[(long long)r * SS + k0 + kk];
        }
#pragma unroll
        for (int i = 0; i < 4; i++) {
            int idx = tid + i * 256; int kk = idx >> 6, cc = idx & 63;
            Bs[kk * 68 + cc] = Vp[(long long)(k0 + kk) * DK + cc];
        }
        __syncthreads();
#pragma unroll
        for (int kk = 0; kk < 16; kk++) {
            float a[8];
#pragma unroll
            for (int i = 0; i < 8; i++) a[i] = As[kk * PADW + ty * 8 + i];
            float4 bv = *(const float4*)&Bs[kk * 68 + tx * 4];
#pragma unroll
            for (int i = 0; i < 8; i++) {
                acc[i][0] = fmaf(a[i], bv.x, acc[i][0]);
                acc[i][1] = fmaf(a[i], bv.y, acc[i][1]);
                acc[i][2] = fmaf(a[i], bv.z, acc[i][2]);
                acc[i][3] = fmaf(a[i], bv.w, acc[i][3]);
            }
        }
        __syncthreads();
    }
    float* P = part + ((long long)(blockIdx.x * BB + b) * SS + rowbase) * DK;
#pragma unroll
    for (int i = 0; i < 8; i++) {
        float4 v = {acc[i][0], acc[i][1], acc[i][2], acc[i][3]};
        *(float4*)&P[(long long)(ty * 8 + i) * DK + tx * 4] = v;
    }
}

__global__ __launch_bounds__(256)
void av_reduce(const float* __restrict__ part, float* __restrict__ Ao)
{
    int i = blockIdx.x * 256 + threadIdx.x;
    float s = 0.f;
#pragma unroll
    for (int t = 0; t < 8; t++) s += part[(long long)t * (BB * SS * DK) + i];
    Ao[i] = s;
}

// ---------------- launch -------------------------------------------------------------
extern "C" void kernel_launch(void* const* d_in, const int* in_sizes, int n_in,
                              void* d_out, int out_size)
{
    const float* query = (const float*)d_in[0];
    const float* key_  = (const float*)d_in[1];
    const float* value = (const float*)d_in[2];
    const float* Wq    = (const float*)d_in[3];
    const float* bq    = (const float*)d_in[4];
    const float* Wk    = (const float*)d_in[5];
    const float* bk    = (const float*)d_in[6];
    const float* Wv    = (const float*)d_in[7];
    const float* bv    = (const float*)d_in[8];
    const float* Wo    = (const float*)d_in[9];
    const float* bo    = (const float*)d_in[10];

    float* out_main = (float*)d_out;                 // [B,S,DM]
    float* out_avg  = out_main + (size_t)ROWS * DM;  // [B,S,S]

    uint4 *Xq, *Xk, *Wtq, *Wtk, *Qpk, *Kpk;
    __half* Esc;
    float *Vp, *Lp, *Rv, *Ao, *Av;
    cudaGetSymbolAddress((void**)&Xq, g_Xq);
    cudaGetSymbolAddress((void**)&Xk, g_Xk);
    cudaGetSymbolAddress((void**)&Wtq, g_Wtq);
    cudaGetSymbolAddress((void**)&Wtk, g_Wtk);
    cudaGetSymbolAddress((void**)&Qpk, g_Qpk);
    cudaGetSymbolAddress((void**)&Kpk, g_Kpk);
    cudaGetSymbolAddress((void**)&Vp, g_Vp);
    cudaGetSymbolAddress((void**)&Esc, g_escore);
    cudaGetSymbolAddress((void**)&Lp, g_lpart);
    cudaGetSymbolAddress((void**)&Rv, g_rinv);
    cudaGetSymbolAddress((void**)&Ao, g_ao);
    cudaGetSymbolAddress((void**)&Av, g_avpart);

    const int smemP = 384 * 16 * 16;                 // proj_mma: 98304
    const int smem1 = 384 * 16 * 16 + 256 * 4 * 4;   // pass1: 102400
    cudaFuncSetAttribute(proj_mma, cudaFuncAttributeMaxDynamicSharedMemorySize, smemP);
    cudaFuncSetAttribute(mma_pass1, cudaFuncAttributeMaxDynamicSharedMemorySize, smem1);

    dim3 blk(256);

    // 1) split inputs and weights into packed bf16 hi/mid
    split_x<<<ROWS, blk>>>(query, Xq);
    split_x<<<ROWS, blk>>>(key_, Xk);
    split_w<<<dim3(16, 16), blk>>>(Wq, Wtq);
    split_w<<<dim3(16, 16), blk>>>(Wk, Wtk);

    // 2) Q/K projections via bf16-split MMA -> packed head layout
    proj_mma<<<dim3(8, 16), 512, smemP>>>(Xq, Wtq, bq, Qpk);
    proj_mma<<<dim3(8, 16), 512, smemP>>>(Xk, Wtk, bk, Kpk);

    // 3) V projection (SIMT)
    proj_gemm<<<dim3(1, 32), blk>>>(value, Wv, bv, Vp, DK, DM, DM, DK, DK);

    // 4) pass1: scores -> fp16 exp + sumexp partials
    mma_pass1<<<dim3(16, 8, BB * HH), 512, smem1>>>(Qpk, Kpk, Esc, Lp);

    // 5) combine partials -> 1/l
    combine_kernel<<<dim3(BB * HH * SS / 256, 1, 1), blk>>>(Lp, Rv);

    // 6) head-averaged attention -> second output
    avg_kernel<<<dim3(SS, BB, 1), blk>>>(Esc, Rv, out_avg);

    // 7) attn_output = avg @ V (split-K=8)
    av_gemm<<<dim3(8, 16, BB), blk>>>(out_avg, Vp, Av);
    av_reduce<<<dim3(BB * SS * DK / 256, 1, 1), blk>>>(Av, Ao);

    // 8) output = attn_output @ Wo + bo
    proj_gemm<<<dim3(8, 32), blk>>>(Ao, Wo, bo, out_main, DM, DK, DK, DM, DM);
}

// round 12
// speedup vs baseline: 1.7102x; 1.0572x over previous
#include <cuda_runtime.h>
#include <cuda_fp16.h>
#include <cstdint>

#define BB 2
#define SS 2048
#define HH 16
#define DK 64
#define DM 1024
#define ROWS (BB*SS)          // 4096

// ---------------- scratch -----------------------------------------------------
__device__ uint4 g_Xq[(size_t)ROWS*256];          // split query  [4096][256]
__device__ uint4 g_Xk[(size_t)ROWS*256];
__device__ uint4 g_Wtq[(size_t)DM*256];           // split Wq^T   [1024][256]
__device__ uint4 g_Wtk[(size_t)DM*256];
__device__ uint4 g_Qpk[(size_t)BB*HH*SS*16];      // head-layout packed Q
__device__ uint4 g_Kpk[(size_t)BB*HH*SS*16];
__device__ float g_Vp[(size_t)ROWS*DK];
__device__ __half g_escore[(size_t)BB*HH*SS*SS];  // exp(s/8) fp16 (268 MB)
__device__ float g_lpart[(size_t)BB*HH*16*SS];
__device__ float g_rinv[(size_t)BB*HH*SS];
__device__ float g_ao[(size_t)ROWS*DK];
__device__ float g_avpart[(size_t)8*BB*SS*DK];

// ---------------- helpers -------------------------------------------------------
__device__ __forceinline__ float fast_exp(float x) {
    x = fmaxf(x, -87.0f);
    float t = fmaf(x, 1.4426950408889634f, 12582912.0f);
    float n = t - 12582912.0f;
    float f = fmaf(x, 1.4426950408889634f, -n);
    float p = 1.3333558146e-3f;
    p = fmaf(p, f, 9.6178371906e-3f);
    p = fmaf(p, f, 5.5502813330e-2f);
    p = fmaf(p, f, 2.4022650695e-1f);
    p = fmaf(p, f, 6.9314718056e-1f);
    p = fmaf(p, f, 1.0f);
    return p * __int_as_float(((int)n + 127) << 23);
}

__device__ __forceinline__ unsigned long long pack2(float lo, float hi) {
    unsigned long long r;
    asm("mov.b64 %0, {%1, %2};" : "=l"(r) : "f"(lo), "f"(hi));
    return r;
}
__device__ __forceinline__ void unpack2(unsigned long long v, float& lo, float& hi) {
    asm("mov.b64 {%0, %1}, %2;" : "=f"(lo), "=f"(hi) : "l"(v));
}
__device__ __forceinline__ unsigned long long fma2(unsigned long long a,
                                                   unsigned long long b,
                                                   unsigned long long c) {
    unsigned long long d;
    asm("fma.rn.f32x2 %0, %1, %2, %3;" : "=l"(d) : "l"(a), "l"(b), "l"(c));
    return d;
}

__device__ __forceinline__ uint32_t bf16pack(float lo, float hi) {
    uint32_t r;
    asm("cvt.rn.bf16x2.f32 %0, %1, %2;" : "=r"(r) : "f"(hi), "f"(lo));
    return r;
}

__device__ __forceinline__ uint2 himid(float v0, float v1) {
    uint32_t hp = bf16pack(v0, v1);
    uint32_t mp = bf16pack(v0 - __uint_as_float(hp << 16),
                           v1 - __uint_as_float(hp & 0xffff0000u));
    uint2 o = {hp, mp};
    return o;
}

__device__ __forceinline__ void mma16(float* c, const uint32_t* a, const uint32_t* b) {
    asm volatile("mma.sync.aligned.m16n8k16.row.col.f32.bf16.bf16.f32 "
        "{%0,%1,%2,%3}, {%4,%5,%6,%7}, {%8,%9}, {%0,%1,%2,%3};"
        : "+f"(c[0]), "+f"(c[1]), "+f"(c[2]), "+f"(c[3])
        : "r"(a[0]), "r"(a[1]), "r"(a[2]), "r"(a[3]), "r"(b[0]), "r"(b[1]));
}

__device__ __forceinline__ uint32_t smem_u32(const void* p) {
    uint32_t a;
    asm("{ .reg .u64 t; cvta.to.shared.u64 t, %1; cvt.u32.u64 %0, t; }" : "=r"(a) : "l"(p));
    return a;
}

__device__ __forceinline__ void cp_async16(uint32_t dst, const void* src) {
    asm volatile("cp.async.cg.shared.global [%0], [%1], 16;" :: "r"(dst), "l"(src) : "memory");
}
__device__ __forceinline__ void cp_commit() {
    asm volatile("cp.async.commit_group;" ::: "memory");
}
template <int N>
__device__ __forceinline__ void cp_wait() {
    asm volatile("cp.async.wait_group %0;" :: "n"(N) : "memory");
}

#define FSWZ(r, f) ((f) ^ (((r) & 1) << 2))

// ---------------- input split kernels ---------------------------------------------
__global__ __launch_bounds__(256)
void split_x(const float* __restrict__ X, uint4* __restrict__ out)
{
    int g = blockIdx.x * 256 + threadIdx.x;
    int r = g >> 8, f = g & 255;
    int k = (f >> 2) * 16 + (f & 3) * 2;
    const float* xp = X + (long long)r * DM + k;
    uint2 a = himid(xp[0], xp[1]);
    uint2 b = himid(xp[8], xp[9]);
    uint4 o = {a.x, a.y, b.x, b.y};
    out[g] = o;
}

__global__ __launch_bounds__(256)
void split_w(const float* __restrict__ W, uint4* __restrict__ out)
{
    __shared__ float ws[64][65];
    const int tid = threadIdx.x;
    const int kb = blockIdx.y * 64, nb = blockIdx.x * 64;
#pragma unroll
    for (int i = 0; i < 16; i++) {
        int idx = tid + i * 256; int kk = idx >> 6, nn = idx & 63;
        ws[kk][nn] = W[(long long)(kb + kk) * DM + nb + nn];
    }
    __syncthreads();
#pragma unroll
    for (int i = 0; i < 4; i++) {
        int idx = tid + i * 256; int nn = idx >> 4, f = idx & 15;
        int kk = (f >> 2) * 16 + (f & 3) * 2;
        uint2 a = himid(ws[kk][nn], ws[kk + 1][nn]);
        uint2 b = himid(ws[kk + 8][nn], ws[kk + 9][nn]);
        uint4 o = {a.x, a.y, b.x, b.y};
        out[(long long)(nb + nn) * 256 + (kb >> 2) + f] = o;
    }
}

// ---------------- Q/K projection via bf16-split MMA + cp.async pipeline ------------
// stage layout (uint4 units): X at s*6144, W at s*6144+4096; 2 stages = 192 KB
__global__ __launch_bounds__(512, 1)
void proj_mma(const uint4* __restrict__ Xpk, const uint4* __restrict__ Wt,
              const float* __restrict__ bias, uint4* __restrict__ Cpk)
{
    extern __shared__ uint4 smq[];
    const uint32_t smb = smem_u32(smq);

    const int tid = threadIdx.x;
    const int colbase = blockIdx.x * 128;
    const int rowbase = blockIdx.y * 256;
    const int wid = tid >> 5, lane = tid & 31;
    const int wm = wid >> 2, wn = wid & 3;
    const int gid = lane >> 2, tig = lane & 3;

    float acc[4][4][4];
#pragma unroll
    for (int mt = 0; mt < 4; mt++)
#pragma unroll
        for (int nt = 0; nt < 4; nt++)
#pragma unroll
            for (int c = 0; c < 4; c++) acc[mt][nt][c] = 0.f;

    // async issue of one k-chunk into stage s
    auto issue = [&](int kc, int s) {
        uint32_t base = smb + s * 98304;
#pragma unroll
        for (int i = 0; i < 8; i++) {
            int idx = tid + i * 512; int r = idx >> 4, f = idx & 15;
            cp_async16(base + (uint32_t)(r * 16 + FSWZ(r, f)) * 16,
                       &Xpk[(long long)(rowbase + r) * 256 + kc * 16 + f]);
        }
#pragma unroll
        for (int i = 0; i < 4; i++) {
            int idx = tid + i * 512; int r = idx >> 4, f = idx & 15;
            cp_async16(base + 65536u + (uint32_t)(r * 16 + FSWZ(r, f)) * 16,
                       &Wt[(long long)(colbase + r) * 256 + kc * 16 + f]);
        }
        cp_commit();
    };

    issue(0, 0);

    for (int kc = 0; kc < 16; kc++) {
        const int s = kc & 1;
        if (kc < 15) { issue(kc + 1, s ^ 1); cp_wait<1>(); }
        else cp_wait<0>();
        __syncthreads();

        const uint4* Xs = smq + s * 6144;
        const uint4* Ws = Xs + 4096;
#pragma unroll
        for (int k16 = 0; k16 < 4; k16++) {
            const int f = k16 * 4 + tig;
            uint32_t bhf[4][2], bmf[4][2];
#pragma unroll
            for (int nt = 0; nt < 4; nt++) {
                int row = wn * 32 + nt * 8 + gid;
                uint4 kv = Ws[row * 16 + FSWZ(row, f)];
                bhf[nt][0] = kv.x; bhf[nt][1] = kv.z;
                bmf[nt][0] = kv.y; bmf[nt][1] = kv.w;
            }
#pragma unroll
            for (int mt = 0; mt < 4; mt++) {
                int r0 = wm * 64 + mt * 16 + gid;
                int r1 = r0 + 8;
                uint4 qa = Xs[r0 * 16 + FSWZ(r0, f)];
                uint4 qb = Xs[r1 * 16 + FSWZ(r1, f)];
                uint32_t ah[4], am[4];
                ah[0] = qa.x; ah[1] = qb.x; ah[2] = qa.z; ah[3] = qb.z;
                am[0] = qa.y; am[1] = qb.y; am[2] = qa.w; am[3] = qb.w;
#pragma unroll
                for (int nt = 0; nt < 4; nt++) {
                    mma16(acc[mt][nt], ah, bhf[nt]);
                    mma16(acc[mt][nt], ah, bmf[nt]);
                    mma16(acc[mt][nt], am, bhf[nt]);
                }
            }
        }
        __syncthreads();
    }

    // epilogue: + bias, hi/mid split, packed head layout
    const int nb = colbase + wn * 32;
    const int h = nb >> 6;
    const int db = nb & 63;
#pragma unroll
    for (int ntp = 0; ntp < 2; ntp++) {
        int cb = nb + ntp * 16 + tig * 2;
        float b0 = bias[cb],     b1 = bias[cb + 1];
        float b2 = bias[cb + 8], b3 = bias[cb + 9];
        int k16o = (db >> 4) + ntp;
#pragma unroll
        for (int mt = 0; mt < 4; mt++) {
#pragma unroll
            for (int rr = 0; rr < 2; rr++) {
                int gr = rowbase + wm * 64 + mt * 16 + rr * 8 + gid;
                int b = gr >> 11, s = gr & (SS - 1);
                uint2 lo = himid(acc[mt][2 * ntp][rr * 2] + b0,
                                 acc[mt][2 * ntp][rr * 2 + 1] + b1);
                uint2 hi = himid(acc[mt][2 * ntp + 1][rr * 2] + b2,
                                 acc[mt][2 * ntp + 1][rr * 2 + 1] + b3);
                uint4 o = {lo.x, lo.y, hi.x, hi.y};
                Cpk[((long long)((b * HH + h) * SS + s)) * 16 + k16o * 4 + tig] = o;
            }
        }
    }
}

// ---------------- pass 1: 256x128 tile, bf16-split MMA -> fp16 exp + sumexp --------
__global__ __launch_bounds__(512, 1)
void mma_pass1(const uint4* __restrict__ Qpk, const uint4* __restrict__ Kpk,
               __half* __restrict__ Esc, float* __restrict__ lpart)
{
    extern __shared__ uint4 smq[];
    uint4* Qs = smq;                          // [256][16]
    uint4* Ks = Qs + 256 * 16;                // [128][16]
    float* rowsum = (float*)(smq + 384 * 16); // [256][4]
    __half* smh = (__half*)smq;               // epilogue staging

    const int tid = threadIdx.x;
    const int kt = blockIdx.x, qt = blockIdx.y, bh = blockIdx.z;
    const long long qbase = ((long long)bh * SS + qt * 256) * 16;
    const long long kbase = ((long long)bh * SS + kt * 128) * 16;

#pragma unroll
    for (int i = 0; i < 8; i++) {
        int idx = tid + i * 512;
        int r = idx >> 4, f = idx & 15;
        Qs[r * 16 + FSWZ(r, f)] = Qpk[qbase + r * 16 + f];
    }
#pragma unroll
    for (int i = 0; i < 4; i++) {
        int idx = tid + i * 512;
        int r = idx >> 4, f = idx & 15;
        Ks[r * 16 + FSWZ(r, f)] = Kpk[kbase + r * 16 + f];
    }
    __syncthreads();

    const int wid = tid >> 5, lane = tid & 31;
    const int wm = wid >> 2, wn = wid & 3;
    const int gid = lane >> 2, tig = lane & 3;

    float acc[4][4][4];
#pragma unroll
    for (int mt = 0; mt < 4; mt++)
#pragma unroll
        for (int nt = 0; nt < 4; nt++)
#pragma unroll
            for (int c = 0; c < 4; c++) acc[mt][nt][c] = 0.f;

#pragma unroll
    for (int k16 = 0; k16 < 4; k16++) {
        const int f = k16 * 4 + tig;
        uint32_t bhf[4][2], bmf[4][2];
#pragma unroll
        for (int nt = 0; nt < 4; nt++) {
            int row = wn * 32 + nt * 8 + gid;
            uint4 kv = Ks[row * 16 + FSWZ(row, f)];
            bhf[nt][0] = kv.x; bhf[nt][1] = kv.z;
            bmf[nt][0] = kv.y; bmf[nt][1] = kv.w;
        }
#pragma unroll
        for (int mt = 0; mt < 4; mt++) {
            int r0 = wm * 64 + mt * 16 + gid;
            int r1 = r0 + 8;
            uint4 qa = Qs[r0 * 16 + FSWZ(r0, f)];
            uint4 qb = Qs[r1 * 16 + FSWZ(r1, f)];
            uint32_t ah[4], am[4];
            ah[0] = qa.x; ah[1] = qb.x; ah[2] = qa.z; ah[3] = qb.z;
            am[0] = qa.y; am[1] = qb.y; am[2] = qa.w; am[3] = qb.w;
#pragma unroll
            for (int nt = 0; nt < 4; nt++) {
                mma16(acc[mt][nt], ah, bhf[nt]);
                mma16(acc[mt][nt], ah, bmf[nt]);
                mma16(acc[mt][nt], am, bhf[nt]);
            }
        }
    }

    float p[4][2];
#pragma unroll
    for (int mt = 0; mt < 4; mt++) { p[mt][0] = 0.f; p[mt][1] = 0.f; }
#pragma unroll
    for (int mt = 0; mt < 4; mt++)
#pragma unroll
        for (int nt = 0; nt < 4; nt++) {
            acc[mt][nt][0] = fast_exp(acc[mt][nt][0] * 0.125f);
            acc[mt][nt][1] = fast_exp(acc[mt][nt][1] * 0.125f);
            acc[mt][nt][2] = fast_exp(acc[mt][nt][2] * 0.125f);
            acc[mt][nt][3] = fast_exp(acc[mt][nt][3] * 0.125f);
            p[mt][0] += acc[mt][nt][0] + acc[mt][nt][1];
            p[mt][1] += acc[mt][nt][2] + acc[mt][nt][3];
        }
#pragma unroll
    for (int o = 1; o <= 2; o <<= 1)
#pragma unroll
        for (int mt = 0; mt < 4; mt++) {
            p[mt][0] += __shfl_xor_sync(0xffffffffu, p[mt][0], o);
            p[mt][1] += __shfl_xor_sync(0xffffffffu, p[mt][1], o);
        }
    if (tig == 0) {
#pragma unroll
        for (int mt = 0; mt < 4; mt++)
#pragma unroll
            for (int j = 0; j < 2; j++) {
                int r = wm * 64 + mt * 16 + j * 8 + gid;
                rowsum[r * 4 + wn] = p[mt][j];
            }
    }
    __syncthreads();

    if (tid < 256) {
        float l = rowsum[tid * 4] + rowsum[tid * 4 + 1]
                + rowsum[tid * 4 + 2] + rowsum[tid * 4 + 3];
        lpart[(long long)(bh * 16 + kt) * SS + qt * 256 + tid] = l;
    }

#pragma unroll
    for (int mt = 0; mt < 4; mt++) {
        int r0 = wm * 64 + mt * 16 + gid;
#pragma unroll
        for (int nt = 0; nt < 4; nt++) {
            int col = wn * 32 + nt * 8 + tig * 2;
            *(__half2*)&smh[r0 * 136 + col] =
                __floats2half2_rn(acc[mt][nt][0], acc[mt][nt][1]);
            *(__half2*)&smh[(r0 + 8) * 136 + col] =
                __floats2half2_rn(acc[mt][nt][2], acc[mt][nt][3]);
        }
    }
    __syncthreads();

    __half* Cp = Esc + ((long long)bh * SS + qt * 256) * SS + kt * 128;
    const int u = tid & 15;
    const int rbase = tid >> 4;
#pragma unroll
    for (int i = 0; i < 8; i++) {
        int row = i * 32 + rbase;
        uint4 v = *(uint4*)&smh[row * 136 + u * 8];
        *(uint4*)&Cp[(long long)row * SS + u * 8] = v;
    }
}

// ---------------- combine: rinv = 1 / sum of partials ----------------------------
__global__ __launch_bounds__(256)
void combine_kernel(const float* __restrict__ lpart, float* __restrict__ rinv)
{
    int rowg = blockIdx.x * 256 + threadIdx.x;
    int bh = rowg >> 11, q = rowg & (SS - 1);
    float l = 0.f;
#pragma unroll
    for (int t = 0; t < 16; t++)
        l += lpart[(long long)(bh * 16 + t) * SS + q];
    rinv[rowg] = 1.0f / l;
}

// ---------------- head-averaged attention (fp16 stream MAC) ----------------------
__global__ __launch_bounds__(256)
void avg_kernel(const __half* __restrict__ Esc, const float* __restrict__ rinv,
                float* __restrict__ avg)
{
    const int q = blockIdx.x;
    const int b = blockIdx.y;
    const int tid = threadIdx.x;

    __shared__ float rw[HH];
    if (tid < HH) rw[tid] = rinv[((long long)(b * HH + tid) << 11) + q] * (1.0f / HH);
    __syncthreads();

    const __half* base = Esc + ((long long)(b * HH) * SS + q) * SS;
    const int k0 = tid * 8;
    float a0 = 0.f, a1 = 0.f, a2 = 0.f, a3 = 0.f;
    float a4 = 0.f, a5 = 0.f, a6 = 0.f, a7 = 0.f;
#pragma unroll
    for (int h = 0; h < HH; h++) {
        uint4 raw = *(const uint4*)(base + (long long)h * SS * SS + k0);
        float2 f0 = __half22float2(*(__half2*)&raw.x);
        float2 f1 = __half22float2(*(__half2*)&raw.y);
        float2 f2 = __half22float2(*(__half2*)&raw.z);
        float2 f3 = __half22float2(*(__half2*)&raw.w);
        float r = rw[h];
        a0 = fmaf(f0.x, r, a0); a1 = fmaf(f0.y, r, a1);
        a2 = fmaf(f1.x, r, a2); a3 = fmaf(f1.y, r, a3);
        a4 = fmaf(f2.x, r, a4); a5 = fmaf(f2.y, r, a5);
        a6 = fmaf(f3.x, r, a6); a7 = fmaf(f3.y, r, a7);
    }
    float* dst = avg + ((long long)b * SS + q) * SS + k0;
    float4 o0 = {a0, a1, a2, a3};
    float4 o1 = {a4, a5, a6, a7};
    *(float4*)&dst[0] = o0;
    *(float4*)&dst[4] = o1;
}

// ---------------- SIMT projection GEMM (V projection + final) ----------------------
#define PADW 132

__global__ __launch_bounds__(256, 2)
void proj_gemm(const float* __restrict__ A, const float* __restrict__ B,
               const float* __restrict__ bias, float* __restrict__ C,
               int N, int K, int lda, int ldb, int ldc)
{
    __shared__ __align__(16) float As[16 * PADW];
    __shared__ __align__(16) float Bs[16 * PADW];

    const int rowbase = blockIdx.y * 128;
    const int colbase = blockIdx.x * 128;
    const int tid = threadIdx.x;
    const int tx = tid & 15, ty = tid >> 4;
    const int row0 = ty * 8, col0 = tx * 8;

    float regA[8], regB[8];
    unsigned long long acc[8][4];
#pragma unroll
    for (int i = 0; i < 8; i++)
#pragma unroll
        for (int j = 0; j < 4; j++) acc[i][j] = 0ull;

#pragma unroll
    for (int i = 0; i < 8; i++) {
        int idx = tid + i * 256; int r = idx >> 4, kk = idx & 15;
        regA[i] = A[(long long)(rowbase + r) * lda + kk];
    }
#pragma unroll
    for (int i = 0; i < 8; i++) {
        int idx = tid + i * 256; int kk = idx >> 7, c = idx & 127;
        int col = colbase + c;
        regB[i] = (col < N) ? B[(long long)kk * ldb + col] : 0.f;
    }
#pragma unroll
    for (int i = 0; i < 8; i++) {
        int idx = tid + i * 256; int r = idx >> 4, kk = idx & 15;
        As[kk * PADW + r] = regA[i];
    }
#pragma unroll
    for (int i = 0; i < 8; i++) {
        int idx = tid + i * 256; int kk = idx >> 7, c = idx & 127;
        Bs[kk * PADW + c] = regB[i];
    }
    __syncthreads();

    for (int k0 = 16; ; k0 += 16) {
        const bool more = (k0 < K);
        if (more) {
#pragma unroll
            for (int i = 0; i < 8; i++) {
                int idx = tid + i * 256; int r = idx >> 4, kk = idx & 15;
                regA[i] = A[(long long)(rowbase + r) * lda + k0 + kk];
            }
#pragma unroll
            for (int i = 0; i < 8; i++) {
                int idx = tid + i * 256; int kk = idx >> 7, c = idx & 127;
                int col = colbase + c;
                regB[i] = (col < N) ? B[(long long)(k0 + kk) * ldb + col] : 0.f;
            }
        }
#pragma unroll
        for (int kk = 0; kk < 16; kk++) {
            float4 a0 = *(const float4*)&As[kk * PADW + row0];
            float4 a1 = *(const float4*)&As[kk * PADW + row0 + 4];
            float4 b0 = *(const float4*)&Bs[kk * PADW + col0];
            float4 b1 = *(const float4*)&Bs[kk * PADW + col0 + 4];
            float a[8] = {a0.x, a0.y, a0.z, a0.w, a1.x, a1.y, a1.z, a1.w};
            unsigned long long bp[4];
            bp[0] = pack2(b0.x, b0.y); bp[1] = pack2(b0.z, b0.w);
            bp[2] = pack2(b1.x, b1.y); bp[3] = pack2(b1.z, b1.w);
#pragma unroll
            for (int i = 0; i < 8; i++) {
                unsigned long long ap = pack2(a[i], a[i]);
#pragma unroll
                for (int j = 0; j < 4; j++) acc[i][j] = fma2(ap, bp[j], acc[i][j]);
            }
        }
        if (!more) break;
        __syncthreads();
#pragma unroll
        for (int i = 0; i < 8; i++) {
            int idx = tid + i * 256; int r = idx >> 4, kk = idx & 15;
            As[kk * PADW + r] = regA[i];
        }
#pragma unroll
        for (int i = 0; i < 8; i++) {
            int idx = tid + i * 256; int kk = idx >> 7, c = idx & 127;
            Bs[kk * PADW + c] = regB[i];
        }
        __syncthreads();
    }

#pragma unroll
    for (int i = 0; i < 8; i++) {
        int gr = rowbase + row0 + i;
#pragma unroll
        for (int j2 = 0; j2 < 4; j2 += 2) {
            int col = colbase + col0 + j2 * 2;
            if (col < N) {
                float4 v;
                unpack2(acc[i][j2],     v.x, v.y);
                unpack2(acc[i][j2 + 1], v.z, v.w);
                const float4 bb = *(const float4*)&bias[col];
                v.x += bb.x; v.y += bb.y; v.z += bb.z; v.w += bb.w;
                *(float4*)&C[(long long)gr * ldc + col] = v;
            }
        }
    }
}

// ---------------- avg @ V (split-K, packed fma2 + reg prefetch) ---------------------
__global__ __launch_bounds__(256)
void av_gemm(const float* __restrict__ avg, const float* __restrict__ V,
             float* __restrict__ part)
{
    __shared__ float As[16 * PADW];
    __shared__ float Bs[16 * 68];
    const int b = blockIdx.z;
    const int rowbase = blockIdx.y * 128;
    const int k0base = blockIdx.x * 256;
    const float* Ap = avg + ((long long)b * SS + rowbase) * SS;
    const float* Vp = V + (long long)b * SS * DK;
    const int tid = threadIdx.x;
    const int tx = tid & 15, ty = tid >> 4;

    unsigned long long acc[8][2];
#pragma unroll
    for (int i = 0; i < 8; i++) { acc[i][0] = 0ull; acc[i][1] = 0ull; }

    float regA[8], regB[4];
#pragma unroll
    for (int i = 0; i < 8; i++) {
        int idx = tid + i * 256; int r = idx >> 4, kk = idx & 15;
        regA[i] = Ap[(long long)r * SS + k0base + kk];
    }
#pragma unroll
    for (int i = 0; i < 4; i++) {
        int idx = tid + i * 256; int kk = idx >> 6, cc = idx & 63;
        regB[i] = Vp[(long long)(k0base + kk) * DK + cc];
    }

    for (int kc = 0; kc < 256; kc += 16) {
#pragma unroll
        for (int i = 0; i < 8; i++) {
            int idx = tid + i * 256; int r = idx >> 4, kk = idx & 15;
            As[kk * PADW + r] = regA[i];
        }
#pragma unroll
        for (int i = 0; i < 4; i++) {
            int idx = tid + i * 256; int kk = idx >> 6, cc = idx & 63;
            Bs[kk * 68 + cc] = regB[i];
        }
        __syncthreads();

        const bool more = (kc + 16 < 256);
        if (more) {
            const int k0 = k0base + kc + 16;
#pragma unroll
            for (int i = 0; i < 8; i++) {
                int idx = tid + i * 256; int r = idx >> 4, kk = idx & 15;
                regA[i] = Ap[(long long)r * SS + k0 + kk];
            }
#pragma unroll
            for (int i = 0; i < 4; i++) {
                int idx = tid + i * 256; int kk = idx >> 6, cc = idx & 63;
                regB[i] = Vp[(long long)(k0 + kk) * DK + cc];
            }
        }

#pragma unroll
        for (int kk = 0; kk < 16; kk++) {
            float a[8];
#pragma unroll
            for (int i = 0; i < 8; i++) a[i] = As[kk * PADW + ty * 8 + i];
            float4 bv = *(const float4*)&Bs[kk * 68 + tx * 4];
            unsigned long long b01 = pack2(bv.x, bv.y);
            unsigned long long b23 = pack2(bv.z, bv.w);
#pragma unroll
            for (int i = 0; i < 8; i++) {
                unsigned long long ap = pack2(a[i], a[i]);
                acc[i][0] = fma2(ap, b01, acc[i][0]);
                acc[i][1] = fma2(ap, b23, acc[i][1]);
            }
        }
        __syncthreads();
    }
    float* P = part + ((long long)(blockIdx.x * BB + b) * SS + rowbase) * DK;
#pragma unroll
    for (int i = 0; i < 8; i++) {
        float4 v;
        unpack2(acc[i][0], v.x, v.y);
        unpack2(acc[i][1], v.z, v.w);
        *(float4*)&P[(long long)(ty * 8 + i) * DK + tx * 4] = v;
    }
}

__global__ __launch_bounds__(256)
void av_reduce(const float* __restrict__ part, float* __restrict__ Ao)
{
    int i = blockIdx.x * 256 + threadIdx.x;
    float s = 0.f;
#pragma unroll
    for (int t = 0; t < 8; t++) s += part[(long long)t * (BB * SS * DK) + i];
    Ao[i] = s;
}

// ---------------- launch -------------------------------------------------------------
extern "C" void kernel_launch(void* const* d_in, const int* in_sizes, int n_in,
                              void* d_out, int out_size)
{
    const float* query = (const float*)d_in[0];
    const float* key_  = (const float*)d_in[1];
    const float* value = (const float*)d_in[2];
    const float* Wq    = (const float*)d_in[3];
    const float* bq    = (const float*)d_in[4];
    const float* Wk    = (const float*)d_in[5];
    const float* bk    = (const float*)d_in[6];
    const float* Wv    = (const float*)d_in[7];
    const float* bv    = (const float*)d_in[8];
    const float* Wo    = (const float*)d_in[9];
    const float* bo    = (const float*)d_in[10];

    float* out_main = (float*)d_out;                 // [B,S,DM]
    float* out_avg  = out_main + (size_t)ROWS * DM;  // [B,S,S]

    uint4 *Xq, *Xk, *Wtq, *Wtk, *Qpk, *Kpk;
    __half* Esc;
    float *Vp, *Lp, *Rv, *Ao, *Av;
    cudaGetSymbolAddress((void**)&Xq, g_Xq);
    cudaGetSymbolAddress((void**)&Xk, g_Xk);
    cudaGetSymbolAddress((void**)&Wtq, g_Wtq);
    cudaGetSymbolAddress((void**)&Wtk, g_Wtk);
    cudaGetSymbolAddress((void**)&Qpk, g_Qpk);
    cudaGetSymbolAddress((void**)&Kpk, g_Kpk);
    cudaGetSymbolAddress((void**)&Vp, g_Vp);
    cudaGetSymbolAddress((void**)&Esc, g_escore);
    cudaGetSymbolAddress((void**)&Lp, g_lpart);
    cudaGetSymbolAddress((void**)&Rv, g_rinv);
    cudaGetSymbolAddress((void**)&Ao, g_ao);
    cudaGetSymbolAddress((void**)&Av, g_avpart);

    const int smemP = 2 * 98304;                     // proj_mma: 192 KB (2 stages)
    const int smem1 = 384 * 16 * 16 + 256 * 4 * 4;   // pass1: 102400
    cudaFuncSetAttribute(proj_mma, cudaFuncAttributeMaxDynamicSharedMemorySize, smemP);
    cudaFuncSetAttribute(mma_pass1, cudaFuncAttributeMaxDynamicSharedMemorySize, smem1);

    dim3 blk(256);

    // 1) split inputs and weights into packed bf16 hi/mid
    split_x<<<ROWS, blk>>>(query, Xq);
    split_x<<<ROWS, blk>>>(key_, Xk);
    split_w<<<dim3(16, 16), blk>>>(Wq, Wtq);
    split_w<<<dim3(16, 16), blk>>>(Wk, Wtk);

    // 2) Q/K projections via pipelined bf16-split MMA -> packed head layout
    proj_mma<<<dim3(8, 16), 512, smemP>>>(Xq, Wtq, bq, Qpk);
    proj_mma<<<dim3(8, 16), 512, smemP>>>(Xk, Wtk, bk, Kpk);

    // 3) V projection (SIMT)
    proj_gemm<<<dim3(1, 32), blk>>>(value, Wv, bv, Vp, DK, DM, DM, DK, DK);

    // 4) pass1: scores -> fp16 exp + sumexp partials
    mma_pass1<<<dim3(16, 8, BB * HH), 512, smem1>>>(Qpk, Kpk, Esc, Lp);

    // 5) combine partials -> 1/l
    combine_kernel<<<dim3(BB * HH * SS / 256, 1, 1), blk>>>(Lp, Rv);

    // 6) head-averaged attention -> second output
    avg_kernel<<<dim3(SS, BB, 1), blk>>>(Esc, Rv, out_avg);

    // 7) attn_output = avg @ V (split-K=8, fma2)
    av_gemm<<<dim3(8, 16, BB), blk>>>(out_avg, Vp, Av);
    av_reduce<<<dim3(BB * SS * DK / 256, 1, 1), blk>>>(Av, Ao);

    // 8) output = attn_output @ Wo + bo
    proj_gemm<<<dim3(8, 32), blk>>>(Ao, Wo, bo, out_main, DM, DK, DK, DM, DM);
}

// round 13
// speedup vs baseline: 2.0497x; 1.1985x over previous
#include <cuda_runtime.h>
#include <cuda_fp16.h>
#include <cstdint>

#define BB 2
#define SS 2048
#define HH 16
#define DK 64
#define DM 1024
#define ROWS (BB*SS)          // 4096

// ---------------- scratch -----------------------------------------------------
__device__ uint4 g_Xq[(size_t)ROWS*256];          // split query  [4096][256]
__device__ uint4 g_Xk[(size_t)ROWS*256];
__device__ uint4 g_Wtq[(size_t)DM*256];           // split Wq^T   [1024][256]
__device__ uint4 g_Wtk[(size_t)DM*256];
__device__ uint4 g_Qpk[(size_t)BB*HH*SS*16];      // head-layout packed Q
__device__ uint4 g_Kpk[(size_t)BB*HH*SS*16];
__device__ float g_Vp[(size_t)ROWS*DK];
__device__ __half g_escore[(size_t)BB*HH*SS*SS];  // exp(s/8) fp16 (268 MB)
__device__ float g_lpart[(size_t)BB*HH*16*SS];
__device__ float g_rinv[(size_t)BB*HH*SS];
__device__ float g_ao[(size_t)ROWS*DK];
__device__ float g_avpart[(size_t)8*BB*SS*DK];

// ---------------- helpers -------------------------------------------------------
__device__ __forceinline__ float fast_exp(float x) {
    x = fmaxf(x, -87.0f);
    float t = fmaf(x, 1.4426950408889634f, 12582912.0f);
    float n = t - 12582912.0f;
    float f = fmaf(x, 1.4426950408889634f, -n);
    float p = 1.3333558146e-3f;
    p = fmaf(p, f, 9.6178371906e-3f);
    p = fmaf(p, f, 5.5502813330e-2f);
    p = fmaf(p, f, 2.4022650695e-1f);
    p = fmaf(p, f, 6.9314718056e-1f);
    p = fmaf(p, f, 1.0f);
    return p * __int_as_float(((int)n + 127) << 23);
}

__device__ __forceinline__ unsigned long long pack2(float lo, float hi) {
    unsigned long long r;
    asm("mov.b64 %0, {%1, %2};" : "=l"(r) : "f"(lo), "f"(hi));
    return r;
}
__device__ __forceinline__ void unpack2(unsigned long long v, float& lo, float& hi) {
    asm("mov.b64 {%0, %1}, %2;" : "=f"(lo), "=f"(hi) : "l"(v));
}
__device__ __forceinline__ unsigned long long fma2(unsigned long long a,
                                                   unsigned long long b,
                                                   unsigned long long c) {
    unsigned long long d;
    asm("fma.rn.f32x2 %0, %1, %2, %3;" : "=l"(d) : "l"(a), "l"(b), "l"(c));
    return d;
}

__device__ __forceinline__ uint32_t bf16pack(float lo, float hi) {
    uint32_t r;
    asm("cvt.rn.bf16x2.f32 %0, %1, %2;" : "=r"(r) : "f"(hi), "f"(lo));
    return r;
}

__device__ __forceinline__ uint2 himid(float v0, float v1) {
    uint32_t hp = bf16pack(v0, v1);
    uint32_t mp = bf16pack(v0 - __uint_as_float(hp << 16),
                           v1 - __uint_as_float(hp & 0xffff0000u));
    uint2 o = {hp, mp};
    return o;
}

__device__ __forceinline__ void mma16(float* c, const uint32_t* a, const uint32_t* b) {
    asm volatile("mma.sync.aligned.m16n8k16.row.col.f32.bf16.bf16.f32 "
        "{%0,%1,%2,%3}, {%4,%5,%6,%7}, {%8,%9}, {%0,%1,%2,%3};"
        : "+f"(c[0]), "+f"(c[1]), "+f"(c[2]), "+f"(c[3])
        : "r"(a[0]), "r"(a[1]), "r"(a[2]), "r"(a[3]), "r"(b[0]), "r"(b[1]));
}

__device__ __forceinline__ uint32_t smem_u32(const void* p) {
    uint32_t a;
    asm("{ .reg .u64 t; cvta.to.shared.u64 t, %1; cvt.u32.u64 %0, t; }" : "=r"(a) : "l"(p));
    return a;
}

__device__ __forceinline__ void cp_async16(uint32_t dst, const void* src) {
    asm volatile("cp.async.cg.shared.global [%0], [%1], 16;" :: "r"(dst), "l"(src) : "memory");
}
__device__ __forceinline__ void cp_commit() {
    asm volatile("cp.async.commit_group;" ::: "memory");
}
template <int N>
__device__ __forceinline__ void cp_wait() {
    asm volatile("cp.async.wait_group %0;" :: "n"(N) : "memory");
}

#define FSWZ(r, f) ((f) ^ (((r) & 1) << 2))

// ---------------- input split kernels ---------------------------------------------
__global__ __launch_bounds__(256)
void split_x(const float* __restrict__ X, uint4* __restrict__ out)
{
    int g = blockIdx.x * 256 + threadIdx.x;
    int r = g >> 8, f = g & 255;
    int k = (f >> 2) * 16 + (f & 3) * 2;
    const float* xp = X + (long long)r * DM + k;
    uint2 a = himid(xp[0], xp[1]);
    uint2 b = himid(xp[8], xp[9]);
    uint4 o = {a.x, a.y, b.x, b.y};
    out[g] = o;
}

__global__ __launch_bounds__(256)
void split_w(const float* __restrict__ W, uint4* __restrict__ out)
{
    __shared__ float ws[64][65];
    const int tid = threadIdx.x;
    const int kb = blockIdx.y * 64, nb = blockIdx.x * 64;
#pragma unroll
    for (int i = 0; i < 16; i++) {
        int idx = tid + i * 256; int kk = idx >> 6, nn = idx & 63;
        ws[kk][nn] = W[(long long)(kb + kk) * DM + nb + nn];
    }
    __syncthreads();
#pragma unroll
    for (int i = 0; i < 4; i++) {
        int idx = tid + i * 256; int nn = idx >> 4, f = idx & 15;
        int kk = (f >> 2) * 16 + (f & 3) * 2;
        uint2 a = himid(ws[kk][nn], ws[kk + 1][nn]);
        uint2 b = himid(ws[kk + 8][nn], ws[kk + 9][nn]);
        uint4 o = {a.x, a.y, b.x, b.y};
        out[(long long)(nb + nn) * 256 + (kb >> 2) + f] = o;
    }
}

// ---------------- Q/K projection via bf16-split MMA + cp.async pipeline ------------
__global__ __launch_bounds__(512, 1)
void proj_mma(const uint4* __restrict__ Xpk, const uint4* __restrict__ Wt,
              const float* __restrict__ bias, uint4* __restrict__ Cpk)
{
    extern __shared__ uint4 smq[];
    const uint32_t smb = smem_u32(smq);

    const int tid = threadIdx.x;
    const int colbase = blockIdx.x * 128;
    const int rowbase = blockIdx.y * 256;
    const int wid = tid >> 5, lane = tid & 31;
    const int wm = wid >> 2, wn = wid & 3;
    const int gid = lane >> 2, tig = lane & 3;

    float acc[4][4][4];
#pragma unroll
    for (int mt = 0; mt < 4; mt++)
#pragma unroll
        for (int nt = 0; nt < 4; nt++)
#pragma unroll
            for (int c = 0; c < 4; c++) acc[mt][nt][c] = 0.f;

    auto issue = [&](int kc, int s) {
        uint32_t base = smb + s * 98304;
#pragma unroll
        for (int i = 0; i < 8; i++) {
            int idx = tid + i * 512; int r = idx >> 4, f = idx & 15;
            cp_async16(base + (uint32_t)(r * 16 + FSWZ(r, f)) * 16,
                       &Xpk[(long long)(rowbase + r) * 256 + kc * 16 + f]);
        }
#pragma unroll
        for (int i = 0; i < 4; i++) {
            int idx = tid + i * 512; int r = idx >> 4, f = idx & 15;
            cp_async16(base + 65536u + (uint32_t)(r * 16 + FSWZ(r, f)) * 16,
                       &Wt[(long long)(colbase + r) * 256 + kc * 16 + f]);
        }
        cp_commit();
    };

    issue(0, 0);

    for (int kc = 0; kc < 16; kc++) {
        const int s = kc & 1;
        if (kc < 15) { issue(kc + 1, s ^ 1); cp_wait<1>(); }
        else cp_wait<0>();
        __syncthreads();

        const uint4* Xs = smq + s * 6144;
        const uint4* Ws = Xs + 4096;
#pragma unroll
        for (int k16 = 0; k16 < 4; k16++) {
            const int f = k16 * 4 + tig;
            uint32_t bhf[4][2], bmf[4][2];
#pragma unroll
            for (int nt = 0; nt < 4; nt++) {
                int row = wn * 32 + nt * 8 + gid;
                uint4 kv = Ws[row * 16 + FSWZ(row, f)];
                bhf[nt][0] = kv.x; bhf[nt][1] = kv.z;
                bmf[nt][0] = kv.y; bmf[nt][1] = kv.w;
            }
#pragma unroll
            for (int mt = 0; mt < 4; mt++) {
                int r0 = wm * 64 + mt * 16 + gid;
                int r1 = r0 + 8;
                uint4 qa = Xs[r0 * 16 + FSWZ(r0, f)];
                uint4 qb = Xs[r1 * 16 + FSWZ(r1, f)];
                uint32_t ah[4], am[4];
                ah[0] = qa.x; ah[1] = qb.x; ah[2] = qa.z; ah[3] = qb.z;
                am[0] = qa.y; am[1] = qb.y; am[2] = qa.w; am[3] = qb.w;
#pragma unroll
                for (int nt = 0; nt < 4; nt++) {
                    mma16(acc[mt][nt], ah, bhf[nt]);
                    mma16(acc[mt][nt], ah, bmf[nt]);
                    mma16(acc[mt][nt], am, bhf[nt]);
                }
            }
        }
        __syncthreads();
    }

    const int nb = colbase + wn * 32;
    const int h = nb >> 6;
    const int db = nb & 63;
#pragma unroll
    for (int ntp = 0; ntp < 2; ntp++) {
        int cb = nb + ntp * 16 + tig * 2;
        float b0 = bias[cb],     b1 = bias[cb + 1];
        float b2 = bias[cb + 8], b3 = bias[cb + 9];
        int k16o = (db >> 4) + ntp;
#pragma unroll
        for (int mt = 0; mt < 4; mt++) {
#pragma unroll
            for (int rr = 0; rr < 2; rr++) {
                int gr = rowbase + wm * 64 + mt * 16 + rr * 8 + gid;
                int b = gr >> 11, s = gr & (SS - 1);
                uint2 lo = himid(acc[mt][2 * ntp][rr * 2] + b0,
                                 acc[mt][2 * ntp][rr * 2 + 1] + b1);
                uint2 hi = himid(acc[mt][2 * ntp + 1][rr * 2] + b2,
                                 acc[mt][2 * ntp + 1][rr * 2 + 1] + b3);
                uint4 o = {lo.x, lo.y, hi.x, hi.y};
                Cpk[((long long)((b * HH + h) * SS + s)) * 16 + k16o * 4 + tig] = o;
            }
        }
    }
}

// ---------------- pass 1: 256x128 tile, bf16-split MMA -> fp16 exp + sumexp --------
__global__ __launch_bounds__(512, 1)
void mma_pass1(const uint4* __restrict__ Qpk, const uint4* __restrict__ Kpk,
               __half* __restrict__ Esc, float* __restrict__ lpart)
{
    extern __shared__ uint4 smq[];
    uint4* Qs = smq;                          // [256][16]
    uint4* Ks = Qs + 256 * 16;                // [128][16]
    float* rowsum = (float*)(smq + 384 * 16); // [256][4]
    __half* smh = (__half*)smq;               // epilogue staging

    const int tid = threadIdx.x;
    const int kt = blockIdx.x, qt = blockIdx.y, bh = blockIdx.z;
    const long long qbase = ((long long)bh * SS + qt * 256) * 16;
    const long long kbase = ((long long)bh * SS + kt * 128) * 16;

#pragma unroll
    for (int i = 0; i < 8; i++) {
        int idx = tid + i * 512;
        int r = idx >> 4, f = idx & 15;
        Qs[r * 16 + FSWZ(r, f)] = Qpk[qbase + r * 16 + f];
    }
#pragma unroll
    for (int i = 0; i < 4; i++) {
        int idx = tid + i * 512;
        int r = idx >> 4, f = idx & 15;
        Ks[r * 16 + FSWZ(r, f)] = Kpk[kbase + r * 16 + f];
    }
    __syncthreads();

    const int wid = tid >> 5, lane = tid & 31;
    const int wm = wid >> 2, wn = wid & 3;
    const int gid = lane >> 2, tig = lane & 3;

    float acc[4][4][4];
#pragma unroll
    for (int mt = 0; mt < 4; mt++)
#pragma unroll
        for (int nt = 0; nt < 4; nt++)
#pragma unroll
            for (int c = 0; c < 4; c++) acc[mt][nt][c] = 0.f;

#pragma unroll
    for (int k16 = 0; k16 < 4; k16++) {
        const int f = k16 * 4 + tig;
        uint32_t bhf[4][2], bmf[4][2];
#pragma unroll
        for (int nt = 0; nt < 4; nt++) {
            int row = wn * 32 + nt * 8 + gid;
            uint4 kv = Ks[row * 16 + FSWZ(row, f)];
            bhf[nt][0] = kv.x; bhf[nt][1] = kv.z;
            bmf[nt][0] = kv.y; bmf[nt][1] = kv.w;
        }
#pragma unroll
        for (int mt = 0; mt < 4; mt++) {
            int r0 = wm * 64 + mt * 16 + gid;
            int r1 = r0 + 8;
            uint4 qa = Qs[r0 * 16 + FSWZ(r0, f)];
            uint4 qb = Qs[r1 * 16 + FSWZ(r1, f)];
            uint32_t ah[4], am[4];
            ah[0] = qa.x; ah[1] = qb.x; ah[2] = qa.z; ah[3] = qb.z;
            am[0] = qa.y; am[1] = qb.y; am[2] = qa.w; am[3] = qb.w;
#pragma unroll
            for (int nt = 0; nt < 4; nt++) {
                mma16(acc[mt][nt], ah, bhf[nt]);
                mma16(acc[mt][nt], ah, bmf[nt]);
                mma16(acc[mt][nt], am, bhf[nt]);
            }
        }
    }

    float p[4][2];
#pragma unroll
    for (int mt = 0; mt < 4; mt++) { p[mt][0] = 0.f; p[mt][1] = 0.f; }
#pragma unroll
    for (int mt = 0; mt < 4; mt++)
#pragma unroll
        for (int nt = 0; nt < 4; nt++) {
            acc[mt][nt][0] = fast_exp(acc[mt][nt][0] * 0.125f);
            acc[mt][nt][1] = fast_exp(acc[mt][nt][1] * 0.125f);
            acc[mt][nt][2] = fast_exp(acc[mt][nt][2] * 0.125f);
            acc[mt][nt][3] = fast_exp(acc[mt][nt][3] * 0.125f);
            p[mt][0] += acc[mt][nt][0] + acc[mt][nt][1];
            p[mt][1] += acc[mt][nt][2] + acc[mt][nt][3];
        }
#pragma unroll
    for (int o = 1; o <= 2; o <<= 1)
#pragma unroll
        for (int mt = 0; mt < 4; mt++) {
            p[mt][0] += __shfl_xor_sync(0xffffffffu, p[mt][0], o);
            p[mt][1] += __shfl_xor_sync(0xffffffffu, p[mt][1], o);
        }
    if (tig == 0) {
#pragma unroll
        for (int mt = 0; mt < 4; mt++)
#pragma unroll
            for (int j = 0; j < 2; j++) {
                int r = wm * 64 + mt * 16 + j * 8 + gid;
                rowsum[r * 4 + wn] = p[mt][j];
            }
    }
    __syncthreads();

    if (tid < 256) {
        float l = rowsum[tid * 4] + rowsum[tid * 4 + 1]
                + rowsum[tid * 4 + 2] + rowsum[tid * 4 + 3];
        lpart[(long long)(bh * 16 + kt) * SS + qt * 256 + tid] = l;
    }

#pragma unroll
    for (int mt = 0; mt < 4; mt++) {
        int r0 = wm * 64 + mt * 16 + gid;
#pragma unroll
        for (int nt = 0; nt < 4; nt++) {
            int col = wn * 32 + nt * 8 + tig * 2;
            *(__half2*)&smh[r0 * 136 + col] =
                __floats2half2_rn(acc[mt][nt][0], acc[mt][nt][1]);
            *(__half2*)&smh[(r0 + 8) * 136 + col] =
                __floats2half2_rn(acc[mt][nt][2], acc[mt][nt][3]);
        }
    }
    __syncthreads();

    __half* Cp = Esc + ((long long)bh * SS + qt * 256) * SS + kt * 128;
    const int u = tid & 15;
    const int rbase = tid >> 4;
#pragma unroll
    for (int i = 0; i < 8; i++) {
        int row = i * 32 + rbase;
        uint4 v = *(uint4*)&smh[row * 136 + u * 8];
        *(uint4*)&Cp[(long long)row * SS + u * 8] = v;
    }
}

// ---------------- combine: rinv = 1 / sum of partials ----------------------------
__global__ __launch_bounds__(256)
void combine_kernel(const float* __restrict__ lpart, float* __restrict__ rinv)
{
    int rowg = blockIdx.x * 256 + threadIdx.x;
    int bh = rowg >> 11, q = rowg & (SS - 1);
    float l = 0.f;
#pragma unroll
    for (int t = 0; t < 16; t++)
        l += lpart[(long long)(bh * 16 + t) * SS + q];
    rinv[rowg] = 1.0f / l;
}

// ---------------- head-averaged attention (fp16 stream MAC) ----------------------
__global__ __launch_bounds__(256)
void avg_kernel(const __half* __restrict__ Esc, const float* __restrict__ rinv,
                float* __restrict__ avg)
{
    const int q = blockIdx.x;
    const int b = blockIdx.y;
    const int tid = threadIdx.x;

    __shared__ float rw[HH];
    if (tid < HH) rw[tid] = rinv[((long long)(b * HH + tid) << 11) + q] * (1.0f / HH);
    __syncthreads();

    const __half* base = Esc + ((long long)(b * HH) * SS + q) * SS;
    const int k0 = tid * 8;
    float a0 = 0.f, a1 = 0.f, a2 = 0.f, a3 = 0.f;
    float a4 = 0.f, a5 = 0.f, a6 = 0.f, a7 = 0.f;
#pragma unroll
    for (int h = 0; h < HH; h++) {
        uint4 raw = *(const uint4*)(base + (long long)h * SS * SS + k0);
        float2 f0 = __half22float2(*(__half2*)&raw.x);
        float2 f1 = __half22float2(*(__half2*)&raw.y);
        float2 f2 = __half22float2(*(__half2*)&raw.z);
        float2 f3 = __half22float2(*(__half2*)&raw.w);
        float r = rw[h];
        a0 = fmaf(f0.x, r, a0); a1 = fmaf(f0.y, r, a1);
        a2 = fmaf(f1.x, r, a2); a3 = fmaf(f1.y, r, a3);
        a4 = fmaf(f2.x, r, a4); a5 = fmaf(f2.y, r, a5);
        a6 = fmaf(f3.x, r, a6); a7 = fmaf(f3.y, r, a7);
    }
    float* dst = avg + ((long long)b * SS + q) * SS + k0;
    float4 o0 = {a0, a1, a2, a3};
    float4 o1 = {a4, a5, a6, a7};
    *(float4*)&dst[0] = o0;
    *(float4*)&dst[4] = o1;
}

// ---------------- SIMT projection GEMM (V projection + final) ----------------------
#define PADW 132

__global__ __launch_bounds__(256, 2)
void proj_gemm(const float* __restrict__ A, const float* __restrict__ B,
               const float* __restrict__ bias, float* __restrict__ C,
               int N, int K, int lda, int ldb, int ldc)
{
    __shared__ __align__(16) float As[16 * PADW];
    __shared__ __align__(16) float Bs[16 * PADW];

    const int rowbase = blockIdx.y * 128;
    const int colbase = blockIdx.x * 128;
    const int tid = threadIdx.x;
    const int tx = tid & 15, ty = tid >> 4;
    const int row0 = ty * 8, col0 = tx * 8;

    float regA[8], regB[8];
    unsigned long long acc[8][4];
#pragma unroll
    for (int i = 0; i < 8; i++)
#pragma unroll
        for (int j = 0; j < 4; j++) acc[i][j] = 0ull;

#pragma unroll
    for (int i = 0; i < 8; i++) {
        int idx = tid + i * 256; int r = idx >> 4, kk = idx & 15;
        regA[i] = A[(long long)(rowbase + r) * lda + kk];
    }
#pragma unroll
    for (int i = 0; i < 8; i++) {
        int idx = tid + i * 256; int kk = idx >> 7, c = idx & 127;
        int col = colbase + c;
        regB[i] = (col < N) ? B[(long long)kk * ldb + col] : 0.f;
    }
#pragma unroll
    for (int i = 0; i < 8; i++) {
        int idx = tid + i * 256; int r = idx >> 4, kk = idx & 15;
        As[kk * PADW + r] = regA[i];
    }
#pragma unroll
    for (int i = 0; i < 8; i++) {
        int idx = tid + i * 256; int kk = idx >> 7, c = idx & 127;
        Bs[kk * PADW + c] = regB[i];
    }
    __syncthreads();

    for (int k0 = 16; ; k0 += 16) {
        const bool more = (k0 < K);
        if (more) {
#pragma unroll
            for (int i = 0; i < 8; i++) {
                int idx = tid + i * 256; int r = idx >> 4, kk = idx & 15;
                regA[i] = A[(long long)(rowbase + r) * lda + k0 + kk];
            }
#pragma unroll
            for (int i = 0; i < 8; i++) {
                int idx = tid + i * 256; int kk = idx >> 7, c = idx & 127;
                int col = colbase + c;
                regB[i] = (col < N) ? B[(long long)(k0 + kk) * ldb + col] : 0.f;
            }
        }
#pragma unroll
        for (int kk = 0; kk < 16; kk++) {
            float4 a0 = *(const float4*)&As[kk * PADW + row0];
            float4 a1 = *(const float4*)&As[kk * PADW + row0 + 4];
            float4 b0 = *(const float4*)&Bs[kk * PADW + col0];
            float4 b1 = *(const float4*)&Bs[kk * PADW + col0 + 4];
            float a[8] = {a0.x, a0.y, a0.z, a0.w, a1.x, a1.y, a1.z, a1.w};
            unsigned long long bp[4];
            bp[0] = pack2(b0.x, b0.y); bp[1] = pack2(b0.z, b0.w);
            bp[2] = pack2(b1.x, b1.y); bp[3] = pack2(b1.z, b1.w);
#pragma unroll
            for (int i = 0; i < 8; i++) {
                unsigned long long ap = pack2(a[i], a[i]);
#pragma unroll
                for (int j = 0; j < 4; j++) acc[i][j] = fma2(ap, bp[j], acc[i][j]);
            }
        }
        if (!more) break;
        __syncthreads();
#pragma unroll
        for (int i = 0; i < 8; i++) {
            int idx = tid + i * 256; int r = idx >> 4, kk = idx & 15;
            As[kk * PADW + r] = regA[i];
        }
#pragma unroll
        for (int i = 0; i < 8; i++) {
            int idx = tid + i * 256; int kk = idx >> 7, c = idx & 127;
            Bs[kk * PADW + c] = regB[i];
        }
        __syncthreads();
    }

#pragma unroll
    for (int i = 0; i < 8; i++) {
        int gr = rowbase + row0 + i;
#pragma unroll
        for (int j2 = 0; j2 < 4; j2 += 2) {
            int col = colbase + col0 + j2 * 2;
            if (col < N) {
                float4 v;
                unpack2(acc[i][j2],     v.x, v.y);
                unpack2(acc[i][j2 + 1], v.z, v.w);
                const float4 bb = *(const float4*)&bias[col];
                v.x += bb.x; v.y += bb.y; v.z += bb.z; v.w += bb.w;
                *(float4*)&C[(long long)gr * ldc + col] = v;
            }
        }
    }
}

// ---------------- avg @ V (split-K, packed fma2 + reg prefetch) ---------------------
__global__ __launch_bounds__(256)
void av_gemm(const float* __restrict__ avg, const float* __restrict__ V,
             float* __restrict__ part)
{
    __shared__ float As[16 * PADW];
    __shared__ float Bs[16 * 68];
    const int b = blockIdx.z;
    const int rowbase = blockIdx.y * 128;
    const int k0base = blockIdx.x * 256;
    const float* Ap = avg + ((long long)b * SS + rowbase) * SS;
    const float* Vp = V + (long long)b * SS * DK;
    const int tid = threadIdx.x;
    const int tx = tid & 15, ty = tid >> 4;

    unsigned long long acc[8][2];
#pragma unroll
    for (int i = 0; i < 8; i++) { acc[i][0] = 0ull; acc[i][1] = 0ull; }

    float regA[8], regB[4];
#pragma unroll
    for (int i = 0; i < 8; i++) {
        int idx = tid + i * 256; int r = idx >> 4, kk = idx & 15;
        regA[i] = Ap[(long long)r * SS + k0base + kk];
    }
#pragma unroll
    for (int i = 0; i < 4; i++) {
        int idx = tid + i * 256; int kk = idx >> 6, cc = idx & 63;
        regB[i] = Vp[(long long)(k0base + kk) * DK + cc];
    }

    for (int kc = 0; kc < 256; kc += 16) {
#pragma unroll
        for (int i = 0; i < 8; i++) {
            int idx = tid + i * 256; int r = idx >> 4, kk = idx & 15;
            As[kk * PADW + r] = regA[i];
        }
#pragma unroll
        for (int i = 0; i < 4; i++) {
            int idx = tid + i * 256; int kk = idx >> 6, cc = idx & 63;
            Bs[kk * 68 + cc] = regB[i];
        }
        __syncthreads();

        const bool more = (kc + 16 < 256);
        if (more) {
            const int k0 = k0base + kc + 16;
#pragma unroll
            for (int i = 0; i < 8; i++) {
                int idx = tid + i * 256; int r = idx >> 4, kk = idx & 15;
                regA[i] = Ap[(long long)r * SS + k0 + kk];
            }
#pragma unroll
            for (int i = 0; i < 4; i++) {
                int idx = tid + i * 256; int kk = idx >> 6, cc = idx & 63;
                regB[i] = Vp[(long long)(k0 + kk) * DK + cc];
            }
        }

#pragma unroll
        for (int kk = 0; kk < 16; kk++) {
            float a[8];
#pragma unroll
            for (int i = 0; i < 8; i++) a[i] = As[kk * PADW + ty * 8 + i];
            float4 bv = *(const float4*)&Bs[kk * 68 + tx * 4];
            unsigned long long b01 = pack2(bv.x, bv.y);
            unsigned long long b23 = pack2(bv.z, bv.w);
#pragma unroll
            for (int i = 0; i < 8; i++) {
                unsigned long long ap = pack2(a[i], a[i]);
                acc[i][0] = fma2(ap, b01, acc[i][0]);
                acc[i][1] = fma2(ap, b23, acc[i][1]);
            }
        }
        __syncthreads();
    }
    float* P = part + ((long long)(blockIdx.x * BB + b) * SS + rowbase) * DK;
#pragma unroll
    for (int i = 0; i < 8; i++) {
        float4 v;
        unpack2(acc[i][0], v.x, v.y);
        unpack2(acc[i][1], v.z, v.w);
        *(float4*)&P[(long long)(ty * 8 + i) * DK + tx * 4] = v;
    }
}

__global__ __launch_bounds__(256)
void av_reduce(const float* __restrict__ part, float* __restrict__ Ao)
{
    int i = blockIdx.x * 256 + threadIdx.x;
    float s = 0.f;
#pragma unroll
    for (int t = 0; t < 8; t++) s += part[(long long)t * (BB * SS * DK) + i];
    Ao[i] = s;
}

// ---------------- launch -------------------------------------------------------------
extern "C" void kernel_launch(void* const* d_in, const int* in_sizes, int n_in,
                              void* d_out, int out_size)
{
    const float* query = (const float*)d_in[0];
    const float* key_  = (const float*)d_in[1];
    const float* value = (const float*)d_in[2];
    const float* Wq    = (const float*)d_in[3];
    const float* bq    = (const float*)d_in[4];
    const float* Wk    = (const float*)d_in[5];
    const float* bk    = (const float*)d_in[6];
    const float* Wv    = (const float*)d_in[7];
    const float* bv    = (const float*)d_in[8];
    const float* Wo    = (const float*)d_in[9];
    const float* bo    = (const float*)d_in[10];

    float* out_main = (float*)d_out;
    float* out_avg  = out_main + (size_t)ROWS * DM;

    uint4 *Xq, *Xk, *Wtq, *Wtk, *Qpk, *Kpk;
    __half* Esc;
    float *Vp, *Lp, *Rv, *Ao, *Av;
    cudaGetSymbolAddress((void**)&Xq, g_Xq);
    cudaGetSymbolAddress((void**)&Xk, g_Xk);
    cudaGetSymbolAddress((void**)&Wtq, g_Wtq);
    cudaGetSymbolAddress((void**)&Wtk, g_Wtk);
    cudaGetSymbolAddress((void**)&Qpk, g_Qpk);
    cudaGetSymbolAddress((void**)&Kpk, g_Kpk);
    cudaGetSymbolAddress((void**)&Vp, g_Vp);
    cudaGetSymbolAddress((void**)&Esc, g_escore);
    cudaGetSymbolAddress((void**)&Lp, g_lpart);
    cudaGetSymbolAddress((void**)&Rv, g_rinv);
    cudaGetSymbolAddress((void**)&Ao, g_ao);
    cudaGetSymbolAddress((void**)&Av, g_avpart);

    const int smemP = 2 * 98304;
    const int smem1 = 384 * 16 * 16 + 256 * 4 * 4;
    cudaFuncSetAttribute(proj_mma, cudaFuncAttributeMaxDynamicSharedMemorySize, smemP);
    cudaFuncSetAttribute(mma_pass1, cudaFuncAttributeMaxDynamicSharedMemorySize, smem1);

    // one-time side streams/events for graph-captured fork/join (no device memory)
    static cudaStream_t sK = nullptr, sV = nullptr;
    static cudaEvent_t evRoot = nullptr, evK = nullptr, evV = nullptr;
    if (sK == nullptr) {
        cudaStreamCreateWithFlags(&sK, cudaStreamNonBlocking);
        cudaStreamCreateWithFlags(&sV, cudaStreamNonBlocking);
        cudaEventCreateWithFlags(&evRoot, cudaEventDisableTiming);
        cudaEventCreateWithFlags(&evK, cudaEventDisableTiming);
        cudaEventCreateWithFlags(&evV, cudaEventDisableTiming);
    }

    dim3 blk(256);

    // fork: K path and V path branch off the main (captured) stream
    cudaEventRecord(evRoot, 0);
    cudaStreamWaitEvent(sK, evRoot, 0);
    cudaStreamWaitEvent(sV, evRoot, 0);

    // main stream: Q path
    split_x<<<ROWS, blk>>>(query, Xq);
    split_w<<<dim3(16, 16), blk>>>(Wq, Wtq);
    proj_mma<<<dim3(8, 16), 512, smemP>>>(Xq, Wtq, bq, Qpk);

    // sK: K path (concurrent with Q path)
    split_x<<<ROWS, blk, 0, sK>>>(key_, Xk);
    split_w<<<dim3(16, 16), blk, 0, sK>>>(Wk, Wtk);
    proj_mma<<<dim3(8, 16), 512, smemP, sK>>>(Xk, Wtk, bk, Kpk);
    cudaEventRecord(evK, sK);

    // sV: V projection (concurrent)
    proj_gemm<<<dim3(1, 32), blk, 0, sV>>>(value, Wv, bv, Vp, DK, DM, DM, DK, DK);
    cudaEventRecord(evV, sV);

    // join K before pass1 (Q already ordered on main stream)
    cudaStreamWaitEvent(0, evK, 0);

    // pass1: scores -> fp16 exp + sumexp partials
    mma_pass1<<<dim3(16, 8, BB * HH), 512, smem1>>>(Qpk, Kpk, Esc, Lp);

    // combine partials -> 1/l
    combine_kernel<<<dim3(BB * HH * SS / 256, 1, 1), blk>>>(Lp, Rv);

    // head-averaged attention -> second output
    avg_kernel<<<dim3(SS, BB, 1), blk>>>(Esc, Rv, out_avg);

    // join V before av_gemm
    cudaStreamWaitEvent(0, evV, 0);

    // attn_output = avg @ V (split-K=8, fma2)
    av_gemm<<<dim3(8, 16, BB), blk>>>(out_avg, Vp, Av);
    av_reduce<<<dim3(BB * SS * DK / 256, 1, 1), blk>>>(Av, Ao);

    // output = attn_output @ Wo + bo
    proj_gemm<<<dim3(8, 32), blk>>>(Ao, Wo, bo, out_main, DM, DK, DK, DM, DM);
}

// round 14
// speedup vs baseline: 2.1334x; 1.0409x over previous
#include <cuda_runtime.h>
#include <cuda_fp16.h>
#include <cstdint>

#define BB 2
#define SS 2048
#define HH 16
#define DK 64
#define DM 1024
#define ROWS (BB*SS)          // 4096

// ---------------- scratch -----------------------------------------------------
__device__ uint4 g_Xq[(size_t)ROWS*256];          // split query  [4096][256]
__device__ uint4 g_Xk[(size_t)ROWS*256];
__device__ uint4 g_Wtq[(size_t)DM*256];           // split Wq^T   [1024][256]
__device__ uint4 g_Wtk[(size_t)DM*256];
__device__ uint4 g_Qpk[(size_t)BB*HH*SS*16];      // head-layout packed Q
__device__ uint4 g_Kpk[(size_t)BB*HH*SS*16];
__device__ float g_Vp[(size_t)ROWS*DK];
__device__ __half g_escore[(size_t)BB*HH*SS*SS];  // exp(s/8) fp16 (268 MB)
__device__ float g_lpart[(size_t)BB*HH*16*SS];
__device__ float g_rinv[(size_t)BB*HH*SS];
__device__ float g_avpart[(size_t)8*BB*SS*DK];
__device__ uint4 g_Aopk[(size_t)ROWS*16];         // packed attn_output [4096][16]
__device__ uint4 g_Wto[(size_t)DM*16];            // packed Wo^T [1024][16]

// ---------------- helpers -------------------------------------------------------
// exp via bits-trick; valid for |x| <~ 80 (scores are |x|<=~8)
__device__ __forceinline__ float fast_exp(float x) {
    float t = fmaf(x, 1.4426950408889634f, 12582912.0f);
    uint32_t ti = __float_as_uint(t);
    float n = t - 12582912.0f;
    float f = fmaf(x, 1.4426950408889634f, -n);
    float p = 1.3333558146e-3f;
    p = fmaf(p, f, 9.6178371906e-3f);
    p = fmaf(p, f, 5.5502813330e-2f);
    p = fmaf(p, f, 2.4022650695e-1f);
    p = fmaf(p, f, 6.9314718056e-1f);
    p = fmaf(p, f, 1.0f);
    return __uint_as_float(__float_as_uint(p) + (ti << 23));
}

__device__ __forceinline__ unsigned long long pack2(float lo, float hi) {
    unsigned long long r;
    asm("mov.b64 %0, {%1, %2};" : "=l"(r) : "f"(lo), "f"(hi));
    return r;
}
__device__ __forceinline__ void unpack2(unsigned long long v, float& lo, float& hi) {
    asm("mov.b64 {%0, %1}, %2;" : "=f"(lo), "=f"(hi) : "l"(v));
}
__device__ __forceinline__ unsigned long long fma2(unsigned long long a,
                                                   unsigned long long b,
                                                   unsigned long long c) {
    unsigned long long d;
    asm("fma.rn.f32x2 %0, %1, %2, %3;" : "=l"(d) : "l"(a), "l"(b), "l"(c));
    return d;
}

__device__ __forceinline__ uint32_t bf16pack(float lo, float hi) {
    uint32_t r;
    asm("cvt.rn.bf16x2.f32 %0, %1, %2;" : "=r"(r) : "f"(hi), "f"(lo));
    return r;
}

__device__ __forceinline__ uint2 himid(float v0, float v1) {
    uint32_t hp = bf16pack(v0, v1);
    uint32_t mp = bf16pack(v0 - __uint_as_float(hp << 16),
                           v1 - __uint_as_float(hp & 0xffff0000u));
    uint2 o = {hp, mp};
    return o;
}

__device__ __forceinline__ void mma16(float* c, const uint32_t* a, const uint32_t* b) {
    asm volatile("mma.sync.aligned.m16n8k16.row.col.f32.bf16.bf16.f32 "
        "{%0,%1,%2,%3}, {%4,%5,%6,%7}, {%8,%9}, {%0,%1,%2,%3};"
        : "+f"(c[0]), "+f"(c[1]), "+f"(c[2]), "+f"(c[3])
        : "r"(a[0]), "r"(a[1]), "r"(a[2]), "r"(a[3]), "r"(b[0]), "r"(b[1]));
}

__device__ __forceinline__ uint32_t smem_u32(const void* p) {
    uint32_t a;
    asm("{ .reg .u64 t; cvta.to.shared.u64 t, %1; cvt.u32.u64 %0, t; }" : "=r"(a) : "l"(p));
    return a;
}

__device__ __forceinline__ void cp_async16(uint32_t dst, const void* src) {
    asm volatile("cp.async.cg.shared.global [%0], [%1], 16;" :: "r"(dst), "l"(src) : "memory");
}
__device__ __forceinline__ void cp_commit() {
    asm volatile("cp.async.commit_group;" ::: "memory");
}
template <int N>
__device__ __forceinline__ void cp_wait() {
    asm volatile("cp.async.wait_group %0;" :: "n"(N) : "memory");
}

#define FSWZ(r, f) ((f) ^ (((r) & 1) << 2))

// ---------------- input split kernels ---------------------------------------------
__global__ __launch_bounds__(256)
void split_x(const float* __restrict__ X, uint4* __restrict__ out)
{
    int g = blockIdx.x * 256 + threadIdx.x;
    int r = g >> 8, f = g & 255;
    int k = (f >> 2) * 16 + (f & 3) * 2;
    const float* xp = X + (long long)r * DM + k;
    uint2 a = himid(xp[0], xp[1]);
    uint2 b = himid(xp[8], xp[9]);
    uint4 o = {a.x, a.y, b.x, b.y};
    out[g] = o;
}

__global__ __launch_bounds__(256)
void split_w(const float* __restrict__ W, uint4* __restrict__ out)
{
    __shared__ float ws[64][65];
    const int tid = threadIdx.x;
    const int kb = blockIdx.y * 64, nb = blockIdx.x * 64;
#pragma unroll
    for (int i = 0; i < 16; i++) {
        int idx = tid + i * 256; int kk = idx >> 6, nn = idx & 63;
        ws[kk][nn] = W[(long long)(kb + kk) * DM + nb + nn];
    }
    __syncthreads();
#pragma unroll
    for (int i = 0; i < 4; i++) {
        int idx = tid + i * 256; int nn = idx >> 4, f = idx & 15;
        int kk = (f >> 2) * 16 + (f & 3) * 2;
        uint2 a = himid(ws[kk][nn], ws[kk + 1][nn]);
        uint2 b = himid(ws[kk + 8][nn], ws[kk + 9][nn]);
        uint4 o = {a.x, a.y, b.x, b.y};
        out[(long long)(nb + nn) * 256 + (kb >> 2) + f] = o;
    }
}

// split Wo [64,1024] -> packed WoT [1024][16]
__global__ __launch_bounds__(256)
void split_wo(const float* __restrict__ W, uint4* __restrict__ out)
{
    __shared__ float ws[64][65];
    const int tid = threadIdx.x;
    const int nb = blockIdx.x * 64;
#pragma unroll
    for (int i = 0; i < 16; i++) {
        int idx = tid + i * 256; int kk = idx >> 6, nn = idx & 63;
        ws[kk][nn] = W[(long long)kk * DM + nb + nn];
    }
    __syncthreads();
#pragma unroll
    for (int i = 0; i < 4; i++) {
        int idx = tid + i * 256; int nn = idx >> 4, f = idx & 15;
        int kk = (f >> 2) * 16 + (f & 3) * 2;
        uint2 a = himid(ws[kk][nn], ws[kk + 1][nn]);
        uint2 b = himid(ws[kk + 8][nn], ws[kk + 9][nn]);
        uint4 o = {a.x, a.y, b.x, b.y};
        out[(long long)(nb + nn) * 16 + f] = o;
    }
}

// ---------------- Q/K projection via bf16-split MMA + cp.async pipeline ------------
__global__ __launch_bounds__(512, 1)
void proj_mma(const uint4* __restrict__ Xpk, const uint4* __restrict__ Wt,
              const float* __restrict__ bias, uint4* __restrict__ Cpk)
{
    extern __shared__ uint4 smq[];
    const uint32_t smb = smem_u32(smq);

    const int tid = threadIdx.x;
    const int colbase = blockIdx.x * 128;
    const int rowbase = blockIdx.y * 256;
    const int wid = tid >> 5, lane = tid & 31;
    const int wm = wid >> 2, wn = wid & 3;
    const int gid = lane >> 2, tig = lane & 3;

    float acc[4][4][4];
#pragma unroll
    for (int mt = 0; mt < 4; mt++)
#pragma unroll
        for (int nt = 0; nt < 4; nt++)
#pragma unroll
            for (int c = 0; c < 4; c++) acc[mt][nt][c] = 0.f;

    auto issue = [&](int kc, int s) {
        uint32_t base = smb + s * 98304;
#pragma unroll
        for (int i = 0; i < 8; i++) {
            int idx = tid + i * 512; int r = idx >> 4, f = idx & 15;
            cp_async16(base + (uint32_t)(r * 16 + FSWZ(r, f)) * 16,
                       &Xpk[(long long)(rowbase + r) * 256 + kc * 16 + f]);
        }
#pragma unroll
        for (int i = 0; i < 4; i++) {
            int idx = tid + i * 512; int r = idx >> 4, f = idx & 15;
            cp_async16(base + 65536u + (uint32_t)(r * 16 + FSWZ(r, f)) * 16,
                       &Wt[(long long)(colbase + r) * 256 + kc * 16 + f]);
        }
        cp_commit();
    };

    issue(0, 0);

    for (int kc = 0; kc < 16; kc++) {
        const int s = kc & 1;
        if (kc < 15) { issue(kc + 1, s ^ 1); cp_wait<1>(); }
        else cp_wait<0>();
        __syncthreads();

        const uint4* Xs = smq + s * 6144;
        const uint4* Ws = Xs + 4096;
#pragma unroll
        for (int k16 = 0; k16 < 4; k16++) {
            const int f = k16 * 4 + tig;
            uint32_t bhf[4][2], bmf[4][2];
#pragma unroll
            for (int nt = 0; nt < 4; nt++) {
                int row = wn * 32 + nt * 8 + gid;
                uint4 kv = Ws[row * 16 + FSWZ(row, f)];
                bhf[nt][0] = kv.x; bhf[nt][1] = kv.z;
                bmf[nt][0] = kv.y; bmf[nt][1] = kv.w;
            }
#pragma unroll
            for (int mt = 0; mt < 4; mt++) {
                int r0 = wm * 64 + mt * 16 + gid;
                int r1 = r0 + 8;
                uint4 qa = Xs[r0 * 16 + FSWZ(r0, f)];
                uint4 qb = Xs[r1 * 16 + FSWZ(r1, f)];
                uint32_t ah[4], am[4];
                ah[0] = qa.x; ah[1] = qb.x; ah[2] = qa.z; ah[3] = qb.z;
                am[0] = qa.y; am[1] = qb.y; am[2] = qa.w; am[3] = qb.w;
#pragma unroll
                for (int nt = 0; nt < 4; nt++) {
                    mma16(acc[mt][nt], ah, bhf[nt]);
                    mma16(acc[mt][nt], ah, bmf[nt]);
                    mma16(acc[mt][nt], am, bhf[nt]);
                }
            }
        }
        __syncthreads();
    }

    const int nb = colbase + wn * 32;
    const int h = nb >> 6;
    const int db = nb & 63;
#pragma unroll
    for (int ntp = 0; ntp < 2; ntp++) {
        int cb = nb + ntp * 16 + tig * 2;
        float b0 = bias[cb],     b1 = bias[cb + 1];
        float b2 = bias[cb + 8], b3 = bias[cb + 9];
        int k16o = (db >> 4) + ntp;
#pragma unroll
        for (int mt = 0; mt < 4; mt++) {
#pragma unroll
            for (int rr = 0; rr < 2; rr++) {
                int gr = rowbase + wm * 64 + mt * 16 + rr * 8 + gid;
                int b = gr >> 11, s = gr & (SS - 1);
                uint2 lo = himid(acc[mt][2 * ntp][rr * 2] + b0,
                                 acc[mt][2 * ntp][rr * 2 + 1] + b1);
                uint2 hi = himid(acc[mt][2 * ntp + 1][rr * 2] + b2,
                                 acc[mt][2 * ntp + 1][rr * 2 + 1] + b3);
                uint4 o = {lo.x, lo.y, hi.x, hi.y};
                Cpk[((long long)((b * HH + h) * SS + s)) * 16 + k16o * 4 + tig] = o;
            }
        }
    }
}

// ---------------- pass 1: 256x128 tile, bf16-split MMA -> fp16 exp + sumexp --------
__global__ __launch_bounds__(512, 1)
void mma_pass1(const uint4* __restrict__ Qpk, const uint4* __restrict__ Kpk,
               __half* __restrict__ Esc, float* __restrict__ lpart)
{
    extern __shared__ uint4 smq[];
    uint4* Qs = smq;                          // [256][16]
    uint4* Ks = Qs + 256 * 16;                // [128][16]
    float* rowsum = (float*)(smq + 384 * 16); // [256][4]
    __half* smh = (__half*)smq;               // epilogue staging

    const int tid = threadIdx.x;
    const int kt = blockIdx.x, qt = blockIdx.y, bh = blockIdx.z;
    const long long qbase = ((long long)bh * SS + qt * 256) * 16;
    const long long kbase = ((long long)bh * SS + kt * 128) * 16;

#pragma unroll
    for (int i = 0; i < 8; i++) {
        int idx = tid + i * 512;
        int r = idx >> 4, f = idx & 15;
        Qs[r * 16 + FSWZ(r, f)] = Qpk[qbase + r * 16 + f];
    }
#pragma unroll
    for (int i = 0; i < 4; i++) {
        int idx = tid + i * 512;
        int r = idx >> 4, f = idx & 15;
        Ks[r * 16 + FSWZ(r, f)] = Kpk[kbase + r * 16 + f];
    }
    __syncthreads();

    const int wid = tid >> 5, lane = tid & 31;
    const int wm = wid >> 2, wn = wid & 3;
    const int gid = lane >> 2, tig = lane & 3;

    float acc[4][4][4];
#pragma unroll
    for (int mt = 0; mt < 4; mt++)
#pragma unroll
        for (int nt = 0; nt < 4; nt++)
#pragma unroll
            for (int c = 0; c < 4; c++) acc[mt][nt][c] = 0.f;

#pragma unroll
    for (int k16 = 0; k16 < 4; k16++) {
        const int f = k16 * 4 + tig;
        uint32_t bhf[4][2], bmf[4][2];
#pragma unroll
        for (int nt = 0; nt < 4; nt++) {
            int row = wn * 32 + nt * 8 + gid;
            uint4 kv = Ks[row * 16 + FSWZ(row, f)];
            bhf[nt][0] = kv.x; bhf[nt][1] = kv.z;
            bmf[nt][0] = kv.y; bmf[nt][1] = kv.w;
        }
#pragma unroll
        for (int mt = 0; mt < 4; mt++) {
            int r0 = wm * 64 + mt * 16 + gid;
            int r1 = r0 + 8;
            uint4 qa = Qs[r0 * 16 + FSWZ(r0, f)];
            uint4 qb = Qs[r1 * 16 + FSWZ(r1, f)];
            uint32_t ah[4], am[4];
            ah[0] = qa.x; ah[1] = qb.x; ah[2] = qa.z; ah[3] = qb.z;
            am[0] = qa.y; am[1] = qb.y; am[2] = qa.w; am[3] = qb.w;
#pragma unroll
            for (int nt = 0; nt < 4; nt++) {
                mma16(acc[mt][nt], ah, bhf[nt]);
                mma16(acc[mt][nt], ah, bmf[nt]);
                mma16(acc[mt][nt], am, bhf[nt]);
            }
        }
    }

    float p[4][2];
#pragma unroll
    for (int mt = 0; mt < 4; mt++) { p[mt][0] = 0.f; p[mt][1] = 0.f; }
#pragma unroll
    for (int mt = 0; mt < 4; mt++)
#pragma unroll
        for (int nt = 0; nt < 4; nt++) {
            acc[mt][nt][0] = fast_exp(acc[mt][nt][0] * 0.125f);
            acc[mt][nt][1] = fast_exp(acc[mt][nt][1] * 0.125f);
            acc[mt][nt][2] = fast_exp(acc[mt][nt][2] * 0.125f);
            acc[mt][nt][3] = fast_exp(acc[mt][nt][3] * 0.125f);
            p[mt][0] += acc[mt][nt][0] + acc[mt][nt][1];
            p[mt][1] += acc[mt][nt][2] + acc[mt][nt][3];
        }
#pragma unroll
    for (int o = 1; o <= 2; o <<= 1)
#pragma unroll
        for (int mt = 0; mt < 4; mt++) {
            p[mt][0] += __shfl_xor_sync(0xffffffffu, p[mt][0], o);
            p[mt][1] += __shfl_xor_sync(0xffffffffu, p[mt][1], o);
        }
    if (tig == 0) {
#pragma unroll
        for (int mt = 0; mt < 4; mt++)
#pragma unroll
            for (int j = 0; j < 2; j++) {
                int r = wm * 64 + mt * 16 + j * 8 + gid;
                rowsum[r * 4 + wn] = p[mt][j];
            }
    }
    __syncthreads();

    if (tid < 256) {
        float l = rowsum[tid * 4] + rowsum[tid * 4 + 1]
                + rowsum[tid * 4 + 2] + rowsum[tid * 4 + 3];
        lpart[(long long)(bh * 16 + kt) * SS + qt * 256 + tid] = l;
    }

#pragma unroll
    for (int mt = 0; mt < 4; mt++) {
        int r0 = wm * 64 + mt * 16 + gid;
#pragma unroll
        for (int nt = 0; nt < 4; nt++) {
            int col = wn * 32 + nt * 8 + tig * 2;
            *(__half2*)&smh[r0 * 136 + col] =
                __floats2half2_rn(acc[mt][nt][0], acc[mt][nt][1]);
            *(__half2*)&smh[(r0 + 8) * 136 + col] =
                __floats2half2_rn(acc[mt][nt][2], acc[mt][nt][3]);
        }
    }
    __syncthreads();

    __half* Cp = Esc + ((long long)bh * SS + qt * 256) * SS + kt * 128;
    const int u = tid & 15;
    const int rbase = tid >> 4;
#pragma unroll
    for (int i = 0; i < 8; i++) {
        int row = i * 32 + rbase;
        uint4 v = *(uint4*)&smh[row * 136 + u * 8];
        *(uint4*)&Cp[(long long)row * SS + u * 8] = v;
    }
}

// ---------------- combine: rinv = 1 / sum of partials ----------------------------
__global__ __launch_bounds__(256)
void combine_kernel(const float* __restrict__ lpart, float* __restrict__ rinv)
{
    int rowg = blockIdx.x * 256 + threadIdx.x;
    int bh = rowg >> 11, q = rowg & (SS - 1);
    float l = 0.f;
#pragma unroll
    for (int t = 0; t < 16; t++)
        l += lpart[(long long)(bh * 16 + t) * SS + q];
    rinv[rowg] = 1.0f / l;
}

// ---------------- head-averaged attention (fp16 stream MAC) ----------------------
__global__ __launch_bounds__(256)
void avg_kernel(const __half* __restrict__ Esc, const float* __restrict__ rinv,
                float* __restrict__ avg)
{
    const int q = blockIdx.x;
    const int b = blockIdx.y;
    const int tid = threadIdx.x;

    __shared__ float rw[HH];
    if (tid < HH) rw[tid] = rinv[((long long)(b * HH + tid) << 11) + q] * (1.0f / HH);
    __syncthreads();

    const __half* base = Esc + ((long long)(b * HH) * SS + q) * SS;
    const int k0 = tid * 8;
    float a0 = 0.f, a1 = 0.f, a2 = 0.f, a3 = 0.f;
    float a4 = 0.f, a5 = 0.f, a6 = 0.f, a7 = 0.f;
#pragma unroll
    for (int h = 0; h < HH; h++) {
        uint4 raw = *(const uint4*)(base + (long long)h * SS * SS + k0);
        float2 f0 = __half22float2(*(__half2*)&raw.x);
        float2 f1 = __half22float2(*(__half2*)&raw.y);
        float2 f2 = __half22float2(*(__half2*)&raw.z);
        float2 f3 = __half22float2(*(__half2*)&raw.w);
        float r = rw[h];
        a0 = fmaf(f0.x, r, a0); a1 = fmaf(f0.y, r, a1);
        a2 = fmaf(f1.x, r, a2); a3 = fmaf(f1.y, r, a3);
        a4 = fmaf(f2.x, r, a4); a5 = fmaf(f2.y, r, a5);
        a6 = fmaf(f3.x, r, a6); a7 = fmaf(f3.y, r, a7);
    }
    float* dst = avg + ((long long)b * SS + q) * SS + k0;
    float4 o0 = {a0, a1, a2, a3};
    float4 o1 = {a4, a5, a6, a7};
    *(float4*)&dst[0] = o0;
    *(float4*)&dst[4] = o1;
}

// ---------------- SIMT projection GEMM (V projection) -------------------------------
#define PADW 132

__global__ __launch_bounds__(256, 2)
void proj_gemm(const float* __restrict__ A, const float* __restrict__ B,
               const float* __restrict__ bias, float* __restrict__ C,
               int N, int K, int lda, int ldb, int ldc)
{
    __shared__ __align__(16) float As[16 * PADW];
    __shared__ __align__(16) float Bs[16 * PADW];

    const int rowbase = blockIdx.y * 128;
    const int colbase = blockIdx.x * 128;
    const int tid = threadIdx.x;
    const int tx = tid & 15, ty = tid >> 4;
    const int row0 = ty * 8, col0 = tx * 8;

    float regA[8], regB[8];
    unsigned long long acc[8][4];
#pragma unroll
    for (int i = 0; i < 8; i++)
#pragma unroll
        for (int j = 0; j < 4; j++) acc[i][j] = 0ull;

#pragma unroll
    for (int i = 0; i < 8; i++) {
        int idx = tid + i * 256; int r = idx >> 4, kk = idx & 15;
        regA[i] = A[(long long)(rowbase + r) * lda + kk];
    }
#pragma unroll
    for (int i = 0; i < 8; i++) {
        int idx = tid + i * 256; int kk = idx >> 7, c = idx & 127;
        int col = colbase + c;
        regB[i] = (col < N) ? B[(long long)kk * ldb + col] : 0.f;
    }
#pragma unroll
    for (int i = 0; i < 8; i++) {
        int idx = tid + i * 256; int r = idx >> 4, kk = idx & 15;
        As[kk * PADW + r] = regA[i];
    }
#pragma unroll
    for (int i = 0; i < 8; i++) {
        int idx = tid + i * 256; int kk = idx >> 7, c = idx & 127;
        Bs[kk * PADW + c] = regB[i];
    }
    __syncthreads();

    for (int k0 = 16; ; k0 += 16) {
        const bool more = (k0 < K);
        if (more) {
#pragma unroll
            for (int i = 0; i < 8; i++) {
                int idx = tid + i * 256; int r = idx >> 4, kk = idx & 15;
                regA[i] = A[(long long)(rowbase + r) * lda + k0 + kk];
            }
#pragma unroll
            for (int i = 0; i < 8; i++) {
                int idx = tid + i * 256; int kk = idx >> 7, c = idx & 127;
                int col = colbase + c;
                regB[i] = (col < N) ? B[(long long)(k0 + kk) * ldb + col] : 0.f;
            }
        }
#pragma unroll
        for (int kk = 0; kk < 16; kk++) {
            float4 a0 = *(const float4*)&As[kk * PADW + row0];
            float4 a1 = *(const float4*)&As[kk * PADW + row0 + 4];
            float4 b0 = *(const float4*)&Bs[kk * PADW + col0];
            float4 b1 = *(const float4*)&Bs[kk * PADW + col0 + 4];
            float a[8] = {a0.x, a0.y, a0.z, a0.w, a1.x, a1.y, a1.z, a1.w};
            unsigned long long bp[4];
            bp[0] = pack2(b0.x, b0.y); bp[1] = pack2(b0.z, b0.w);
            bp[2] = pack2(b1.x, b1.y); bp[3] = pack2(b1.z, b1.w);
#pragma unroll
            for (int i = 0; i < 8; i++) {
                unsigned long long ap = pack2(a[i], a[i]);
#pragma unroll
                for (int j = 0; j < 4; j++) acc[i][j] = fma2(ap, bp[j], acc[i][j]);
            }
        }
        if (!more) break;
        __syncthreads();
#pragma unroll
        for (int i = 0; i < 8; i++) {
            int idx = tid + i * 256; int r = idx >> 4, kk = idx & 15;
            As[kk * PADW + r] = regA[i];
        }
#pragma unroll
        for (int i = 0; i < 8; i++) {
            int idx = tid + i * 256; int kk = idx >> 7, c = idx & 127;
            Bs[kk * PADW + c] = regB[i];
        }
        __syncthreads();
    }

#pragma unroll
    for (int i = 0; i < 8; i++) {
        int gr = rowbase + row0 + i;
#pragma unroll
        for (int j2 = 0; j2 < 4; j2 += 2) {
            int col = colbase + col0 + j2 * 2;
            if (col < N) {
                float4 v;
                unpack2(acc[i][j2],     v.x, v.y);
                unpack2(acc[i][j2 + 1], v.z, v.w);
                const float4 bb = *(const float4*)&bias[col];
                v.x += bb.x; v.y += bb.y; v.z += bb.z; v.w += bb.w;
                *(float4*)&C[(long long)gr * ldc + col] = v;
            }
        }
    }
}

// ---------------- avg @ V (split-K, packed fma2 + reg prefetch) ---------------------
__global__ __launch_bounds__(256)
void av_gemm(const float* __restrict__ avg, const float* __restrict__ V,
             float* __restrict__ part)
{
    __shared__ float As[16 * PADW];
    __shared__ float Bs[16 * 68];
    const int b = blockIdx.z;
    const int rowbase = blockIdx.y * 128;
    const int k0base = blockIdx.x * 256;
    const float* Ap = avg + ((long long)b * SS + rowbase) * SS;
    const float* Vp = V + (long long)b * SS * DK;
    const int tid = threadIdx.x;
    const int tx = tid & 15, ty = tid >> 4;

    unsigned long long acc[8][2];
#pragma unroll
    for (int i = 0; i < 8; i++) { acc[i][0] = 0ull; acc[i][1] = 0ull; }

    float regA[8], regB[4];
#pragma unroll
    for (int i = 0; i < 8; i++) {
        int idx = tid + i * 256; int r = idx >> 4, kk = idx & 15;
        regA[i] = Ap[(long long)r * SS + k0base + kk];
    }
#pragma unroll
    for (int i = 0; i < 4; i++) {
        int idx = tid + i * 256; int kk = idx >> 6, cc = idx & 63;
        regB[i] = Vp[(long long)(k0base + kk) * DK + cc];
    }

    for (int kc = 0; kc < 256; kc += 16) {
#pragma unroll
        for (int i = 0; i < 8; i++) {
            int idx = tid + i * 256; int r = idx >> 4, kk = idx & 15;
            As[kk * PADW + r] = regA[i];
        }
#pragma unroll
        for (int i = 0; i < 4; i++) {
            int idx = tid + i * 256; int kk = idx >> 6, cc = idx & 63;
            Bs[kk * 68 + cc] = regB[i];
        }
        __syncthreads();

        const bool more = (kc + 16 < 256);
        if (more) {
            const int k0 = k0base + kc + 16;
#pragma unroll
            for (int i = 0; i < 8; i++) {
                int idx = tid + i * 256; int r = idx >> 4, kk = idx & 15;
                regA[i] = Ap[(long long)r * SS + k0 + kk];
            }
#pragma unroll
            for (int i = 0; i < 4; i++) {
                int idx = tid + i * 256; int kk = idx >> 6, cc = idx & 63;
                regB[i] = Vp[(long long)(k0 + kk) * DK + cc];
            }
        }

#pragma unroll
        for (int kk = 0; kk < 16; kk++) {
            float a[8];
#pragma unroll
            for (int i = 0; i < 8; i++) a[i] = As[kk * PADW + ty * 8 + i];
            float4 bv = *(const float4*)&Bs[kk * 68 + tx * 4];
            unsigned long long b01 = pack2(bv.x, bv.y);
            unsigned long long b23 = pack2(bv.z, bv.w);
#pragma unroll
            for (int i = 0; i < 8; i++) {
                unsigned long long ap = pack2(a[i], a[i]);
                acc[i][0] = fma2(ap, b01, acc[i][0]);
                acc[i][1] = fma2(ap, b23, acc[i][1]);
            }
        }
        __syncthreads();
    }
    float* P = part + ((long long)(blockIdx.x * BB + b) * SS + rowbase) * DK;
#pragma unroll
    for (int i = 0; i < 8; i++) {
        float4 v;
        unpack2(acc[i][0], v.x, v.y);
        unpack2(acc[i][1], v.z, v.w);
        *(float4*)&P[(long long)(ty * 8 + i) * DK + tx * 4] = v;
    }
}

// reduce split-K partials and emit packed bf16 hi/mid Ao
__global__ __launch_bounds__(256)
void av_reduce_pack(const float* __restrict__ part, uint4* __restrict__ Aopk)
{
    int g = blockIdx.x * 256 + threadIdx.x;       // over ROWS*16
    int r = g >> 4, f = g & 15;
    int k = (f >> 2) * 16 + (f & 3) * 2;
    float v0 = 0.f, v1 = 0.f, v8 = 0.f, v9 = 0.f;
#pragma unroll
    for (int t = 0; t < 8; t++) {
        const float* p = part + (long long)t * (BB * SS * DK) + (long long)r * DK + k;
        float2 a = *(const float2*)p;
        float2 b = *(const float2*)(p + 8);
        v0 += a.x; v1 += a.y; v8 += b.x; v9 += b.y;
    }
    uint2 lo = himid(v0, v1);
    uint2 hi = himid(v8, v9);
    uint4 o = {lo.x, lo.y, hi.x, hi.y};
    Aopk[g] = o;
}

// ---------------- final GEMM: out = Ao @ Wo + bo via bf16-split MMA ------------------
__global__ __launch_bounds__(512, 1)
void out_mma(const uint4* __restrict__ Aopk, const uint4* __restrict__ Wto,
             const float* __restrict__ bias, float* __restrict__ C)
{
    extern __shared__ uint4 smq[];
    uint4* Xs = smq;                 // [256][16]
    uint4* Ws = Xs + 256 * 16;       // [128][16]

    const int tid = threadIdx.x;
    const int colbase = blockIdx.x * 128;
    const int rowbase = blockIdx.y * 256;
    const int wid = tid >> 5, lane = tid & 31;
    const int wm = wid >> 2, wn = wid & 3;
    const int gid = lane >> 2, tig = lane & 3;

#pragma unroll
    for (int i = 0; i < 8; i++) {
        int idx = tid + i * 512; int r = idx >> 4, f = idx & 15;
        Xs[r * 16 + FSWZ(r, f)] = Aopk[(long long)(rowbase + r) * 16 + f];
    }
#pragma unroll
    for (int i = 0; i < 4; i++) {
        int idx = tid + i * 512; int r = idx >> 4, f = idx & 15;
        Ws[r * 16 + FSWZ(r, f)] = Wto[(long long)(colbase + r) * 16 + f];
    }
    __syncthreads();

    float acc[4][4][4];
#pragma unroll
    for (int mt = 0; mt < 4; mt++)
#pragma unroll
        for (int nt = 0; nt < 4; nt++)
#pragma unroll
            for (int c = 0; c < 4; c++) acc[mt][nt][c] = 0.f;

#pragma unroll
    for (int k16 = 0; k16 < 4; k16++) {
        const int f = k16 * 4 + tig;
        uint32_t bhf[4][2], bmf[4][2];
#pragma unroll
        for (int nt = 0; nt < 4; nt++) {
            int row = wn * 32 + nt * 8 + gid;
            uint4 kv = Ws[row * 16 + FSWZ(row, f)];
            bhf[nt][0] = kv.x; bhf[nt][1] = kv.z;
            bmf[nt][0] = kv.y; bmf[nt][1] = kv.w;
        }
#pragma unroll
        for (int mt = 0; mt < 4; mt++) {
            int r0 = wm * 64 + mt * 16 + gid;
            int r1 = r0 + 8;
            uint4 qa = Xs[r0 * 16 + FSWZ(r0, f)];
            uint4 qb = Xs[r1 * 16 + FSWZ(r1, f)];
            uint32_t ah[4], am[4];
            ah[0] = qa.x; ah[1] = qb.x; ah[2] = qa.z; ah[3] = qb.z;
            am[0] = qa.y; am[1] = qb.y; am[2] = qa.w; am[3] = qb.w;
#pragma unroll
            for (int nt = 0; nt < 4; nt++) {
                mma16(acc[mt][nt], ah, bhf[nt]);
                mma16(acc[mt][nt], ah, bmf[nt]);
                mma16(acc[mt][nt], am, bhf[nt]);
            }
        }
    }

    // epilogue: + bias, direct float2 stores
#pragma unroll
    for (int nt = 0; nt < 4; nt++) {
        int col = colbase + wn * 32 + nt * 8 + tig * 2;
        float b0 = bias[col], b1 = bias[col + 1];
#pragma unroll
        for (int mt = 0; mt < 4; mt++) {
            int r0 = rowbase + wm * 64 + mt * 16 + gid;
            float2 v0 = {acc[mt][nt][0] + b0, acc[mt][nt][1] + b1};
            float2 v1 = {acc[mt][nt][2] + b0, acc[mt][nt][3] + b1};
            *(float2*)&C[(long long)r0 * DM + col] = v0;
            *(float2*)&C[(long long)(r0 + 8) * DM + col] = v1;
        }
    }
}

// ---------------- launch -------------------------------------------------------------
extern "C" void kernel_launch(void* const* d_in, const int* in_sizes, int n_in,
                              void* d_out, int out_size)
{
    const float* query = (const float*)d_in[0];
    const float* key_  = (const float*)d_in[1];
    const float* value = (const float*)d_in[2];
    const float* Wq    = (const float*)d_in[3];
    const float* bq    = (const float*)d_in[4];
    const float* Wk    = (const float*)d_in[5];
    const float* bk    = (const float*)d_in[6];
    const float* Wv    = (const float*)d_in[7];
    const float* bv    = (const float*)d_in[8];
    const float* Wo    = (const float*)d_in[9];
    const float* bo    = (const float*)d_in[10];

    float* out_main = (float*)d_out;
    float* out_avg  = out_main + (size_t)ROWS * DM;

    uint4 *Xq, *Xk, *Wtq, *Wtk, *Qpk, *Kpk, *Aopk, *Wto;
    __half* Esc;
    float *Vp, *Lp, *Rv, *Av;
    cudaGetSymbolAddress((void**)&Xq, g_Xq);
    cudaGetSymbolAddress((void**)&Xk, g_Xk);
    cudaGetSymbolAddress((void**)&Wtq, g_Wtq);
    cudaGetSymbolAddress((void**)&Wtk, g_Wtk);
    cudaGetSymbolAddress((void**)&Qpk, g_Qpk);
    cudaGetSymbolAddress((void**)&Kpk, g_Kpk);
    cudaGetSymbolAddress((void**)&Vp, g_Vp);
    cudaGetSymbolAddress((void**)&Esc, g_escore);
    cudaGetSymbolAddress((void**)&Lp, g_lpart);
    cudaGetSymbolAddress((void**)&Rv, g_rinv);
    cudaGetSymbolAddress((void**)&Av, g_avpart);
    cudaGetSymbolAddress((void**)&Aopk, g_Aopk);
    cudaGetSymbolAddress((void**)&Wto, g_Wto);

    const int smemP = 2 * 98304;
    const int smem1 = 384 * 16 * 16 + 256 * 4 * 4;
    const int smemO = 384 * 16 * 16;
    cudaFuncSetAttribute(proj_mma, cudaFuncAttributeMaxDynamicSharedMemorySize, smemP);
    cudaFuncSetAttribute(mma_pass1, cudaFuncAttributeMaxDynamicSharedMemorySize, smem1);
    cudaFuncSetAttribute(out_mma, cudaFuncAttributeMaxDynamicSharedMemorySize, smemO);

    static cudaStream_t sK = nullptr, sV = nullptr;
    static cudaEvent_t evRoot = nullptr, evK = nullptr, evV = nullptr;
    if (sK == nullptr) {
        cudaStreamCreateWithFlags(&sK, cudaStreamNonBlocking);
        cudaStreamCreateWithFlags(&sV, cudaStreamNonBlocking);
        cudaEventCreateWithFlags(&evRoot, cudaEventDisableTiming);
        cudaEventCreateWithFlags(&evK, cudaEventDisableTiming);
        cudaEventCreateWithFlags(&evV, cudaEventDisableTiming);
    }

    dim3 blk(256);

    // fork
    cudaEventRecord(evRoot, 0);
    cudaStreamWaitEvent(sK, evRoot, 0);
    cudaStreamWaitEvent(sV, evRoot, 0);

    // main stream: Q path
    split_x<<<ROWS, blk>>>(query, Xq);
    split_w<<<dim3(16, 16), blk>>>(Wq, Wtq);
    proj_mma<<<dim3(8, 16), 512, smemP>>>(Xq, Wtq, bq, Qpk);

    // sK: K path
    split_x<<<ROWS, blk, 0, sK>>>(key_, Xk);
    split_w<<<dim3(16, 16), blk, 0, sK>>>(Wk, Wtk);
    proj_mma<<<dim3(8, 16), 512, smemP, sK>>>(Xk, Wtk, bk, Kpk);
    cudaEventRecord(evK, sK);

    // sV: V projection + Wo split (both needed only late)
    proj_gemm<<<dim3(1, 32), blk, 0, sV>>>(value, Wv, bv, Vp, DK, DM, DM, DK, DK);
    split_wo<<<dim3(16, 1), blk, 0, sV>>>(Wo, Wto);
    cudaEventRecord(evV, sV);

    // join K before pass1
    cudaStreamWaitEvent(0, evK, 0);

    mma_pass1<<<dim3(16, 8, BB * HH), 512, smem1>>>(Qpk, Kpk, Esc, Lp);
    combine_kernel<<<dim3(BB * HH * SS / 256, 1, 1), blk>>>(Lp, Rv);
    avg_kernel<<<dim3(SS, BB, 1), blk>>>(Esc, Rv, out_avg);

    // join V before av_gemm
    cudaStreamWaitEvent(0, evV, 0);

    av_gemm<<<dim3(8, 16, BB), blk>>>(out_avg, Vp, Av);
    av_reduce_pack<<<dim3(ROWS * 16 / 256, 1, 1), blk>>>(Av, Aopk);

    // final: out = Ao @ Wo + bo (bf16-split MMA)
    out_mma<<<dim3(8, 16), 512, smemO>>>(Aopk, Wto, bo, out_main);
}

// round 15
// speedup vs baseline: 2.3299x; 1.0921x over previous
#include <cuda_runtime.h>
#include <cuda_fp16.h>
#include <cstdint>

#define BB 2
#define SS 2048
#define HH 16
#define DK 64
#define DM 1024
#define ROWS (BB*SS)          // 4096

// ---------------- scratch -----------------------------------------------------
__device__ uint4 g_Xq[(size_t)ROWS*256];
__device__ uint4 g_Xk[(size_t)ROWS*256];
__device__ uint4 g_Wtq[(size_t)DM*256];
__device__ uint4 g_Wtk[(size_t)DM*256];
__device__ uint4 g_Qpk[(size_t)BB*HH*SS*16];
__device__ uint4 g_Kpk[(size_t)BB*HH*SS*16];
__device__ float g_Vp[(size_t)ROWS*DK];
__device__ __half g_escore[(size_t)BB*HH*SS*SS];  // exp(s/8) fp16 (268 MB)
__device__ float g_lpart[(size_t)BB*HH*16*SS];
__device__ float g_avpart[(size_t)8*BB*SS*DK];
__device__ uint4 g_Aopk[(size_t)ROWS*16];
__device__ uint4 g_Wto[(size_t)DM*16];

// ---------------- helpers -------------------------------------------------------
__device__ __forceinline__ unsigned long long pack2(float lo, float hi) {
    unsigned long long r;
    asm("mov.b64 %0, {%1, %2};" : "=l"(r) : "f"(lo), "f"(hi));
    return r;
}
__device__ __forceinline__ void unpack2(unsigned long long v, float& lo, float& hi) {
    asm("mov.b64 {%0, %1}, %2;" : "=f"(lo), "=f"(hi) : "l"(v));
}
__device__ __forceinline__ unsigned long long fma2(unsigned long long a,
                                                   unsigned long long b,
                                                   unsigned long long c) {
    unsigned long long d;
    asm("fma.rn.f32x2 %0, %1, %2, %3;" : "=l"(d) : "l"(a), "l"(b), "l"(c));
    return d;
}
__device__ __forceinline__ unsigned long long add2(unsigned long long a,
                                                   unsigned long long b) {
    unsigned long long d;
    asm("add.rn.f32x2 %0, %1, %2;" : "=l"(d) : "l"(a), "l"(b));
    return d;
}

// paired exp(x*0.125) via f32x2 pipe; valid |x/8| < ~80
__device__ __forceinline__ unsigned long long exp8_pair(float x0, float x1,
                                                        float& e0, float& e1) {
    const float K = 0.18033688011112042f;            // 0.125 * log2(e)
    unsigned long long X = pack2(x0, x1);
    unsigned long long K2 = pack2(K, K);
    unsigned long long MG = pack2(12582912.f, 12582912.f);
    unsigned long long T = fma2(X, K2, MG);
    unsigned long long N = add2(T, pack2(-12582912.f, -12582912.f));
    unsigned long long F = fma2(X, K2, N ^ 0x8000000080000000ull);
    unsigned long long P = pack2(1.3333558146e-3f, 1.3333558146e-3f);
    P = fma2(P, F, pack2(9.6178371906e-3f, 9.6178371906e-3f));
    P = fma2(P, F, pack2(5.5502813330e-2f, 5.5502813330e-2f));
    P = fma2(P, F, pack2(2.4022650695e-1f, 2.4022650695e-1f));
    P = fma2(P, F, pack2(6.9314718056e-1f, 6.9314718056e-1f));
    P = fma2(P, F, pack2(1.0f, 1.0f));
    float tl, th, pl, ph;
    unpack2(T, tl, th);
    unpack2(P, pl, ph);
    e0 = __uint_as_float(__float_as_uint(pl) + (__float_as_uint(tl) << 23));
    e1 = __uint_as_float(__float_as_uint(ph) + (__float_as_uint(th) << 23));
    return pack2(e0, e1);
}

__device__ __forceinline__ uint32_t bf16pack(float lo, float hi) {
    uint32_t r;
    asm("cvt.rn.bf16x2.f32 %0, %1, %2;" : "=r"(r) : "f"(hi), "f"(lo));
    return r;
}

__device__ __forceinline__ uint2 himid(float v0, float v1) {
    uint32_t hp = bf16pack(v0, v1);
    uint32_t mp = bf16pack(v0 - __uint_as_float(hp << 16),
                           v1 - __uint_as_float(hp & 0xffff0000u));
    uint2 o = {hp, mp};
    return o;
}

__device__ __forceinline__ void mma16(float* c, const uint32_t* a, const uint32_t* b) {
    asm volatile("mma.sync.aligned.m16n8k16.row.col.f32.bf16.bf16.f32 "
        "{%0,%1,%2,%3}, {%4,%5,%6,%7}, {%8,%9}, {%0,%1,%2,%3};"
        : "+f"(c[0]), "+f"(c[1]), "+f"(c[2]), "+f"(c[3])
        : "r"(a[0]), "r"(a[1]), "r"(a[2]), "r"(a[3]), "r"(b[0]), "r"(b[1]));
}

__device__ __forceinline__ uint32_t smem_u32(const void* p) {
    uint32_t a;
    asm("{ .reg .u64 t; cvta.to.shared.u64 t, %1; cvt.u32.u64 %0, t; }" : "=r"(a) : "l"(p));
    return a;
}

__device__ __forceinline__ void cp_async16(uint32_t dst, const void* src) {
    asm volatile("cp.async.cg.shared.global [%0], [%1], 16;" :: "r"(dst), "l"(src) : "memory");
}
__device__ __forceinline__ void cp_commit() {
    asm volatile("cp.async.commit_group;" ::: "memory");
}
template <int N>
__device__ __forceinline__ void cp_wait() {
    asm volatile("cp.async.wait_group %0;" :: "n"(N) : "memory");
}

#define FSWZ(r, f) ((f) ^ (((r) & 1) << 2))

// ---------------- input split kernels ---------------------------------------------
__global__ __launch_bounds__(256)
void split_x(const float* __restrict__ X, uint4* __restrict__ out)
{
    int g = blockIdx.x * 256 + threadIdx.x;
    int r = g >> 8, f = g & 255;
    int k = (f >> 2) * 16 + (f & 3) * 2;
    const float* xp = X + (long long)r * DM + k;
    uint2 a = himid(xp[0], xp[1]);
    uint2 b = himid(xp[8], xp[9]);
    uint4 o = {a.x, a.y, b.x, b.y};
    out[g] = o;
}

__global__ __launch_bounds__(256)
void split_w(const float* __restrict__ W, uint4* __restrict__ out)
{
    __shared__ float ws[64][65];
    const int tid = threadIdx.x;
    const int kb = blockIdx.y * 64, nb = blockIdx.x * 64;
#pragma unroll
    for (int i = 0; i < 16; i++) {
        int idx = tid + i * 256; int kk = idx >> 6, nn = idx & 63;
        ws[kk][nn] = W[(long long)(kb + kk) * DM + nb + nn];
    }
    __syncthreads();
#pragma unroll
    for (int i = 0; i < 4; i++) {
        int idx = tid + i * 256; int nn = idx >> 4, f = idx & 15;
        int kk = (f >> 2) * 16 + (f & 3) * 2;
        uint2 a = himid(ws[kk][nn], ws[kk + 1][nn]);
        uint2 b = himid(ws[kk + 8][nn], ws[kk + 9][nn]);
        uint4 o = {a.x, a.y, b.x, b.y};
        out[(long long)(nb + nn) * 256 + (kb >> 2) + f] = o;
    }
}

__global__ __launch_bounds__(256)
void split_wo(const float* __restrict__ W, uint4* __restrict__ out)
{
    __shared__ float ws[64][65];
    const int tid = threadIdx.x;
    const int nb = blockIdx.x * 64;
#pragma unroll
    for (int i = 0; i < 16; i++) {
        int idx = tid + i * 256; int kk = idx >> 6, nn = idx & 63;
        ws[kk][nn] = W[(long long)kk * DM + nb + nn];
    }
    __syncthreads();
#pragma unroll
    for (int i = 0; i < 4; i++) {
        int idx = tid + i * 256; int nn = idx >> 4, f = idx & 15;
        int kk = (f >> 2) * 16 + (f & 3) * 2;
        uint2 a = himid(ws[kk][nn], ws[kk + 1][nn]);
        uint2 b = himid(ws[kk + 8][nn], ws[kk + 9][nn]);
        uint4 o = {a.x, a.y, b.x, b.y};
        out[(long long)(nb + nn) * 16 + f] = o;
    }
}

// ---------------- Q/K projection via bf16-split MMA + cp.async pipeline ------------
__global__ __launch_bounds__(512, 1)
void proj_mma(const uint4* __restrict__ Xpk, const uint4* __restrict__ Wt,
              const float* __restrict__ bias, uint4* __restrict__ Cpk)
{
    extern __shared__ uint4 smq[];
    const uint32_t smb = smem_u32(smq);

    const int tid = threadIdx.x;
    const int colbase = blockIdx.x * 128;
    const int rowbase = blockIdx.y * 256;
    const int wid = tid >> 5, lane = tid & 31;
    const int wm = wid >> 2, wn = wid & 3;
    const int gid = lane >> 2, tig = lane & 3;

    float acc[4][4][4];
#pragma unroll
    for (int mt = 0; mt < 4; mt++)
#pragma unroll
        for (int nt = 0; nt < 4; nt++)
#pragma unroll
            for (int c = 0; c < 4; c++) acc[mt][nt][c] = 0.f;

    auto issue = [&](int kc, int s) {
        uint32_t base = smb + s * 98304;
#pragma unroll
        for (int i = 0; i < 8; i++) {
            int idx = tid + i * 512; int r = idx >> 4, f = idx & 15;
            cp_async16(base + (uint32_t)(r * 16 + FSWZ(r, f)) * 16,
                       &Xpk[(long long)(rowbase + r) * 256 + kc * 16 + f]);
        }
#pragma unroll
        for (int i = 0; i < 4; i++) {
            int idx = tid + i * 512; int r = idx >> 4, f = idx & 15;
            cp_async16(base + 65536u + (uint32_t)(r * 16 + FSWZ(r, f)) * 16,
                       &Wt[(long long)(colbase + r) * 256 + kc * 16 + f]);
        }
        cp_commit();
    };

    issue(0, 0);

    for (int kc = 0; kc < 16; kc++) {
        const int s = kc & 1;
        if (kc < 15) { issue(kc + 1, s ^ 1); cp_wait<1>(); }
        else cp_wait<0>();
        __syncthreads();

        const uint4* Xs = smq + s * 6144;
        const uint4* Ws = Xs + 4096;
#pragma unroll
        for (int k16 = 0; k16 < 4; k16++) {
            const int f = k16 * 4 + tig;
            uint32_t bhf[4][2], bmf[4][2];
#pragma unroll
            for (int nt = 0; nt < 4; nt++) {
                int row = wn * 32 + nt * 8 + gid;
                uint4 kv = Ws[row * 16 + FSWZ(row, f)];
                bhf[nt][0] = kv.x; bhf[nt][1] = kv.z;
                bmf[nt][0] = kv.y; bmf[nt][1] = kv.w;
            }
#pragma unroll
            for (int mt = 0; mt < 4; mt++) {
                int r0 = wm * 64 + mt * 16 + gid;
                int r1 = r0 + 8;
                uint4 qa = Xs[r0 * 16 + FSWZ(r0, f)];
                uint4 qb = Xs[r1 * 16 + FSWZ(r1, f)];
                uint32_t ah[4], am[4];
                ah[0] = qa.x; ah[1] = qb.x; ah[2] = qa.z; ah[3] = qb.z;
                am[0] = qa.y; am[1] = qb.y; am[2] = qa.w; am[3] = qb.w;
#pragma unroll
                for (int nt = 0; nt < 4; nt++) {
                    mma16(acc[mt][nt], ah, bhf[nt]);
                    mma16(acc[mt][nt], ah, bmf[nt]);
                    mma16(acc[mt][nt], am, bhf[nt]);
                }
            }
        }
        __syncthreads();
    }

    const int nb = colbase + wn * 32;
    const int h = nb >> 6;
    const int db = nb & 63;
#pragma unroll
    for (int ntp = 0; ntp < 2; ntp++) {
        int cb = nb + ntp * 16 + tig * 2;
        float b0 = bias[cb],     b1 = bias[cb + 1];
        float b2 = bias[cb + 8], b3 = bias[cb + 9];
        int k16o = (db >> 4) + ntp;
#pragma unroll
        for (int mt = 0; mt < 4; mt++) {
#pragma unroll
            for (int rr = 0; rr < 2; rr++) {
                int gr = rowbase + wm * 64 + mt * 16 + rr * 8 + gid;
                int b = gr >> 11, s = gr & (SS - 1);
                uint2 lo = himid(acc[mt][2 * ntp][rr * 2] + b0,
                                 acc[mt][2 * ntp][rr * 2 + 1] + b1);
                uint2 hi = himid(acc[mt][2 * ntp + 1][rr * 2] + b2,
                                 acc[mt][2 * ntp + 1][rr * 2 + 1] + b3);
                uint4 o = {lo.x, lo.y, hi.x, hi.y};
                Cpk[((long long)((b * HH + h) * SS + s)) * 16 + k16o * 4 + tig] = o;
            }
        }
    }
}

// ---------------- pass 1: 128x128 tile, 256 thr, 2 blocks/SM -----------------------
__global__ __launch_bounds__(256, 2)
void mma_pass1(const uint4* __restrict__ Qpk, const uint4* __restrict__ Kpk,
               __half* __restrict__ Esc, float* __restrict__ lpart)
{
    extern __shared__ uint4 smq[];
    uint4* Qs = smq;                          // [128][16]
    uint4* Ks = Qs + 128 * 16;                // [128][16]
    float* rowsum = (float*)(smq + 256 * 16); // [128][4] at 64 KB
    __half* smh = (__half*)smq;               // epilogue staging (34 KB, below rowsum)

    const int tid = threadIdx.x;
    const int kt = blockIdx.x, qt = blockIdx.y, bh = blockIdx.z;
    const long long qbase = ((long long)bh * SS + qt * 128) * 16;
    const long long kbase = ((long long)bh * SS + kt * 128) * 16;

#pragma unroll
    for (int i = 0; i < 8; i++) {
        int idx = tid + i * 256;
        int r = idx >> 4, f = idx & 15;
        Qs[r * 16 + FSWZ(r, f)] = Qpk[qbase + r * 16 + f];
        Ks[r * 16 + FSWZ(r, f)] = Kpk[kbase + r * 16 + f];
    }
    __syncthreads();

    const int wid = tid >> 5, lane = tid & 31;
    const int wm = wid >> 2, wn = wid & 3;    // 2x4 warp grid, warp tile 64x32
    const int gid = lane >> 2, tig = lane & 3;

    float acc[4][4][4];
#pragma unroll
    for (int mt = 0; mt < 4; mt++)
#pragma unroll
        for (int nt = 0; nt < 4; nt++)
#pragma unroll
            for (int c = 0; c < 4; c++) acc[mt][nt][c] = 0.f;

#pragma unroll
    for (int k16 = 0; k16 < 4; k16++) {
        const int f = k16 * 4 + tig;
        uint32_t bhf[4][2], bmf[4][2];
#pragma unroll
        for (int nt = 0; nt < 4; nt++) {
            int row = wn * 32 + nt * 8 + gid;
            uint4 kv = Ks[row * 16 + FSWZ(row, f)];
            bhf[nt][0] = kv.x; bhf[nt][1] = kv.z;
            bmf[nt][0] = kv.y; bmf[nt][1] = kv.w;
        }
#pragma unroll
        for (int mt = 0; mt < 4; mt++) {
            int r0 = wm * 64 + mt * 16 + gid;
            int r1 = r0 + 8;
            uint4 qa = Qs[r0 * 16 + FSWZ(r0, f)];
            uint4 qb = Qs[r1 * 16 + FSWZ(r1, f)];
            uint32_t ah[4], am[4];
            ah[0] = qa.x; ah[1] = qb.x; ah[2] = qa.z; ah[3] = qb.z;
            am[0] = qa.y; am[1] = qb.y; am[2] = qa.w; am[3] = qb.w;
#pragma unroll
            for (int nt = 0; nt < 4; nt++) {
                mma16(acc[mt][nt], ah, bhf[nt]);
                mma16(acc[mt][nt], ah, bmf[nt]);
                mma16(acc[mt][nt], am, bhf[nt]);
            }
        }
    }

    // exp (paired f32x2) in place + packed row sums
    unsigned long long S0[4], S1[4];
#pragma unroll
    for (int mt = 0; mt < 4; mt++) { S0[mt] = 0ull; S1[mt] = 0ull; }
#pragma unroll
    for (int mt = 0; mt < 4; mt++)
#pragma unroll
        for (int nt = 0; nt < 4; nt++) {
            unsigned long long P01 = exp8_pair(acc[mt][nt][0], acc[mt][nt][1],
                                               acc[mt][nt][0], acc[mt][nt][1]);
            unsigned long long P23 = exp8_pair(acc[mt][nt][2], acc[mt][nt][3],
                                               acc[mt][nt][2], acc[mt][nt][3]);
            S0[mt] = add2(S0[mt], P01);
            S1[mt] = add2(S1[mt], P23);
        }
    float p[4][2];
#pragma unroll
    for (int mt = 0; mt < 4; mt++) {
        float a, b;
        unpack2(S0[mt], a, b); p[mt][0] = a + b;
        unpack2(S1[mt], a, b); p[mt][1] = a + b;
    }
#pragma unroll
    for (int o = 1; o <= 2; o <<= 1)
#pragma unroll
        for (int mt = 0; mt < 4; mt++) {
            p[mt][0] += __shfl_xor_sync(0xffffffffu, p[mt][0], o);
            p[mt][1] += __shfl_xor_sync(0xffffffffu, p[mt][1], o);
        }
    if (tig == 0) {
#pragma unroll
        for (int mt = 0; mt < 4; mt++)
#pragma unroll
            for (int j = 0; j < 2; j++) {
                int r = wm * 64 + mt * 16 + j * 8 + gid;
                rowsum[r * 4 + wn] = p[mt][j];
            }
    }
    __syncthreads();   // mainloop smem reads + rowsum writes complete

    if (tid < 128) {
        float l = rowsum[tid * 4] + rowsum[tid * 4 + 1]
                + rowsum[tid * 4 + 2] + rowsum[tid * 4 + 3];
        lpart[(long long)(bh * 16 + kt) * SS + qt * 128 + tid] = l;
    }

    // stage fp16 tile (pitch 136) then coalesced copy out
#pragma unroll
    for (int mt = 0; mt < 4; mt++) {
        int r0 = wm * 64 + mt * 16 + gid;
#pragma unroll
        for (int nt = 0; nt < 4; nt++) {
            int col = wn * 32 + nt * 8 + tig * 2;
            *(__half2*)&smh[r0 * 136 + col] =
                __floats2half2_rn(acc[mt][nt][0], acc[mt][nt][1]);
            *(__half2*)&smh[(r0 + 8) * 136 + col] =
                __floats2half2_rn(acc[mt][nt][2], acc[mt][nt][3]);
        }
    }
    __syncthreads();

    __half* Cp = Esc + ((long long)bh * SS + qt * 128) * SS + kt * 128;
    const int u = tid & 15;
    const int rbase = tid >> 4;               // 0..15
#pragma unroll
    for (int i = 0; i < 8; i++) {
        int row = i * 16 + rbase;
        uint4 v = *(uint4*)&smh[row * 136 + u * 8];
        *(uint4*)&Cp[(long long)row * SS + u * 8] = v;
    }
}

// ---------------- head-averaged attention (combine folded in) ----------------------
__global__ __launch_bounds__(256)
void avg_kernel(const __half* __restrict__ Esc, const float* __restrict__ lpart,
                float* __restrict__ avg)
{
    const int q = blockIdx.x;
    const int b = blockIdx.y;
    const int tid = threadIdx.x;

    __shared__ float rw[HH];
    if (tid < HH) {
        float l = 0.f;
#pragma unroll
        for (int kt = 0; kt < 16; kt++)
            l += lpart[(long long)((b * HH + tid) * 16 + kt) * SS + q];
        rw[tid] = (1.0f / HH) / l;
    }
    __syncthreads();

    const __half* base = Esc + ((long long)(b * HH) * SS + q) * SS;
    const int k0 = tid * 8;
    float a0 = 0.f, a1 = 0.f, a2 = 0.f, a3 = 0.f;
    float a4 = 0.f, a5 = 0.f, a6 = 0.f, a7 = 0.f;
#pragma unroll
    for (int h = 0; h < HH; h++) {
        uint4 raw = *(const uint4*)(base + (long long)h * SS * SS + k0);
        float2 f0 = __half22float2(*(__half2*)&raw.x);
        float2 f1 = __half22float2(*(__half2*)&raw.y);
        float2 f2 = __half22float2(*(__half2*)&raw.z);
        float2 f3 = __half22float2(*(__half2*)&raw.w);
        float r = rw[h];
        a0 = fmaf(f0.x, r, a0); a1 = fmaf(f0.y, r, a1);
        a2 = fmaf(f1.x, r, a2); a3 = fmaf(f1.y, r, a3);
        a4 = fmaf(f2.x, r, a4); a5 = fmaf(f2.y, r, a5);
        a6 = fmaf(f3.x, r, a6); a7 = fmaf(f3.y, r, a7);
    }
    float* dst = avg + ((long long)b * SS + q) * SS + k0;
    float4 o0 = {a0, a1, a2, a3};
    float4 o1 = {a4, a5, a6, a7};
    *(float4*)&dst[0] = o0;
    *(float4*)&dst[4] = o1;
}

// ---------------- SIMT projection GEMM (V projection) -------------------------------
#define PADW 132

__global__ __launch_bounds__(256, 2)
void proj_gemm(const float* __restrict__ A, const float* __restrict__ B,
               const float* __restrict__ bias, float* __restrict__ C,
               int N, int K, int lda, int ldb, int ldc)
{
    __shared__ __align__(16) float As[16 * PADW];
    __shared__ __align__(16) float Bs[16 * PADW];

    const int rowbase = blockIdx.y * 128;
    const int colbase = blockIdx.x * 128;
    const int tid = threadIdx.x;
    const int tx = tid & 15, ty = tid >> 4;
    const int row0 = ty * 8, col0 = tx * 8;

    float regA[8], regB[8];
    unsigned long long acc[8][4];
#pragma unroll
    for (int i = 0; i < 8; i++)
#pragma unroll
        for (int j = 0; j < 4; j++) acc[i][j] = 0ull;

#pragma unroll
    for (int i = 0; i < 8; i++) {
        int idx = tid + i * 256; int r = idx >> 4, kk = idx & 15;
        regA[i] = A[(long long)(rowbase + r) * lda + kk];
    }
#pragma unroll
    for (int i = 0; i < 8; i++) {
        int idx = tid + i * 256; int kk = idx >> 7, c = idx & 127;
        int col = colbase + c;
        regB[i] = (col < N) ? B[(long long)kk * ldb + col] : 0.f;
    }
#pragma unroll
    for (int i = 0; i < 8; i++) {
        int idx = tid + i * 256; int r = idx >> 4, kk = idx & 15;
        As[kk * PADW + r] = regA[i];
    }
#pragma unroll
    for (int i = 0; i < 8; i++) {
        int idx = tid + i * 256; int kk = idx >> 7, c = idx & 127;
        Bs[kk * PADW + c] = regB[i];
    }
    __syncthreads();

    for (int k0 = 16; ; k0 += 16) {
        const bool more = (k0 < K);
        if (more) {
#pragma unroll
            for (int i = 0; i < 8; i++) {
                int idx = tid + i * 256; int r = idx >> 4, kk = idx & 15;
                regA[i] = A[(long long)(rowbase + r) * lda + k0 + kk];
            }
#pragma unroll
            for (int i = 0; i < 8; i++) {
                int idx = tid + i * 256; int kk = idx >> 7, c = idx & 127;
                int col = colbase + c;
                regB[i] = (col < N) ? B[(long long)(k0 + kk) * ldb + col] : 0.f;
            }
        }
#pragma unroll
        for (int kk = 0; kk < 16; kk++) {
            float4 a0 = *(const float4*)&As[kk * PADW + row0];
            float4 a1 = *(const float4*)&As[kk * PADW + row0 + 4];
            float4 b0 = *(const float4*)&Bs[kk * PADW + col0];
            float4 b1 = *(const float4*)&Bs[kk * PADW + col0 + 4];
            float a[8] = {a0.x, a0.y, a0.z, a0.w, a1.x, a1.y, a1.z, a1.w};
            unsigned long long bp[4];
            bp[0] = pack2(b0.x, b0.y); bp[1] = pack2(b0.z, b0.w);
            bp[2] = pack2(b1.x, b1.y); bp[3] = pack2(b1.z, b1.w);
#pragma unroll
            for (int i = 0; i < 8; i++) {
                unsigned long long ap = pack2(a[i], a[i]);
#pragma unroll
                for (int j = 0; j < 4; j++) acc[i][j] = fma2(ap, bp[j], acc[i][j]);
            }
        }
        if (!more) break;
        __syncthreads();
#pragma unroll
        for (int i = 0; i < 8; i++) {
            int idx = tid + i * 256; int r = idx >> 4, kk = idx & 15;
            As[kk * PADW + r] = regA[i];
        }
#pragma unroll
        for (int i = 0; i < 8; i++) {
            int idx = tid + i * 256; int kk = idx >> 7, c = idx & 127;
            Bs[kk * PADW + c] = regB[i];
        }
        __syncthreads();
    }

#pragma unroll
    for (int i = 0; i < 8; i++) {
        int gr = rowbase + row0 + i;
#pragma unroll
        for (int j2 = 0; j2 < 4; j2 += 2) {
            int col = colbase + col0 + j2 * 2;
            if (col < N) {
                float4 v;
                unpack2(acc[i][j2],     v.x, v.y);
                unpack2(acc[i][j2 + 1], v.z, v.w);
                const float4 bb = *(const float4*)&bias[col];
                v.x += bb.x; v.y += bb.y; v.z += bb.z; v.w += bb.w;
                *(float4*)&C[(long long)gr * ldc + col] = v;
            }
        }
    }
}

// ---------------- avg @ V (split-K, packed fma2 + reg prefetch) ---------------------
__global__ __launch_bounds__(256)
void av_gemm(const float* __restrict__ avg, const float* __restrict__ V,
             float* __restrict__ part)
{
    __shared__ float As[16 * PADW];
    __shared__ float Bs[16 * 68];
    const int b = blockIdx.z;
    const int rowbase = blockIdx.y * 128;
    const int k0base = blockIdx.x * 256;
    const float* Ap = avg + ((long long)b * SS + rowbase) * SS;
    const float* Vp = V + (long long)b * SS * DK;
    const int tid = threadIdx.x;
    const int tx = tid & 15, ty = tid >> 4;

    unsigned long long acc[8][2];
#pragma unroll
    for (int i = 0; i < 8; i++) { acc[i][0] = 0ull; acc[i][1] = 0ull; }

    float regA[8], regB[4];
#pragma unroll
    for (int i = 0; i < 8; i++) {
        int idx = tid + i * 256; int r = idx >> 4, kk = idx & 15;
        regA[i] = Ap[(long long)r * SS + k0base + kk];
    }
#pragma unroll
    for (int i = 0; i < 4; i++) {
        int idx = tid + i * 256; int kk = idx >> 6, cc = idx & 63;
        regB[i] = Vp[(long long)(k0base + kk) * DK + cc];
    }

    for (int kc = 0; kc < 256; kc += 16) {
#pragma unroll
        for (int i = 0; i < 8; i++) {
            int idx = tid + i * 256; int r = idx >> 4, kk = idx & 15;
            As[kk * PADW + r] = regA[i];
        }
#pragma unroll
        for (int i = 0; i < 4; i++) {
            int idx = tid + i * 256; int kk = idx >> 6, cc = idx & 63;
            Bs[kk * 68 + cc] = regB[i];
        }
        __syncthreads();

        const bool more = (kc + 16 < 256);
        if (more) {
            const int k0 = k0base + kc + 16;
#pragma unroll
            for (int i = 0; i < 8; i++) {
                int idx = tid + i * 256; int r = idx >> 4, kk = idx & 15;
                regA[i] = Ap[(long long)r * SS + k0 + kk];
            }
#pragma unroll
            for (int i = 0; i < 4; i++) {
                int idx = tid + i * 256; int kk = idx >> 6, cc = idx & 63;
                regB[i] = Vp[(long long)(k0 + kk) * DK + cc];
            }
        }

#pragma unroll
        for (int kk = 0; kk < 16; kk++) {
            float a[8];
#pragma unroll
            for (int i = 0; i < 8; i++) a[i] = As[kk * PADW + ty * 8 + i];
            float4 bv = *(const float4*)&Bs[kk * 68 + tx * 4];
            unsigned long long b01 = pack2(bv.x, bv.y);
            unsigned long long b23 = pack2(bv.z, bv.w);
#pragma unroll
            for (int i = 0; i < 8; i++) {
                unsigned long long ap = pack2(a[i], a[i]);
                acc[i][0] = fma2(ap, b01, acc[i][0]);
                acc[i][1] = fma2(ap, b23, acc[i][1]);
            }
        }
        __syncthreads();
    }
    float* P = part + ((long long)(blockIdx.x * BB + b) * SS + rowbase) * DK;
#pragma unroll
    for (int i = 0; i < 8; i++) {
        float4 v;
        unpack2(acc[i][0], v.x, v.y);
        unpack2(acc[i][1], v.z, v.w);
        *(float4*)&P[(long long)(ty * 8 + i) * DK + tx * 4] = v;
    }
}

__global__ __launch_bounds__(256)
void av_reduce_pack(const float* __restrict__ part, uint4* __restrict__ Aopk)
{
    int g = blockIdx.x * 256 + threadIdx.x;
    int r = g >> 4, f = g & 15;
    int k = (f >> 2) * 16 + (f & 3) * 2;
    float v0 = 0.f, v1 = 0.f, v8 = 0.f, v9 = 0.f;
#pragma unroll
    for (int t = 0; t < 8; t++) {
        const float* p = part + (long long)t * (BB * SS * DK) + (long long)r * DK + k;
        float2 a = *(const float2*)p;
        float2 b = *(const float2*)(p + 8);
        v0 += a.x; v1 += a.y; v8 += b.x; v9 += b.y;
    }
    uint2 lo = himid(v0, v1);
    uint2 hi = himid(v8, v9);
    uint4 o = {lo.x, lo.y, hi.x, hi.y};
    Aopk[g] = o;
}

// ---------------- final GEMM: out = Ao @ Wo + bo ------------------------------------
__global__ __launch_bounds__(512, 1)
void out_mma(const uint4* __restrict__ Aopk, const uint4* __restrict__ Wto,
             const float* __restrict__ bias, float* __restrict__ C)
{
    extern __shared__ uint4 smq[];
    uint4* Xs = smq;
    uint4* Ws = Xs + 256 * 16;

    const int tid = threadIdx.x;
    const int colbase = blockIdx.x * 128;
    const int rowbase = blockIdx.y * 256;
    const int wid = tid >> 5, lane = tid & 31;
    const int wm = wid >> 2, wn = wid & 3;
    const int gid = lane >> 2, tig = lane & 3;

#pragma unroll
    for (int i = 0; i < 8; i++) {
        int idx = tid + i * 512; int r = idx >> 4, f = idx & 15;
        Xs[r * 16 + FSWZ(r, f)] = Aopk[(long long)(rowbase + r) * 16 + f];
    }
#pragma unroll
    for (int i = 0; i < 4; i++) {
        int idx = tid + i * 512; int r = idx >> 4, f = idx & 15;
        Ws[r * 16 + FSWZ(r, f)] = Wto[(long long)(colbase + r) * 16 + f];
    }
    __syncthreads();

    float acc[4][4][4];
#pragma unroll
    for (int mt = 0; mt < 4; mt++)
#pragma unroll
        for (int nt = 0; nt < 4; nt++)
#pragma unroll
            for (int c = 0; c < 4; c++) acc[mt][nt][c] = 0.f;

#pragma unroll
    for (int k16 = 0; k16 < 4; k16++) {
        const int f = k16 * 4 + tig;
        uint32_t bhf[4][2], bmf[4][2];
#pragma unroll
        for (int nt = 0; nt < 4; nt++) {
            int row = wn * 32 + nt * 8 + gid;
            uint4 kv = Ws[row * 16 + FSWZ(row, f)];
            bhf[nt][0] = kv.x; bhf[nt][1] = kv.z;
            bmf[nt][0] = kv.y; bmf[nt][1] = kv.w;
        }
#pragma unroll
        for (int mt = 0; mt < 4; mt++) {
            int r0 = wm * 64 + mt * 16 + gid;
            int r1 = r0 + 8;
            uint4 qa = Xs[r0 * 16 + FSWZ(r0, f)];
            uint4 qb = Xs[r1 * 16 + FSWZ(r1, f)];
            uint32_t ah[4], am[4];
            ah[0] = qa.x; ah[1] = qb.x; ah[2] = qa.z; ah[3] = qb.z;
            am[0] = qa.y; am[1] = qb.y; am[2] = qa.w; am[3] = qb.w;
#pragma unroll
            for (int nt = 0; nt < 4; nt++) {
                mma16(acc[mt][nt], ah, bhf[nt]);
                mma16(acc[mt][nt], ah, bmf[nt]);
                mma16(acc[mt][nt], am, bhf[nt]);
            }
        }
    }

#pragma unroll
    for (int nt = 0; nt < 4; nt++) {
        int col = colbase + wn * 32 + nt * 8 + tig * 2;
        float b0 = bias[col], b1 = bias[col + 1];
#pragma unroll
        for (int mt = 0; mt < 4; mt++) {
            int r0 = rowbase + wm * 64 + mt * 16 + gid;
            float2 v0 = {acc[mt][nt][0] + b0, acc[mt][nt][1] + b1};
            float2 v1 = {acc[mt][nt][2] + b0, acc[mt][nt][3] + b1};
            *(float2*)&C[(long long)r0 * DM + col] = v0;
            *(float2*)&C[(long long)(r0 + 8) * DM + col] = v1;
        }
    }
}

// ---------------- launch -------------------------------------------------------------
extern "C" void kernel_launch(void* const* d_in, const int* in_sizes, int n_in,
                              void* d_out, int out_size)
{
    const float* query = (const float*)d_in[0];
    const float* key_  = (const float*)d_in[1];
    const float* value = (const float*)d_in[2];
    const float* Wq    = (const float*)d_in[3];
    const float* bq    = (const float*)d_in[4];
    const float* Wk    = (const float*)d_in[5];
    const float* bk    = (const float*)d_in[6];
    const float* Wv    = (const float*)d_in[7];
    const float* bv    = (const float*)d_in[8];
    const float* Wo    = (const float*)d_in[9];
    const float* bo    = (const float*)d_in[10];

    float* out_main = (float*)d_out;
    float* out_avg  = out_main + (size_t)ROWS * DM;

    uint4 *Xq, *Xk, *Wtq, *Wtk, *Qpk, *Kpk, *Aopk, *Wto;
    __half* Esc;
    float *Vp, *Lp, *Av;
    cudaGetSymbolAddress((void**)&Xq, g_Xq);
    cudaGetSymbolAddress((void**)&Xk, g_Xk);
    cudaGetSymbolAddress((void**)&Wtq, g_Wtq);
    cudaGetSymbolAddress((void**)&Wtk, g_Wtk);
    cudaGetSymbolAddress((void**)&Qpk, g_Qpk);
    cudaGetSymbolAddress((void**)&Kpk, g_Kpk);
    cudaGetSymbolAddress((void**)&Vp, g_Vp);
    cudaGetSymbolAddress((void**)&Esc, g_escore);
    cudaGetSymbolAddress((void**)&Lp, g_lpart);
    cudaGetSymbolAddress((void**)&Av, g_avpart);
    cudaGetSymbolAddress((void**)&Aopk, g_Aopk);
    cudaGetSymbolAddress((void**)&Wto, g_Wto);

    const int smemP = 2 * 98304;
    const int smem1 = 256 * 16 * 16 + 128 * 4 * 4;   // 67584
    const int smemO = 384 * 16 * 16;
    cudaFuncSetAttribute(proj_mma, cudaFuncAttributeMaxDynamicSharedMemorySize, smemP);
    cudaFuncSetAttribute(mma_pass1, cudaFuncAttributeMaxDynamicSharedMemorySize, smem1);
    cudaFuncSetAttribute(out_mma, cudaFuncAttributeMaxDynamicSharedMemorySize, smemO);

    static cudaStream_t sK = nullptr, sV = nullptr;
    static cudaEvent_t evRoot = nullptr, evK = nullptr, evV = nullptr;
    if (sK == nullptr) {
        cudaStreamCreateWithFlags(&sK, cudaStreamNonBlocking);
        cudaStreamCreateWithFlags(&sV, cudaStreamNonBlocking);
        cudaEventCreateWithFlags(&evRoot, cudaEventDisableTiming);
        cudaEventCreateWithFlags(&evK, cudaEventDisableTiming);
        cudaEventCreateWithFlags(&evV, cudaEventDisableTiming);
    }

    dim3 blk(256);

    // fork
    cudaEventRecord(evRoot, 0);
    cudaStreamWaitEvent(sK, evRoot, 0);
    cudaStreamWaitEvent(sV, evRoot, 0);

    // main stream: Q path
    split_x<<<ROWS, blk>>>(query, Xq);
    split_w<<<dim3(16, 16), blk>>>(Wq, Wtq);
    proj_mma<<<dim3(8, 16), 512, smemP>>>(Xq, Wtq, bq, Qpk);

    // sK: K path
    split_x<<<ROWS, blk, 0, sK>>>(key_, Xk);
    split_w<<<dim3(16, 16), blk, 0, sK>>>(Wk, Wtk);
    proj_mma<<<dim3(8, 16), 512, smemP, sK>>>(Xk, Wtk, bk, Kpk);
    cudaEventRecord(evK, sK);

    // sV: V projection + Wo split
    proj_gemm<<<dim3(1, 32), blk, 0, sV>>>(value, Wv, bv, Vp, DK, DM, DM, DK, DK);
    split_wo<<<dim3(16, 1), blk, 0, sV>>>(Wo, Wto);
    cudaEventRecord(evV, sV);

    // join K before pass1
    cudaStreamWaitEvent(0, evK, 0);

    mma_pass1<<<dim3(16, 16, BB * HH), 256, smem1>>>(Qpk, Kpk, Esc, Lp);
    avg_kernel<<<dim3(SS, BB, 1), blk>>>(Esc, Lp, out_avg);

    // join V before av_gemm
    cudaStreamWaitEvent(0, evV, 0);

    av_gemm<<<dim3(8, 16, BB), blk>>>(out_avg, Vp, Av);
    av_reduce_pack<<<dim3(ROWS * 16 / 256, 1, 1), blk>>>(Av, Aopk);

    out_mma<<<dim3(8, 16), 512, smemO>>>(Aopk, Wto, bo, out_main);
}

// round 16
// speedup vs baseline: 2.3696x; 1.0170x over previous
#include <cuda_runtime.h>
#include <cuda_fp16.h>
#include <cstdint>

#define BB 2
#define SS 2048
#define HH 16
#define DK 64
#define DM 1024
#define ROWS (BB*SS)          // 4096

// ---------------- scratch -----------------------------------------------------
__device__ uint4 g_Xq[(size_t)ROWS*256];
__device__ uint4 g_Xk[(size_t)ROWS*256];
__device__ uint4 g_Wtq[(size_t)DM*256];
__device__ uint4 g_Wtk[(size_t)DM*256];
__device__ uint4 g_Qpk[(size_t)BB*HH*SS*16];
__device__ uint4 g_Kpk[(size_t)BB*HH*SS*16];
__device__ float g_Vp[(size_t)ROWS*DK];
__device__ __half g_escore[(size_t)BB*HH*SS*SS];  // exp(s/8) fp16 (268 MB)
__device__ float g_lpart[(size_t)BB*HH*16*SS];
__device__ float g_avpart[(size_t)8*BB*SS*DK];
__device__ uint4 g_Aopk[(size_t)ROWS*16];
__device__ uint4 g_Wto[(size_t)DM*16];

// ---------------- helpers -------------------------------------------------------
__device__ __forceinline__ unsigned long long pack2(float lo, float hi) {
    unsigned long long r;
    asm("mov.b64 %0, {%1, %2};" : "=l"(r) : "f"(lo), "f"(hi));
    return r;
}
__device__ __forceinline__ void unpack2(unsigned long long v, float& lo, float& hi) {
    asm("mov.b64 {%0, %1}, %2;" : "=f"(lo), "=f"(hi) : "l"(v));
}
__device__ __forceinline__ unsigned long long fma2(unsigned long long a,
                                                   unsigned long long b,
                                                   unsigned long long c) {
    unsigned long long d;
    asm("fma.rn.f32x2 %0, %1, %2, %3;" : "=l"(d) : "l"(a), "l"(b), "l"(c));
    return d;
}
__device__ __forceinline__ unsigned long long add2(unsigned long long a,
                                                   unsigned long long b) {
    unsigned long long d;
    asm("add.rn.f32x2 %0, %1, %2;" : "=l"(d) : "l"(a), "l"(b));
    return d;
}

// paired exp(x*0.125) via f32x2 pipe
__device__ __forceinline__ unsigned long long exp8_pair(float x0, float x1,
                                                        float& e0, float& e1) {
    const float K = 0.18033688011112042f;            // 0.125 * log2(e)
    unsigned long long X = pack2(x0, x1);
    unsigned long long K2 = pack2(K, K);
    unsigned long long MG = pack2(12582912.f, 12582912.f);
    unsigned long long T = fma2(X, K2, MG);
    unsigned long long N = add2(T, pack2(-12582912.f, -12582912.f));
    unsigned long long F = fma2(X, K2, N ^ 0x8000000080000000ull);
    unsigned long long P = pack2(1.3333558146e-3f, 1.3333558146e-3f);
    P = fma2(P, F, pack2(9.6178371906e-3f, 9.6178371906e-3f));
    P = fma2(P, F, pack2(5.5502813330e-2f, 5.5502813330e-2f));
    P = fma2(P, F, pack2(2.4022650695e-1f, 2.4022650695e-1f));
    P = fma2(P, F, pack2(6.9314718056e-1f, 6.9314718056e-1f));
    P = fma2(P, F, pack2(1.0f, 1.0f));
    float tl, th, pl, ph;
    unpack2(T, tl, th);
    unpack2(P, pl, ph);
    e0 = __uint_as_float(__float_as_uint(pl) + (__float_as_uint(tl) << 23));
    e1 = __uint_as_float(__float_as_uint(ph) + (__float_as_uint(th) << 23));
    return pack2(e0, e1);
}

__device__ __forceinline__ uint32_t bf16pack(float lo, float hi) {
    uint32_t r;
    asm("cvt.rn.bf16x2.f32 %0, %1, %2;" : "=r"(r) : "f"(hi), "f"(lo));
    return r;
}

__device__ __forceinline__ uint2 himid(float v0, float v1) {
    uint32_t hp = bf16pack(v0, v1);
    uint32_t mp = bf16pack(v0 - __uint_as_float(hp << 16),
                           v1 - __uint_as_float(hp & 0xffff0000u));
    uint2 o = {hp, mp};
    return o;
}

__device__ __forceinline__ void mma16(float* c, const uint32_t* a, const uint32_t* b) {
    asm volatile("mma.sync.aligned.m16n8k16.row.col.f32.bf16.bf16.f32 "
        "{%0,%1,%2,%3}, {%4,%5,%6,%7}, {%8,%9}, {%0,%1,%2,%3};"
        : "+f"(c[0]), "+f"(c[1]), "+f"(c[2]), "+f"(c[3])
        : "r"(a[0]), "r"(a[1]), "r"(a[2]), "r"(a[3]), "r"(b[0]), "r"(b[1]));
}

__device__ __forceinline__ uint32_t smem_u32(const void* p) {
    uint32_t a;
    asm("{ .reg .u64 t; cvta.to.shared.u64 t, %1; cvt.u32.u64 %0, t; }" : "=r"(a) : "l"(p));
    return a;
}

__device__ __forceinline__ void cp_async16(uint32_t dst, const void* src) {
    asm volatile("cp.async.cg.shared.global [%0], [%1], 16;" :: "r"(dst), "l"(src) : "memory");
}
__device__ __forceinline__ void cp_commit() {
    asm volatile("cp.async.commit_group;" ::: "memory");
}
template <int N>
__device__ __forceinline__ void cp_wait() {
    asm volatile("cp.async.wait_group %0;" :: "n"(N) : "memory");
}

#define FSWZ(r, f) ((f) ^ (((r) & 1) << 2))

// ---------------- input split kernels ---------------------------------------------
__global__ __launch_bounds__(256)
void split_x(const float* __restrict__ X, uint4* __restrict__ out)
{
    int g = blockIdx.x * 256 + threadIdx.x;
    int r = g >> 8, f = g & 255;
    int k = (f >> 2) * 16 + (f & 3) * 2;
    const float* xp = X + (long long)r * DM + k;
    uint2 a = himid(xp[0], xp[1]);
    uint2 b = himid(xp[8], xp[9]);
    uint4 o = {a.x, a.y, b.x, b.y};
    out[g] = o;
}

__global__ __launch_bounds__(256)
void split_w(const float* __restrict__ W, uint4* __restrict__ out)
{
    __shared__ float ws[64][65];
    const int tid = threadIdx.x;
    const int kb = blockIdx.y * 64, nb = blockIdx.x * 64;
#pragma unroll
    for (int i = 0; i < 16; i++) {
        int idx = tid + i * 256; int kk = idx >> 6, nn = idx & 63;
        ws[kk][nn] = W[(long long)(kb + kk) * DM + nb + nn];
    }
    __syncthreads();
#pragma unroll
    for (int i = 0; i < 4; i++) {
        int idx = tid + i * 256; int nn = idx >> 4, f = idx & 15;
        int kk = (f >> 2) * 16 + (f & 3) * 2;
        uint2 a = himid(ws[kk][nn], ws[kk + 1][nn]);
        uint2 b = himid(ws[kk + 8][nn], ws[kk + 9][nn]);
        uint4 o = {a.x, a.y, b.x, b.y};
        out[(long long)(nb + nn) * 256 + (kb >> 2) + f] = o;
    }
}

__global__ __launch_bounds__(256)
void split_wo(const float* __restrict__ W, uint4* __restrict__ out)
{
    __shared__ float ws[64][65];
    const int tid = threadIdx.x;
    const int nb = blockIdx.x * 64;
#pragma unroll
    for (int i = 0; i < 16; i++) {
        int idx = tid + i * 256; int kk = idx >> 6, nn = idx & 63;
        ws[kk][nn] = W[(long long)kk * DM + nb + nn];
    }
    __syncthreads();
#pragma unroll
    for (int i = 0; i < 4; i++) {
        int idx = tid + i * 256; int nn = idx >> 4, f = idx & 15;
        int kk = (f >> 2) * 16 + (f & 3) * 2;
        uint2 a = himid(ws[kk][nn], ws[kk + 1][nn]);
        uint2 b = himid(ws[kk + 8][nn], ws[kk + 9][nn]);
        uint4 o = {a.x, a.y, b.x, b.y};
        out[(long long)(nb + nn) * 16 + f] = o;
    }
}

// ---------------- Q/K projection via bf16-split MMA + cp.async pipeline ------------
__global__ __launch_bounds__(512, 1)
void proj_mma(const uint4* __restrict__ Xpk, const uint4* __restrict__ Wt,
              const float* __restrict__ bias, uint4* __restrict__ Cpk)
{
    extern __shared__ uint4 smq[];
    const uint32_t smb = smem_u32(smq);

    const int tid = threadIdx.x;
    const int colbase = blockIdx.x * 128;
    const int rowbase = blockIdx.y * 256;
    const int wid = tid >> 5, lane = tid & 31;
    const int wm = wid >> 2, wn = wid & 3;
    const int gid = lane >> 2, tig = lane & 3;

    float acc[4][4][4];
#pragma unroll
    for (int mt = 0; mt < 4; mt++)
#pragma unroll
        for (int nt = 0; nt < 4; nt++)
#pragma unroll
            for (int c = 0; c < 4; c++) acc[mt][nt][c] = 0.f;

    auto issue = [&](int kc, int s) {
        uint32_t base = smb + s * 98304;
#pragma unroll
        for (int i = 0; i < 8; i++) {
            int idx = tid + i * 512; int r = idx >> 4, f = idx & 15;
            cp_async16(base + (uint32_t)(r * 16 + FSWZ(r, f)) * 16,
                       &Xpk[(long long)(rowbase + r) * 256 + kc * 16 + f]);
        }
#pragma unroll
        for (int i = 0; i < 4; i++) {
            int idx = tid + i * 512; int r = idx >> 4, f = idx & 15;
            cp_async16(base + 65536u + (uint32_t)(r * 16 + FSWZ(r, f)) * 16,
                       &Wt[(long long)(colbase + r) * 256 + kc * 16 + f]);
        }
        cp_commit();
    };

    issue(0, 0);

    for (int kc = 0; kc < 16; kc++) {
        const int s = kc & 1;
        if (kc < 15) { issue(kc + 1, s ^ 1); cp_wait<1>(); }
        else cp_wait<0>();
        __syncthreads();

        const uint4* Xs = smq + s * 6144;
        const uint4* Ws = Xs + 4096;
#pragma unroll
        for (int k16 = 0; k16 < 4; k16++) {
            const int f = k16 * 4 + tig;
            uint32_t bhf[4][2], bmf[4][2];
#pragma unroll
            for (int nt = 0; nt < 4; nt++) {
                int row = wn * 32 + nt * 8 + gid;
                uint4 kv = Ws[row * 16 + FSWZ(row, f)];
                bhf[nt][0] = kv.x; bhf[nt][1] = kv.z;
                bmf[nt][0] = kv.y; bmf[nt][1] = kv.w;
            }
#pragma unroll
            for (int mt = 0; mt < 4; mt++) {
                int r0 = wm * 64 + mt * 16 + gid;
                int r1 = r0 + 8;
                uint4 qa = Xs[r0 * 16 + FSWZ(r0, f)];
                uint4 qb = Xs[r1 * 16 + FSWZ(r1, f)];
                uint32_t ah[4], am[4];
                ah[0] = qa.x; ah[1] = qb.x; ah[2] = qa.z; ah[3] = qb.z;
                am[0] = qa.y; am[1] = qb.y; am[2] = qa.w; am[3] = qb.w;
#pragma unroll
                for (int nt = 0; nt < 4; nt++) {
                    mma16(acc[mt][nt], ah, bhf[nt]);
                    mma16(acc[mt][nt], ah, bmf[nt]);
                    mma16(acc[mt][nt], am, bhf[nt]);
                }
            }
        }
        __syncthreads();
    }

    const int nb = colbase + wn * 32;
    const int h = nb >> 6;
    const int db = nb & 63;
#pragma unroll
    for (int ntp = 0; ntp < 2; ntp++) {
        int cb = nb + ntp * 16 + tig * 2;
        float b0 = bias[cb],     b1 = bias[cb + 1];
        float b2 = bias[cb + 8], b3 = bias[cb + 9];
        int k16o = (db >> 4) + ntp;
#pragma unroll
        for (int mt = 0; mt < 4; mt++) {
#pragma unroll
            for (int rr = 0; rr < 2; rr++) {
                int gr = rowbase + wm * 64 + mt * 16 + rr * 8 + gid;
                int b = gr >> 11, s = gr & (SS - 1);
                uint2 lo = himid(acc[mt][2 * ntp][rr * 2] + b0,
                                 acc[mt][2 * ntp][rr * 2 + 1] + b1);
                uint2 hi = himid(acc[mt][2 * ntp + 1][rr * 2] + b2,
                                 acc[mt][2 * ntp + 1][rr * 2 + 1] + b3);
                uint4 o = {lo.x, lo.y, hi.x, hi.y};
                Cpk[((long long)((b * HH + h) * SS + s)) * 16 + k16o * 4 + tig] = o;
            }
        }
    }
}

// ---------------- pass 1: 128x128 tile, 256 thr, 2 blocks/SM, z-offset --------------
__global__ __launch_bounds__(256, 2)
void mma_pass1(const uint4* __restrict__ Qpk, const uint4* __restrict__ Kpk,
               __half* __restrict__ Esc, float* __restrict__ lpart, int zoff)
{
    extern __shared__ uint4 smq[];
    uint4* Qs = smq;                          // [128][16]
    uint4* Ks = Qs + 128 * 16;                // [128][16]
    float* rowsum = (float*)(smq + 256 * 16); // [128][4]
    __half* smh = (__half*)smq;               // epilogue staging

    const int tid = threadIdx.x;
    const int kt = blockIdx.x, qt = blockIdx.y, bh = blockIdx.z + zoff;
    const long long qbase = ((long long)bh * SS + qt * 128) * 16;
    const long long kbase = ((long long)bh * SS + kt * 128) * 16;

#pragma unroll
    for (int i = 0; i < 8; i++) {
        int idx = tid + i * 256;
        int r = idx >> 4, f = idx & 15;
        Qs[r * 16 + FSWZ(r, f)] = Qpk[qbase + r * 16 + f];
        Ks[r * 16 + FSWZ(r, f)] = Kpk[kbase + r * 16 + f];
    }
    __syncthreads();

    const int wid = tid >> 5, lane = tid & 31;
    const int wm = wid >> 2, wn = wid & 3;
    const int gid = lane >> 2, tig = lane & 3;

    float acc[4][4][4];
#pragma unroll
    for (int mt = 0; mt < 4; mt++)
#pragma unroll
        for (int nt = 0; nt < 4; nt++)
#pragma unroll
            for (int c = 0; c < 4; c++) acc[mt][nt][c] = 0.f;

#pragma unroll
    for (int k16 = 0; k16 < 4; k16++) {
        const int f = k16 * 4 + tig;
        uint32_t bhf[4][2], bmf[4][2];
#pragma unroll
        for (int nt = 0; nt < 4; nt++) {
            int row = wn * 32 + nt * 8 + gid;
            uint4 kv = Ks[row * 16 + FSWZ(row, f)];
            bhf[nt][0] = kv.x; bhf[nt][1] = kv.z;
            bmf[nt][0] = kv.y; bmf[nt][1] = kv.w;
        }
#pragma unroll
        for (int mt = 0; mt < 4; mt++) {
            int r0 = wm * 64 + mt * 16 + gid;
            int r1 = r0 + 8;
            uint4 qa = Qs[r0 * 16 + FSWZ(r0, f)];
            uint4 qb = Qs[r1 * 16 + FSWZ(r1, f)];
            uint32_t ah[4], am[4];
            ah[0] = qa.x; ah[1] = qb.x; ah[2] = qa.z; ah[3] = qb.z;
            am[0] = qa.y; am[1] = qb.y; am[2] = qa.w; am[3] = qb.w;
#pragma unroll
            for (int nt = 0; nt < 4; nt++) {
                mma16(acc[mt][nt], ah, bhf[nt]);
                mma16(acc[mt][nt], ah, bmf[nt]);
                mma16(acc[mt][nt], am, bhf[nt]);
            }
        }
    }

    unsigned long long S0[4], S1[4];
#pragma unroll
    for (int mt = 0; mt < 4; mt++) { S0[mt] = 0ull; S1[mt] = 0ull; }
#pragma unroll
    for (int mt = 0; mt < 4; mt++)
#pragma unroll
        for (int nt = 0; nt < 4; nt++) {
            unsigned long long P01 = exp8_pair(acc[mt][nt][0], acc[mt][nt][1],
                                               acc[mt][nt][0], acc[mt][nt][1]);
            unsigned long long P23 = exp8_pair(acc[mt][nt][2], acc[mt][nt][3],
                                               acc[mt][nt][2], acc[mt][nt][3]);
            S0[mt] = add2(S0[mt], P01);
            S1[mt] = add2(S1[mt], P23);
        }
    float p[4][2];
#pragma unroll
    for (int mt = 0; mt < 4; mt++) {
        float a, b;
        unpack2(S0[mt], a, b); p[mt][0] = a + b;
        unpack2(S1[mt], a, b); p[mt][1] = a + b;
    }
#pragma unroll
    for (int o = 1; o <= 2; o <<= 1)
#pragma unroll
        for (int mt = 0; mt < 4; mt++) {
            p[mt][0] += __shfl_xor_sync(0xffffffffu, p[mt][0], o);
            p[mt][1] += __shfl_xor_sync(0xffffffffu, p[mt][1], o);
        }
    if (tig == 0) {
#pragma unroll
        for (int mt = 0; mt < 4; mt++)
#pragma unroll
            for (int j = 0; j < 2; j++) {
                int r = wm * 64 + mt * 16 + j * 8 + gid;
                rowsum[r * 4 + wn] = p[mt][j];
            }
    }
    __syncthreads();

    if (tid < 128) {
        float l = rowsum[tid * 4] + rowsum[tid * 4 + 1]
                + rowsum[tid * 4 + 2] + rowsum[tid * 4 + 3];
        lpart[(long long)(bh * 16 + kt) * SS + qt * 128 + tid] = l;
    }

#pragma unroll
    for (int mt = 0; mt < 4; mt++) {
        int r0 = wm * 64 + mt * 16 + gid;
#pragma unroll
        for (int nt = 0; nt < 4; nt++) {
            int col = wn * 32 + nt * 8 + tig * 2;
            *(__half2*)&smh[r0 * 136 + col] =
                __floats2half2_rn(acc[mt][nt][0], acc[mt][nt][1]);
            *(__half2*)&smh[(r0 + 8) * 136 + col] =
                __floats2half2_rn(acc[mt][nt][2], acc[mt][nt][3]);
        }
    }
    __syncthreads();

    __half* Cp = Esc + ((long long)bh * SS + qt * 128) * SS + kt * 128;
    const int u = tid & 15;
    const int rbase = tid >> 4;
#pragma unroll
    for (int i = 0; i < 8; i++) {
        int row = i * 16 + rbase;
        uint4 v = *(uint4*)&smh[row * 136 + u * 8];
        *(uint4*)&Cp[(long long)row * SS + u * 8] = v;
    }
}

// ---------------- head-averaged attention (per-batch) -------------------------------
__global__ __launch_bounds__(256)
void avg_kernel(const __half* __restrict__ Esc, const float* __restrict__ lpart,
                float* __restrict__ avg, int b)
{
    const int q = blockIdx.x;
    const int tid = threadIdx.x;

    __shared__ float rw[HH];
    if (tid < HH) {
        float l = 0.f;
#pragma unroll
        for (int kt = 0; kt < 16; kt++)
            l += lpart[(long long)((b * HH + tid) * 16 + kt) * SS + q];
        rw[tid] = (1.0f / HH) / l;
    }
    __syncthreads();

    const __half* base = Esc + ((long long)(b * HH) * SS + q) * SS;
    const int k0 = tid * 8;
    float a0 = 0.f, a1 = 0.f, a2 = 0.f, a3 = 0.f;
    float a4 = 0.f, a5 = 0.f, a6 = 0.f, a7 = 0.f;
#pragma unroll
    for (int h = 0; h < HH; h++) {
        uint4 raw = *(const uint4*)(base + (long long)h * SS * SS + k0);
        float2 f0 = __half22float2(*(__half2*)&raw.x);
        float2 f1 = __half22float2(*(__half2*)&raw.y);
        float2 f2 = __half22float2(*(__half2*)&raw.z);
        float2 f3 = __half22float2(*(__half2*)&raw.w);
        float r = rw[h];
        a0 = fmaf(f0.x, r, a0); a1 = fmaf(f0.y, r, a1);
        a2 = fmaf(f1.x, r, a2); a3 = fmaf(f1.y, r, a3);
        a4 = fmaf(f2.x, r, a4); a5 = fmaf(f2.y, r, a5);
        a6 = fmaf(f3.x, r, a6); a7 = fmaf(f3.y, r, a7);
    }
    float* dst = avg + ((long long)b * SS + q) * SS + k0;
    float4 o0 = {a0, a1, a2, a3};
    float4 o1 = {a4, a5, a6, a7};
    *(float4*)&dst[0] = o0;
    *(float4*)&dst[4] = o1;
}

// ---------------- SIMT projection GEMM (V projection) -------------------------------
#define PADW 132

__global__ __launch_bounds__(256, 2)
void proj_gemm(const float* __restrict__ A, const float* __restrict__ B,
               const float* __restrict__ bias, float* __restrict__ C,
               int N, int K, int lda, int ldb, int ldc)
{
    __shared__ __align__(16) float As[16 * PADW];
    __shared__ __align__(16) float Bs[16 * PADW];

    const int rowbase = blockIdx.y * 128;
    const int colbase = blockIdx.x * 128;
    const int tid = threadIdx.x;
    const int tx = tid & 15, ty = tid >> 4;
    const int row0 = ty * 8, col0 = tx * 8;

    float regA[8], regB[8];
    unsigned long long acc[8][4];
#pragma unroll
    for (int i = 0; i < 8; i++)
#pragma unroll
        for (int j = 0; j < 4; j++) acc[i][j] = 0ull;

#pragma unroll
    for (int i = 0; i < 8; i++) {
        int idx = tid + i * 256; int r = idx >> 4, kk = idx & 15;
        regA[i] = A[(long long)(rowbase + r) * lda + kk];
    }
#pragma unroll
    for (int i = 0; i < 8; i++) {
        int idx = tid + i * 256; int kk = idx >> 7, c = idx & 127;
        int col = colbase + c;
        regB[i] = (col < N) ? B[(long long)kk * ldb + col] : 0.f;
    }
#pragma unroll
    for (int i = 0; i < 8; i++) {
        int idx = tid + i * 256; int r = idx >> 4, kk = idx & 15;
        As[kk * PADW + r] = regA[i];
    }
#pragma unroll
    for (int i = 0; i < 8; i++) {
        int idx = tid + i * 256; int kk = idx >> 7, c = idx & 127;
        Bs[kk * PADW + c] = regB[i];
    }
    __syncthreads();

    for (int k0 = 16; ; k0 += 16) {
        const bool more = (k0 < K);
        if (more) {
#pragma unroll
            for (int i = 0; i < 8; i++) {
                int idx = tid + i * 256; int r = idx >> 4, kk = idx & 15;
                regA[i] = A[(long long)(rowbase + r) * lda + k0 + kk];
            }
#pragma unroll
            for (int i = 0; i < 8; i++) {
                int idx = tid + i * 256; int kk = idx >> 7, c = idx & 127;
                int col = colbase + c;
                regB[i] = (col < N) ? B[(long long)(k0 + kk) * ldb + col] : 0.f;
            }
        }
#pragma unroll
        for (int kk = 0; kk < 16; kk++) {
            float4 a0 = *(const float4*)&As[kk * PADW + row0];
            float4 a1 = *(const float4*)&As[kk * PADW + row0 + 4];
            float4 b0 = *(const float4*)&Bs[kk * PADW + col0];
            float4 b1 = *(const float4*)&Bs[kk * PADW + col0 + 4];
            float a[8] = {a0.x, a0.y, a0.z, a0.w, a1.x, a1.y, a1.z, a1.w};
            unsigned long long bp[4];
            bp[0] = pack2(b0.x, b0.y); bp[1] = pack2(b0.z, b0.w);
            bp[2] = pack2(b1.x, b1.y); bp[3] = pack2(b1.z, b1.w);
#pragma unroll
            for (int i = 0; i < 8; i++) {
                unsigned long long ap = pack2(a[i], a[i]);
#pragma unroll
                for (int j = 0; j < 4; j++) acc[i][j] = fma2(ap, bp[j], acc[i][j]);
            }
        }
        if (!more) break;
        __syncthreads();
#pragma unroll
        for (int i = 0; i < 8; i++) {
            int idx = tid + i * 256; int r = idx >> 4, kk = idx & 15;
            As[kk * PADW + r] = regA[i];
        }
#pragma unroll
        for (int i = 0; i < 8; i++) {
            int idx = tid + i * 256; int kk = idx >> 7, c = idx & 127;
            Bs[kk * PADW + c] = regB[i];
        }
        __syncthreads();
    }

#pragma unroll
    for (int i = 0; i < 8; i++) {
        int gr = rowbase + row0 + i;
#pragma unroll
        for (int j2 = 0; j2 < 4; j2 += 2) {
            int col = colbase + col0 + j2 * 2;
            if (col < N) {
                float4 v;
                unpack2(acc[i][j2],     v.x, v.y);
                unpack2(acc[i][j2 + 1], v.z, v.w);
                const float4 bb = *(const float4*)&bias[col];
                v.x += bb.x; v.y += bb.y; v.z += bb.z; v.w += bb.w;
                *(float4*)&C[(long long)gr * ldc + col] = v;
            }
        }
    }
}

// ---------------- avg @ V (split-K, per-batch) ---------------------------------------
__global__ __launch_bounds__(256)
void av_gemm(const float* __restrict__ avg, const float* __restrict__ V,
             float* __restrict__ part, int b)
{
    __shared__ float As[16 * PADW];
    __shared__ float Bs[16 * 68];
    const int rowbase = blockIdx.y * 128;
    const int k0base = blockIdx.x * 256;
    const float* Ap = avg + ((long long)b * SS + rowbase) * SS;
    const float* Vp = V + (long long)b * SS * DK;
    const int tid = threadIdx.x;
    const int tx = tid & 15, ty = tid >> 4;

    unsigned long long acc[8][2];
#pragma unroll
    for (int i = 0; i < 8; i++) { acc[i][0] = 0ull; acc[i][1] = 0ull; }

    float regA[8], regB[4];
#pragma unroll
    for (int i = 0; i < 8; i++) {
        int idx = tid + i * 256; int r = idx >> 4, kk = idx & 15;
        regA[i] = Ap[(long long)r * SS + k0base + kk];
    }
#pragma unroll
    for (int i = 0; i < 4; i++) {
        int idx = tid + i * 256; int kk = idx >> 6, cc = idx & 63;
        regB[i] = Vp[(long long)(k0base + kk) * DK + cc];
    }

    for (int kc = 0; kc < 256; kc += 16) {
#pragma unroll
        for (int i = 0; i < 8; i++) {
            int idx = tid + i * 256; int r = idx >> 4, kk = idx & 15;
            As[kk * PADW + r] = regA[i];
        }
#pragma unroll
        for (int i = 0; i < 4; i++) {
            int idx = tid + i * 256; int kk = idx >> 6, cc = idx & 63;
            Bs[kk * 68 + cc] = regB[i];
        }
        __syncthreads();

        const bool more = (kc + 16 < 256);
        if (more) {
            const int k0 = k0base + kc + 16;
#pragma unroll
            for (int i = 0; i < 8; i++) {
                int idx = tid + i * 256; int r = idx >> 4, kk = idx & 15;
                regA[i] = Ap[(long long)r * SS + k0 + kk];
            }
#pragma unroll
            for (int i = 0; i < 4; i++) {
                int idx = tid + i * 256; int kk = idx >> 6, cc = idx & 63;
                regB[i] = Vp[(long long)(k0 + kk) * DK + cc];
            }
        }

#pragma unroll
        for (int kk = 0; kk < 16; kk++) {
            float a[8];
#pragma unroll
            for (int i = 0; i < 8; i++) a[i] = As[kk * PADW + ty * 8 + i];
            float4 bv = *(const float4*)&Bs[kk * 68 + tx * 4];
            unsigned long long b01 = pack2(bv.x, bv.y);
            unsigned long long b23 = pack2(bv.z, bv.w);
#pragma unroll
            for (int i = 0; i < 8; i++) {
                unsigned long long ap = pack2(a[i], a[i]);
                acc[i][0] = fma2(ap, b01, acc[i][0]);
                acc[i][1] = fma2(ap, b23, acc[i][1]);
            }
        }
        __syncthreads();
    }
    float* P = part + ((long long)(blockIdx.x * BB + b) * SS + rowbase) * DK;
#pragma unroll
    for (int i = 0; i < 8; i++) {
        float4 v;
        unpack2(acc[i][0], v.x, v.y);
        unpack2(acc[i][1], v.z, v.w);
        *(float4*)&P[(long long)(ty * 8 + i) * DK + tx * 4] = v;
    }
}

__global__ __launch_bounds__(256)
void av_reduce_pack(const float* __restrict__ part, uint4* __restrict__ Aopk)
{
    int g = blockIdx.x * 256 + threadIdx.x;
    int r = g >> 4, f = g & 15;
    int k = (f >> 2) * 16 + (f & 3) * 2;
    float v0 = 0.f, v1 = 0.f, v8 = 0.f, v9 = 0.f;
#pragma unroll
    for (int t = 0; t < 8; t++) {
        const float* p = part + (long long)t * (BB * SS * DK) + (long long)r * DK + k;
        float2 a = *(const float2*)p;
        float2 b = *(const float2*)(p + 8);
        v0 += a.x; v1 += a.y; v8 += b.x; v9 += b.y;
    }
    uint2 lo = himid(v0, v1);
    uint2 hi = himid(v8, v9);
    uint4 o = {lo.x, lo.y, hi.x, hi.y};
    Aopk[g] = o;
}

// ---------------- final GEMM: out = Ao @ Wo + bo ------------------------------------
__global__ __launch_bounds__(512, 1)
void out_mma(const uint4* __restrict__ Aopk, const uint4* __restrict__ Wto,
             const float* __restrict__ bias, float* __restrict__ C)
{
    extern __shared__ uint4 smq[];
    uint4* Xs = smq;
    uint4* Ws = Xs + 256 * 16;

    const int tid = threadIdx.x;
    const int colbase = blockIdx.x * 128;
    const int rowbase = blockIdx.y * 256;
    const int wid = tid >> 5, lane = tid & 31;
    const int wm = wid >> 2, wn = wid & 3;
    const int gid = lane >> 2, tig = lane & 3;

#pragma unroll
    for (int i = 0; i < 8; i++) {
        int idx = tid + i * 512; int r = idx >> 4, f = idx & 15;
        Xs[r * 16 + FSWZ(r, f)] = Aopk[(long long)(rowbase + r) * 16 + f];
    }
#pragma unroll
    for (int i = 0; i < 4; i++) {
        int idx = tid + i * 512; int r = idx >> 4, f = idx & 15;
        Ws[r * 16 + FSWZ(r, f)] = Wto[(long long)(colbase + r) * 16 + f];
    }
    __syncthreads();

    float acc[4][4][4];
#pragma unroll
    for (int mt = 0; mt < 4; mt++)
#pragma unroll
        for (int nt = 0; nt < 4; nt++)
#pragma unroll
            for (int c = 0; c < 4; c++) acc[mt][nt][c] = 0.f;

#pragma unroll
    for (int k16 = 0; k16 < 4; k16++) {
        const int f = k16 * 4 + tig;
        uint32_t bhf[4][2], bmf[4][2];
#pragma unroll
        for (int nt = 0; nt < 4; nt++) {
            int row = wn * 32 + nt * 8 + gid;
            uint4 kv = Ws[row * 16 + FSWZ(row, f)];
            bhf[nt][0] = kv.x; bhf[nt][1] = kv.z;
            bmf[nt][0] = kv.y; bmf[nt][1] = kv.w;
        }
#pragma unroll
        for (int mt = 0; mt < 4; mt++) {
            int r0 = wm * 64 + mt * 16 + gid;
            int r1 = r0 + 8;
            uint4 qa = Xs[r0 * 16 + FSWZ(r0, f)];
            uint4 qb = Xs[r1 * 16 + FSWZ(r1, f)];
            uint32_t ah[4], am[4];
            ah[0] = qa.x; ah[1] = qb.x; ah[2] = qa.z; ah[3] = qb.z;
            am[0] = qa.y; am[1] = qb.y; am[2] = qa.w; am[3] = qb.w;
#pragma unroll
            for (int nt = 0; nt < 4; nt++) {
                mma16(acc[mt][nt], ah, bhf[nt]);
                mma16(acc[mt][nt], ah, bmf[nt]);
                mma16(acc[mt][nt], am, bhf[nt]);
            }
        }
    }

#pragma unroll
    for (int nt = 0; nt < 4; nt++) {
        int col = colbase + wn * 32 + nt * 8 + tig * 2;
        float b0 = bias[col], b1 = bias[col + 1];
#pragma unroll
        for (int mt = 0; mt < 4; mt++) {
            int r0 = rowbase + wm * 64 + mt * 16 + gid;
            float2 v0 = {acc[mt][nt][0] + b0, acc[mt][nt][1] + b1};
            float2 v1 = {acc[mt][nt][2] + b0, acc[mt][nt][3] + b1};
            *(float2*)&C[(long long)r0 * DM + col] = v0;
            *(float2*)&C[(long long)(r0 + 8) * DM + col] = v1;
        }
    }
}

// ---------------- launch -------------------------------------------------------------
extern "C" void kernel_launch(void* const* d_in, const int* in_sizes, int n_in,
                              void* d_out, int out_size)
{
    const float* query = (const float*)d_in[0];
    const float* key_  = (const float*)d_in[1];
    const float* value = (const float*)d_in[2];
    const float* Wq    = (const float*)d_in[3];
    const float* bq    = (const float*)d_in[4];
    const float* Wk    = (const float*)d_in[5];
    const float* bk    = (const float*)d_in[6];
    const float* Wv    = (const float*)d_in[7];
    const float* bv    = (const float*)d_in[8];
    const float* Wo    = (const float*)d_in[9];
    const float* bo    = (const float*)d_in[10];

    float* out_main = (float*)d_out;
    float* out_avg  = out_main + (size_t)ROWS * DM;

    uint4 *Xq, *Xk, *Wtq, *Wtk, *Qpk, *Kpk, *Aopk, *Wto;
    __half* Esc;
    float *Vp, *Lp, *Av;
    cudaGetSymbolAddress((void**)&Xq, g_Xq);
    cudaGetSymbolAddress((void**)&Xk, g_Xk);
    cudaGetSymbolAddress((void**)&Wtq, g_Wtq);
    cudaGetSymbolAddress((void**)&Wtk, g_Wtk);
    cudaGetSymbolAddress((void**)&Qpk, g_Qpk);
    cudaGetSymbolAddress((void**)&Kpk, g_Kpk);
    cudaGetSymbolAddress((void**)&Vp, g_Vp);
    cudaGetSymbolAddress((void**)&Esc, g_escore);
    cudaGetSymbolAddress((void**)&Lp, g_lpart);
    cudaGetSymbolAddress((void**)&Av, g_avpart);
    cudaGetSymbolAddress((void**)&Aopk, g_Aopk);
    cudaGetSymbolAddress((void**)&Wto, g_Wto);

    const int smemP = 2 * 98304;
    const int smem1 = 256 * 16 * 16 + 128 * 4 * 4;   // 67584
    const int smemO = 384 * 16 * 16;
    cudaFuncSetAttribute(proj_mma, cudaFuncAttributeMaxDynamicSharedMemorySize, smemP);
    cudaFuncSetAttribute(mma_pass1, cudaFuncAttributeMaxDynamicSharedMemorySize, smem1);
    cudaFuncSetAttribute(out_mma, cudaFuncAttributeMaxDynamicSharedMemorySize, smemO);

    static cudaStream_t sK = nullptr, sV = nullptr;
    static cudaEvent_t evRoot = nullptr, evQ = nullptr, evK = nullptr,
                       evV = nullptr, evB1 = nullptr;
    if (sK == nullptr) {
        cudaStreamCreateWithFlags(&sK, cudaStreamNonBlocking);
        cudaStreamCreateWithFlags(&sV, cudaStreamNonBlocking);
        cudaEventCreateWithFlags(&evRoot, cudaEventDisableTiming);
        cudaEventCreateWithFlags(&evQ, cudaEventDisableTiming);
        cudaEventCreateWithFlags(&evK, cudaEventDisableTiming);
        cudaEventCreateWithFlags(&evV, cudaEventDisableTiming);
        cudaEventCreateWithFlags(&evB1, cudaEventDisableTiming);
    }

    dim3 blk(256);

    // fork
    cudaEventRecord(evRoot, 0);
    cudaStreamWaitEvent(sK, evRoot, 0);
    cudaStreamWaitEvent(sV, evRoot, 0);

    // main: Q path
    split_x<<<ROWS, blk>>>(query, Xq);
    split_w<<<dim3(16, 16), blk>>>(Wq, Wtq);
    proj_mma<<<dim3(8, 16), 512, smemP>>>(Xq, Wtq, bq, Qpk);
    cudaEventRecord(evQ, 0);

    // sK: K path
    split_x<<<ROWS, blk, 0, sK>>>(key_, Xk);
    split_w<<<dim3(16, 16), blk, 0, sK>>>(Wk, Wtk);
    proj_mma<<<dim3(8, 16), 512, smemP, sK>>>(Xk, Wtk, bk, Kpk);
    cudaEventRecord(evK, sK);

    // sV: V projection + Wo split
    proj_gemm<<<dim3(1, 32), blk, 0, sV>>>(value, Wv, bv, Vp, DK, DM, DM, DK, DK);
    split_wo<<<dim3(16, 1), blk, 0, sV>>>(Wo, Wto);
    cudaEventRecord(evV, sV);

    // batch-pipelined attention tail:
    // main handles b=0; sK handles b=1 (each needs full Q & K projections)
    cudaStreamWaitEvent(0, evK, 0);      // main has Q ordered; wait for K
    cudaStreamWaitEvent(sK, evQ, 0);     // sK has K ordered; wait for Q

    // b = 0 on main
    mma_pass1<<<dim3(16, 16, HH), 256, smem1>>>(Qpk, Kpk, Esc, Lp, 0);
    avg_kernel<<<dim3(SS, 1, 1), blk>>>(Esc, Lp, out_avg, 0);
    cudaStreamWaitEvent(0, evV, 0);
    av_gemm<<<dim3(8, 16, 1), blk>>>(out_avg, Vp, Av, 0);

    // b = 1 on sK
    mma_pass1<<<dim3(16, 16, HH), 256, smem1, sK>>>(Qpk, Kpk, Esc, Lp, HH);
    avg_kernel<<<dim3(SS, 1, 1), blk, 0, sK>>>(Esc, Lp, out_avg, 1);
    cudaStreamWaitEvent(sK, evV, 0);
    av_gemm<<<dim3(8, 16, 1), blk, 0, sK>>>(out_avg, Vp, Av, 1);
    cudaEventRecord(evB1, sK);

    // join and finish on main
    cudaStreamWaitEvent(0, evB1, 0);
    av_reduce_pack<<<dim3(ROWS * 16 / 256, 1, 1), blk>>>(Av, Aopk);
    out_mma<<<dim3(8, 16), 512, smemO>>>(Aopk, Wto, bo, out_main);
}